// round 2
// baseline (speedup 1.0000x reference)
#include <cuda_runtime.h>
#include <math.h>

// Problem constants (B=8, V=T=1024, H=1024, L=V+T=2048)
#define BB 8
#define SS 1024
#define HH 1024
#define LL 2048
#define MID_M 341   // t2v active mid rows: 341..681
#define MID_N 512   // keys 256..767

// -------------------- scratch (device globals; no runtime alloc) ------------
__device__ __align__(128) float g_q_text[BB*SS*HH];
__device__ __align__(128) float g_k_vis [BB*SS*HH];
__device__ __align__(128) float g_v_vis [BB*SS*HH];
__device__ __align__(128) float g_q_vis [BB*SS*HH];
__device__ __align__(128) float g_k_text[BB*SS*HH];
__device__ __align__(128) float g_v_text[BB*SS*HH];
__device__ __align__(128) float g_att   [BB*LL*HH];   // attended concat [b, l, h]
__device__ __align__(128) float g_scores[BB*MID_M*MID_N];
__device__ __align__(128) float g_c1    [BB*LL*HH];   // conv1+gelu out [b, l, c]

// -------------------- generic fp32 SGEMM: C = A*B(^T) (+bias) (+resid) ------
// A [M,K] row-major (lda). TRANSB: B [N,K] row-major (ldb) -> C=A*B^T.
// !TRANSB: B [K,N] row-major (ldb) -> C=A*B. N must be a multiple of 128,
// K a multiple of 16 (true for all call sites). M guarded.
template<bool TRANSB, bool BIAS, bool RESID>
__global__ __launch_bounds__(256)
void sgemm_k(const float* __restrict__ A, int lda, long long sA,
             const float* __restrict__ Bm, int ldb, long long sB,
             float* __restrict__ C, int ldc, long long sC,
             const float* __restrict__ bias,
             const float* __restrict__ Rm, int ldr, long long sR,
             int M, int N, int K)
{
    constexpr int Bb = 128, Bn = 128, Bk = 16;
    __shared__ float As[2][Bk][Bb];
    __shared__ float Bs[2][Bk][Bn];

    A  += (long long)blockIdx.z * sA;
    Bm += (long long)blockIdx.z * sB;
    C  += (long long)blockIdx.z * sC;
    if (RESID) Rm += (long long)blockIdx.z * sR;

    const int tid = threadIdx.x;
    const int bx = blockIdx.x, by = blockIdx.y;
    const int ar = tid >> 2;           // 0..63
    const int ac = (tid & 3) << 2;     // 0,4,8,12
    const int br = tid >> 5;           // 0..7
    const int bc = (tid & 31) << 2;    // 0..124

    const int warp = tid >> 5, lane = tid & 31;
    const int mb = (warp & 3) * 32 + (lane >> 3) * 8;
    const int nb = (warp >> 2) * 64 + (lane & 7) * 8;

    float4 aR[2], bR[2];
    float acc[8][8];
    #pragma unroll
    for (int i = 0; i < 8; i++)
        #pragma unroll
        for (int j = 0; j < 8; j++) acc[i][j] = 0.f;

    const int nk = K / Bk;

    // ---- prologue: load tile 0 ----
    {
        const int k0 = 0;
        #pragma unroll
        for (int p = 0; p < 2; p++) {
            int m = by * Bb + ar + p * 64;
            aR[p] = (m < M) ? *(const float4*)(A + (long long)m * lda + k0 + ac)
                            : make_float4(0.f, 0.f, 0.f, 0.f);
        }
        if (TRANSB) {
            #pragma unroll
            for (int p = 0; p < 2; p++) {
                int n = bx * Bn + ar + p * 64;
                bR[p] = *(const float4*)(Bm + (long long)n * ldb + k0 + ac);
            }
        } else {
            #pragma unroll
            for (int p = 0; p < 2; p++) {
                int kk = br + p * 8;
                bR[p] = *(const float4*)(Bm + (long long)(k0 + kk) * ldb + bx * Bn + bc);
            }
        }
    }
    int buf = 0;
    #pragma unroll
    for (int p = 0; p < 2; p++) {
        As[buf][ac + 0][ar + p * 64] = aR[p].x;
        As[buf][ac + 1][ar + p * 64] = aR[p].y;
        As[buf][ac + 2][ar + p * 64] = aR[p].z;
        As[buf][ac + 3][ar + p * 64] = aR[p].w;
    }
    if (TRANSB) {
        #pragma unroll
        for (int p = 0; p < 2; p++) {
            Bs[buf][ac + 0][ar + p * 64] = bR[p].x;
            Bs[buf][ac + 1][ar + p * 64] = bR[p].y;
            Bs[buf][ac + 2][ar + p * 64] = bR[p].z;
            Bs[buf][ac + 3][ar + p * 64] = bR[p].w;
        }
    } else {
        #pragma unroll
        for (int p = 0; p < 2; p++)
            *(float4*)&Bs[buf][br + p * 8][bc] = bR[p];
    }
    __syncthreads();

    for (int kt = 0; kt < nk; kt++) {
        const bool more = (kt + 1 < nk);
        if (more) {
            const int k0 = (kt + 1) * Bk;
            #pragma unroll
            for (int p = 0; p < 2; p++) {
                int m = by * Bb + ar + p * 64;
                aR[p] = (m < M) ? *(const float4*)(A + (long long)m * lda + k0 + ac)
                                : make_float4(0.f, 0.f, 0.f, 0.f);
            }
            if (TRANSB) {
                #pragma unroll
                for (int p = 0; p < 2; p++) {
                    int n = bx * Bn + ar + p * 64;
                    bR[p] = *(const float4*)(Bm + (long long)n * ldb + k0 + ac);
                }
            } else {
                #pragma unroll
                for (int p = 0; p < 2; p++) {
                    int kk = br + p * 8;
                    bR[p] = *(const float4*)(Bm + (long long)(k0 + kk) * ldb + bx * Bn + bc);
                }
            }
        }
        #pragma unroll
        for (int k = 0; k < Bk; k++) {
            float a[8], bv2[8];
            *(float4*)&a[0]   = *(const float4*)&As[buf][k][mb];
            *(float4*)&a[4]   = *(const float4*)&As[buf][k][mb + 4];
            *(float4*)&bv2[0] = *(const float4*)&Bs[buf][k][nb];
            *(float4*)&bv2[4] = *(const float4*)&Bs[buf][k][nb + 4];
            #pragma unroll
            for (int i = 0; i < 8; i++)
                #pragma unroll
                for (int j = 0; j < 8; j++)
                    acc[i][j] += a[i] * bv2[j];
        }
        if (more) {
            buf ^= 1;
            #pragma unroll
            for (int p = 0; p < 2; p++) {
                As[buf][ac + 0][ar + p * 64] = aR[p].x;
                As[buf][ac + 1][ar + p * 64] = aR[p].y;
                As[buf][ac + 2][ar + p * 64] = aR[p].z;
                As[buf][ac + 3][ar + p * 64] = aR[p].w;
            }
            if (TRANSB) {
                #pragma unroll
                for (int p = 0; p < 2; p++) {
                    Bs[buf][ac + 0][ar + p * 64] = bR[p].x;
                    Bs[buf][ac + 1][ar + p * 64] = bR[p].y;
                    Bs[buf][ac + 2][ar + p * 64] = bR[p].z;
                    Bs[buf][ac + 3][ar + p * 64] = bR[p].w;
                }
            } else {
                #pragma unroll
                for (int p = 0; p < 2; p++)
                    *(float4*)&Bs[buf][br + p * 8][bc] = bR[p];
            }
            __syncthreads();
        }
    }

    // ---- epilogue ----
    float bvv[8];
    if (BIAS) {
        #pragma unroll
        for (int j = 0; j < 8; j++) bvv[j] = bias[bx * Bn + nb + j];
    }
    #pragma unroll
    for (int i = 0; i < 8; i++) {
        int m = by * Bb + mb + i;
        if (m < M) {
            float* Cp = C + (long long)m * ldc + bx * Bn + nb;
            const float* Rp = RESID ? (Rm + (long long)m * ldr + bx * Bn + nb) : (const float*)0;
            #pragma unroll
            for (int j = 0; j < 8; j += 4) {
                float4 v;
                v.x = acc[i][j + 0]; v.y = acc[i][j + 1];
                v.z = acc[i][j + 2]; v.w = acc[i][j + 3];
                if (BIAS) { v.x += bvv[j]; v.y += bvv[j + 1]; v.z += bvv[j + 2]; v.w += bvv[j + 3]; }
                if (RESID) {
                    float4 rv = *(const float4*)(Rp + j);
                    v.x += rv.x; v.y += rv.y; v.z += rv.z; v.w += rv.w;
                }
                *(float4*)(Cp + j) = v;
            }
        }
    }
}

// -------------------- copy text features into concat buffer ----------------
__global__ void copy_text(const float4* __restrict__ src, float4* __restrict__ dst)
{
    int idx = blockIdx.x * 256 + threadIdx.x;        // total 8*1024*1024/4 = 2M
    int b = idx >> 18;                               // / 262144
    int r = idx & 262143;
    dst[(long long)b * 524288 + 262144 + r] = src[idx];
}

// -------------------- v2t attention (<=13 keys/row) + residual --------------
__global__ __launch_bounds__(128) void v2t_attn(
    const float* __restrict__ qvis, const float* __restrict__ ktext,
    const float* __restrict__ vtext, const float* __restrict__ visf,
    float* __restrict__ att)
{
    const int i = blockIdx.x, b = blockIdx.y;
    const int tid = threadIdx.x, lane = tid & 31, warp = tid >> 5;
    const int s0 = (i < 1016) ? i : 1016;
    const int nk = (i < 5) ? (i + 8) : 13;   // union of {0..4} and window

    const float* q = qvis + ((long long)b * SS + i) * HH;
    float qr[8];
    #pragma unroll
    for (int r = 0; r < 8; r++) qr[r] = q[r * 128 + tid];

    const float* kb = ktext + (long long)b * SS * HH;
    float p[13];
    #pragma unroll
    for (int j = 0; j < 13; j++) {
        float s = 0.f;
        if (j < nk) {
            int kj = (i < 5) ? j : ((j < 5) ? j : (s0 + j - 5));
            const float* kp = kb + (long long)kj * HH + tid;
            #pragma unroll
            for (int r = 0; r < 8; r++) s += qr[r] * kp[r * 128];
        }
        p[j] = s;
    }
    #pragma unroll
    for (int j = 0; j < 13; j++) {
        #pragma unroll
        for (int off = 16; off; off >>= 1) p[j] += __shfl_xor_sync(0xffffffffu, p[j], off);
    }
    __shared__ float red[4][13];
    if (lane == 0) {
        #pragma unroll
        for (int j = 0; j < 13; j++) red[warp][j] = p[j];
    }
    __syncthreads();

    float sc[13];
    float mx = -3.4e38f;
    #pragma unroll
    for (int j = 0; j < 13; j++) {
        sc[j] = red[0][j] + red[1][j] + red[2][j] + red[3][j];
        if (j < nk) mx = fmaxf(mx, sc[j]);
    }
    float sum = 0.f;
    #pragma unroll
    for (int j = 0; j < 13; j++) {
        float e = (j < nk) ? expf(sc[j] - mx) : 0.f;
        sc[j] = e; sum += e;
    }
    const float inv = 1.f / sum;

    const float* vf = visf + ((long long)b * SS + i) * HH;
    const float* vb = vtext + (long long)b * SS * HH;
    float* op = att + ((long long)b * LL + i) * HH;
    #pragma unroll
    for (int r = 0; r < 8; r++) {
        int h = r * 128 + tid;
        float a2 = vf[h];
        #pragma unroll
        for (int j = 0; j < 13; j++) {
            if (j < nk) {
                int kj = (i < 5) ? j : ((j < 5) ? j : (s0 + j - 5));
                a2 += sc[j] * inv * vb[(long long)kj * HH + h];
            }
        }
        op[h] = a2;
    }
}

// -------------------- t2v rows 0..4 (full softmax over 1024 keys) -----------
__global__ __launch_bounds__(256) void t2v_full_rows(
    const float* __restrict__ qtext, const float* __restrict__ kvis,
    const float* __restrict__ vvis, float* __restrict__ att)
{
    const int r = blockIdx.x, b = blockIdx.y;
    const int tid = threadIdx.x, lane = tid & 31, warp = tid >> 5;
    __shared__ float qs[1024];
    __shared__ float sc[1024];
    __shared__ float red[8];

    const float* q = qtext + ((long long)b * SS + r) * HH;
    for (int h = tid; h < 1024; h += 256) qs[h] = q[h];
    __syncthreads();

    const float* kb = kvis + (long long)b * SS * HH;
    for (int t = warp * 128; t < warp * 128 + 128; t++) {
        const float* kp = kb + (long long)t * HH;
        float p = 0.f;
        #pragma unroll
        for (int c = 0; c < 32; c++) p += qs[c * 32 + lane] * kp[c * 32 + lane];
        #pragma unroll
        for (int off = 16; off; off >>= 1) p += __shfl_xor_sync(0xffffffffu, p, off);
        if (lane == 0) sc[t] = p;
    }
    __syncthreads();

    float m = -3.4e38f;
    for (int t = tid; t < 1024; t += 256) m = fmaxf(m, sc[t]);
    #pragma unroll
    for (int off = 16; off; off >>= 1) m = fmaxf(m, __shfl_xor_sync(0xffffffffu, m, off));
    if (lane == 0) red[warp] = m;
    __syncthreads();
    float mx = red[0];
    #pragma unroll
    for (int k = 1; k < 8; k++) mx = fmaxf(mx, red[k]);

    float s = 0.f;
    for (int t = tid; t < 1024; t += 256) { float e = expf(sc[t] - mx); sc[t] = e; s += e; }
    #pragma unroll
    for (int off = 16; off; off >>= 1) s += __shfl_xor_sync(0xffffffffu, s, off);
    __syncthreads();            // protect red reuse; also publishes sc[]
    if (lane == 0) red[warp] = s;
    __syncthreads();
    float tot = 0.f;
    #pragma unroll
    for (int k = 0; k < 8; k++) tot += red[k];
    const float inv = 1.f / tot;

    const float* vb = vvis + (long long)b * SS * HH;
    float* op = att + ((long long)b * LL + 1024 + r) * HH;
    float accv[4] = {0.f, 0.f, 0.f, 0.f};
    for (int t = 0; t < 1024; t++) {
        float pw = sc[t];
        const float* vr = vb + (long long)t * HH + tid;
        accv[0] += pw * vr[0];
        accv[1] += pw * vr[256];
        accv[2] += pw * vr[512];
        accv[3] += pw * vr[768];
    }
    #pragma unroll
    for (int k = 0; k < 4; k++) op[tid + k * 256] += accv[k] * inv;
}

// -------------------- softmax over 512-col rows (t2v mid block) -------------
__global__ __launch_bounds__(256) void softmax512(float* __restrict__ S)
{
    float* row = S + (long long)blockIdx.x * 512;
    const int tid = threadIdx.x, lane = tid & 31, warp = tid >> 5;
    __shared__ float red[8];
    float a = row[tid], b2 = row[tid + 256];
    float m = fmaxf(a, b2);
    #pragma unroll
    for (int off = 16; off; off >>= 1) m = fmaxf(m, __shfl_xor_sync(0xffffffffu, m, off));
    if (lane == 0) red[warp] = m;
    __syncthreads();
    float mx = red[0];
    #pragma unroll
    for (int k = 1; k < 8; k++) mx = fmaxf(mx, red[k]);
    float e0 = expf(a - mx), e1 = expf(b2 - mx);
    float s = e0 + e1;
    #pragma unroll
    for (int off = 16; off; off >>= 1) s += __shfl_xor_sync(0xffffffffu, s, off);
    __syncthreads();
    if (lane == 0) red[warp] = s;
    __syncthreads();
    float tot = 0.f;
    #pragma unroll
    for (int k = 0; k < 8; k++) tot += red[k];
    float inv = 1.f / tot;
    row[tid] = e0 * inv;
    row[tid + 256] = e1 * inv;
}

// -------------------- grouped conv1 (k=3, groups=8) + exact GELU ------------
__global__ __launch_bounds__(128) void conv1_gelu(
    const float* __restrict__ att, const float* __restrict__ W,
    const float* __restrict__ bias, float* __restrict__ out)
{
    __shared__ float s[34][128];      // input tile: l0-1 .. l0+32, 128 channels of group
    __shared__ float Ws[128][49];     // 16 input channels * 3 taps = 48 weights / out-ch
    const int b = blockIdx.z, g = blockIdx.y;
    const int l0 = blockIdx.x * 32;
    const int tid = threadIdx.x;

    const float* base = att + (long long)b * LL * HH + g * 128;
    #pragma unroll
    for (int j = 0; j < 34; j++) {
        int l = l0 - 1 + j;
        s[j][tid] = (l >= 0 && l < LL) ? base[(long long)l * HH + tid] : 0.f;
    }
    const int o = g * 128 + tid;
    float acc[32];
    #pragma unroll
    for (int l = 0; l < 32; l++) acc[l] = 0.f;

    for (int ic = 0; ic < 8; ic++) {
        __syncthreads();                      // covers s[] on first pass, Ws reuse after
        for (int t = tid; t < 128 * 48; t += 128) {
            int oo = t / 48, j = t % 48;
            Ws[oo][j] = W[((long long)(g * 128 + oo)) * 384 + ic * 48 + j];
        }
        __syncthreads();
        #pragma unroll
        for (int ii = 0; ii < 16; ii++) {
            int i = ic * 16 + ii;
            float w0 = Ws[tid][ii * 3 + 0];
            float w1 = Ws[tid][ii * 3 + 1];
            float w2 = Ws[tid][ii * 3 + 2];
            #pragma unroll
            for (int l = 0; l < 32; l++)
                acc[l] += w0 * s[l][i] + w1 * s[l + 1][i] + w2 * s[l + 2][i];
        }
    }
    const float bo = bias[o];
    float* op = out + ((long long)b * LL + l0) * HH + o;
    #pragma unroll
    for (int l = 0; l < 32; l++) {
        float x = acc[l] + bo;
        float y = 0.5f * x * (1.0f + erff(x * 0.70710678118654752f));   // exact GELU
        op[(long long)l * HH] = y;
    }
}

// -------------------- launcher ----------------------------------------------
extern "C" void kernel_launch(void* const* d_in, const int* in_sizes, int n_in,
                              void* d_out, int out_size)
{
    (void)in_sizes; (void)n_in; (void)out_size;
    const float* vis = (const float*)d_in[0];
    const float* txt = (const float*)d_in[1];
    const float* Wq  = (const float*)d_in[2];  const float* bq  = (const float*)d_in[3];
    const float* Wk  = (const float*)d_in[4];  const float* bk  = (const float*)d_in[5];
    const float* Wv  = (const float*)d_in[6];  const float* bv  = (const float*)d_in[7];
    const float* Wc1 = (const float*)d_in[8];  const float* bc1 = (const float*)d_in[9];
    const float* Wc2 = (const float*)d_in[10]; const float* bc2 = (const float*)d_in[11];
    float* out = (float*)d_out;

    float *qt, *kv, *vv, *qv, *kt, *vt, *attb, *scb, *c1b;
    cudaGetSymbolAddress((void**)&qt,  g_q_text);
    cudaGetSymbolAddress((void**)&kv,  g_k_vis);
    cudaGetSymbolAddress((void**)&vv,  g_v_vis);
    cudaGetSymbolAddress((void**)&qv,  g_q_vis);
    cudaGetSymbolAddress((void**)&kt,  g_k_text);
    cudaGetSymbolAddress((void**)&vt,  g_v_text);
    cudaGetSymbolAddress((void**)&attb, g_att);
    cudaGetSymbolAddress((void**)&scb, g_scores);
    cudaGetSymbolAddress((void**)&c1b, g_c1);

    const long long SH = (long long)SS * HH;       // 1048576
    const long long LH = (long long)LL * HH;       // 2097152
    const long long SCs = (long long)MID_M * MID_N; // 174592

    // 1) projections: [8192,1024] @ W^T + bias
    dim3 gP(HH / 128, (BB * SS) / 128, 1);
    sgemm_k<true, true, false><<<gP, 256>>>(txt, HH, 0, Wq, HH, 0, qt, HH, 0, bq, nullptr, 0, 0, BB*SS, HH, HH);
    sgemm_k<true, true, false><<<gP, 256>>>(vis, HH, 0, Wk, HH, 0, kv, HH, 0, bk, nullptr, 0, 0, BB*SS, HH, HH);
    sgemm_k<true, true, false><<<gP, 256>>>(vis, HH, 0, Wv, HH, 0, vv, HH, 0, bv, nullptr, 0, 0, BB*SS, HH, HH);
    sgemm_k<true, true, false><<<gP, 256>>>(vis, HH, 0, Wq, HH, 0, qv, HH, 0, bq, nullptr, 0, 0, BB*SS, HH, HH);
    sgemm_k<true, true, false><<<gP, 256>>>(txt, HH, 0, Wk, HH, 0, kt, HH, 0, bk, nullptr, 0, 0, BB*SS, HH, HH);
    sgemm_k<true, true, false><<<gP, 256>>>(txt, HH, 0, Wv, HH, 0, vt, HH, 0, bv, nullptr, 0, 0, BB*SS, HH, HH);

    // 2) init text half of concat buffer with residual text features
    copy_text<<<8192, 256>>>((const float4*)txt, (float4*)attb);

    // 3) v2t sparse attention (<=13 keys) + visual residual -> att rows [0,1024)
    v2t_attn<<<dim3(SS, BB), 128>>>(qv, kt, vt, vis, attb);

    // 4) t2v rows 0..4: full softmax over all visual keys, add into text rows
    t2v_full_rows<<<dim3(5, BB), 256>>>(qt, kv, vv, attb);

    // 5) t2v mid block: scores [341,512] = q_text[341:682] @ k_vis[256:768]^T
    sgemm_k<true, false, false><<<dim3(MID_N / 128, 3, BB), 256>>>(
        qt + 341 * HH, HH, SH, kv + 256 * HH, HH, SH,
        scb, MID_N, SCs, nullptr, nullptr, 0, 0, MID_M, MID_N, HH);

    // 6) row softmax over 512 cols
    softmax512<<<BB * MID_M, 256>>>(scb);

    // 7) AV: att_text[341:682] = text_resid + probs @ v_vis[256:768]
    sgemm_k<false, false, true><<<dim3(HH / 128, 3, BB), 256>>>(
        scb, MID_N, SCs, vv + 256 * HH, HH, SH,
        attb + (long long)(1024 + 341) * HH, HH, LH,
        nullptr, txt + 341 * HH, HH, SH, MID_M, HH, MID_N);

    // 8) grouped conv1 (k=3, groups=8) + exact GELU
    conv1_gelu<<<dim3(LL / 32, 8, BB), 128>>>(attb, Wc1, bc1, c1b);

    // 9) pointwise conv2 as GEMM -> output [B, V+T, H]
    sgemm_k<true, true, false><<<dim3(HH / 128, (BB * LL) / 128, 1), 256>>>(
        c1b, HH, 0, Wc2, HH, 0, out, HH, 0, bc2, nullptr, 0, 0, BB * LL, HH, HH);
}

// round 4
// speedup vs baseline: 2.0804x; 2.0804x over previous
#include <cuda_runtime.h>
#include <cuda_fp16.h>
#include <math.h>
#include <stdint.h>

// Problem constants (B=8, V=T=1024, H=1024, L=V+T=2048)
#define BB 8
#define SS 1024
#define HH 1024
#define LL 2048
#define MID_M 341   // t2v active mid rows: 341..681
#define MID_N 512   // keys 256..767
#define WW (HH*HH)

// -------------------- scratch (device globals; no runtime alloc) ------------
__device__ __align__(128) float g_q_text[BB*SS*HH];
__device__ __align__(128) float g_k_vis [BB*SS*HH];
__device__ __align__(128) float g_v_vis [BB*SS*HH];
__device__ __align__(128) float g_q_vis [BB*SS*HH];
__device__ __align__(128) float g_k_text[BB*SS*HH];
__device__ __align__(128) float g_v_text[BB*SS*HH];
__device__ __align__(128) float g_att   [BB*LL*HH];   // attended concat [b, l, h]
__device__ __align__(128) float g_scores[BB*MID_M*MID_N];
// split-fp16 operand buffers
__device__ __align__(128) __half g_vis_hi[BB*SS*HH];
__device__ __align__(128) __half g_vis_lo[BB*SS*HH];
__device__ __align__(128) __half g_txt_hi[BB*SS*HH];
__device__ __align__(128) __half g_txt_lo[BB*SS*HH];
__device__ __align__(128) __half g_c1_hi [BB*LL*HH];
__device__ __align__(128) __half g_c1_lo [BB*LL*HH];
__device__ __align__(128) __half g_w_hi  [4*WW];      // Wq, Wk, Wv, Wc2
__device__ __align__(128) __half g_w_lo  [4*WW];

// ===================== low-level helpers ====================================
__device__ __forceinline__ uint32_t smem_to_u32(const void* p) {
    uint32_t a;
    asm("{ .reg .u64 t; cvta.to.shared.u64 t, %1; cvt.u32.u64 %0, t; }" : "=r"(a) : "l"(p));
    return a;
}
__device__ __forceinline__ void cp_async16(uint32_t saddr, const void* gptr) {
    asm volatile("cp.async.cg.shared.global [%0], [%1], 16;" :: "r"(saddr), "l"(gptr));
}
#define CP_COMMIT() asm volatile("cp.async.commit_group;" ::: "memory")
#define CP_WAIT1()  asm volatile("cp.async.wait_group 1;" ::: "memory")
#define CP_WAIT0()  asm volatile("cp.async.wait_group 0;" ::: "memory")

__device__ __forceinline__ void ldm_x4(uint32_t& r0, uint32_t& r1, uint32_t& r2, uint32_t& r3,
                                       uint32_t addr) {
    asm volatile("ldmatrix.sync.aligned.m8n8.x4.shared.b16 {%0,%1,%2,%3}, [%4];"
                 : "=r"(r0), "=r"(r1), "=r"(r2), "=r"(r3) : "r"(addr));
}
__device__ __forceinline__ void ldm_x2(uint32_t& r0, uint32_t& r1, uint32_t addr) {
    asm volatile("ldmatrix.sync.aligned.m8n8.x2.shared.b16 {%0,%1}, [%2];"
                 : "=r"(r0), "=r"(r1) : "r"(addr));
}
__device__ __forceinline__ void mma16816(float* c, const uint32_t* a, const uint32_t* b) {
    asm volatile("mma.sync.aligned.m16n8k16.row.col.f32.f16.f16.f32 "
                 "{%0,%1,%2,%3}, {%4,%5,%6,%7}, {%8,%9}, {%0,%1,%2,%3};"
                 : "+f"(c[0]), "+f"(c[1]), "+f"(c[2]), "+f"(c[3])
                 : "r"(a[0]), "r"(a[1]), "r"(a[2]), "r"(a[3]), "r"(b[0]), "r"(b[1]));
}

// =================== tensor-core split-fp16 GEMM (mma.sync) =================
// C[M,1024] = A[M,1024] @ W[1024,1024]^T + bias   (fp32 accuracy via 3 terms)
// grid = (8, M/128), 256 threads, 128 KB dynamic smem (2 stages x 4 tiles x 16KB).
#define MG_SMEM (2 * 4 * 16384)

__global__ __launch_bounds__(256, 1)
void mma_gemm(const __half* __restrict__ Ahi, const __half* __restrict__ Alo,
              const __half* __restrict__ Bhi, const __half* __restrict__ Blo,
              const float* __restrict__ bias, float* __restrict__ C)
{
    extern __shared__ char smem[];
    const uint32_t sbase = smem_to_u32(smem);
    const int tid = threadIdx.x;
    const int wid = tid >> 5, lane = tid & 31;
    const int m0 = blockIdx.y * 128, n0 = blockIdx.x * 128;
    const int m_w = (wid & 1) * 64;        // warp m offset in tile
    const int n_w = (wid >> 1) * 32;       // warp n offset in tile

    // ---- cp.async copy geometry: 256 thr x 4 x 16B per 16KB tile ----
    const int crow = tid >> 3;             // 0..31
    const int cc16 = tid & 7;              // 16B unit in 128B row

    auto issue_stage = [&](int kc, int s) {
        const int k0 = kc * 64;
        const uint32_t st = sbase + (uint32_t)s * 65536u;
        #pragma unroll
        for (int p = 0; p < 4; p++) {
            int row = p * 32 + crow;
            uint32_t soff = (uint32_t)(row * 128) + (uint32_t)((cc16 * 16) ^ ((row & 7) << 4));
            long long ga = (long long)(m0 + row) * 1024 + k0 + cc16 * 8;
            long long gb = (long long)(n0 + row) * 1024 + k0 + cc16 * 8;
            cp_async16(st + soff,          Ahi + ga);
            cp_async16(st + 16384 + soff,  Alo + ga);
            cp_async16(st + 32768 + soff,  Bhi + gb);
            cp_async16(st + 49152 + soff,  Blo + gb);
        }
    };

    // ---- per-lane ldmatrix addressing (row part + swizzle XOR constant) ----
    uint32_t aRow[4], aXor[4];             // A tiles: rows m_w+16*mt+(lane&15)
    #pragma unroll
    for (int mt = 0; mt < 4; mt++) {
        int r = m_w + 16 * mt + (lane & 15);
        aRow[mt] = (uint32_t)(r * 128);
        aXor[mt] = (uint32_t)((r & 7) << 4);
    }
    const uint32_t aCol = (uint32_t)((lane >> 4) * 16);   // k halves select
    uint32_t bRow[4], bXor[4];             // B tiles: rows n_w+8*nt+(lane&7)
    #pragma unroll
    for (int nt = 0; nt < 4; nt++) {
        int r = n_w + 8 * nt + (lane & 7);
        bRow[nt] = (uint32_t)(r * 128);
        bXor[nt] = (uint32_t)((r & 7) << 4);
    }
    const uint32_t bCol = (uint32_t)(((lane >> 3) & 1) * 16);

    float acc[4][4][4];
    #pragma unroll
    for (int mt = 0; mt < 4; mt++)
        #pragma unroll
        for (int nt = 0; nt < 4; nt++)
            #pragma unroll
            for (int q = 0; q < 4; q++) acc[mt][nt][q] = 0.f;

    auto compute = [&](int s) {
        const uint32_t st = sbase + (uint32_t)s * 65536u;
        #pragma unroll
        for (int ks = 0; ks < 4; ks++) {
            const uint32_t kb = (uint32_t)(ks * 32);
            uint32_t ah[4][4], al[4][4], bh[4][2], bl[4][2];
            #pragma unroll
            for (int mt = 0; mt < 4; mt++) {
                uint32_t ad = st + aRow[mt] + ((kb + aCol) ^ aXor[mt]);
                ldm_x4(ah[mt][0], ah[mt][1], ah[mt][2], ah[mt][3], ad);
                ldm_x4(al[mt][0], al[mt][1], al[mt][2], al[mt][3], ad + 16384);
            }
            #pragma unroll
            for (int nt = 0; nt < 4; nt++) {
                uint32_t bd = st + 32768 + bRow[nt] + ((kb + bCol) ^ bXor[nt]);
                ldm_x2(bh[nt][0], bh[nt][1], bd);
                ldm_x2(bl[nt][0], bl[nt][1], bd + 16384);
            }
            #pragma unroll
            for (int mt = 0; mt < 4; mt++)
                #pragma unroll
                for (int nt = 0; nt < 4; nt++) {
                    mma16816(acc[mt][nt], ah[mt], bh[nt]);
                    mma16816(acc[mt][nt], ah[mt], bl[nt]);
                    mma16816(acc[mt][nt], al[mt], bh[nt]);
                }
        }
    };

    // ---- pipelined mainloop over 16 K-chunks of 64 ----
    issue_stage(0, 0); CP_COMMIT();
    for (int kc = 0; kc < 16; kc++) {
        if (kc + 1 < 16) { issue_stage(kc + 1, (kc + 1) & 1); CP_COMMIT(); CP_WAIT1(); }
        else             { CP_WAIT0(); }
        __syncthreads();
        compute(kc & 1);
        __syncthreads();
    }

    // ---- epilogue: bias + fp32 store ----
    const int rq = lane >> 2, cq = (lane & 3) * 2;
    #pragma unroll
    for (int mt = 0; mt < 4; mt++) {
        int row0 = m0 + m_w + 16 * mt + rq;
        #pragma unroll
        for (int nt = 0; nt < 4; nt++) {
            int col = n0 + n_w + 8 * nt + cq;
            float b0 = bias[col], b1 = bias[col + 1];
            float2 v0 = make_float2(acc[mt][nt][0] + b0, acc[mt][nt][1] + b1);
            float2 v1 = make_float2(acc[mt][nt][2] + b0, acc[mt][nt][3] + b1);
            *(float2*)(C + (long long)row0 * 1024 + col)       = v0;
            *(float2*)(C + (long long)(row0 + 8) * 1024 + col) = v1;
        }
    }
}

// -------------------- fp32 -> (hi, lo) fp16 split ---------------------------
__global__ void split_fp16(const float4* __restrict__ x, uint2* __restrict__ hi,
                           uint2* __restrict__ lo, int n4)
{
    int i = blockIdx.x * 256 + threadIdx.x;
    if (i >= n4) return;
    float4 v = x[i];
    __half hx = __float2half_rn(v.x), hy = __float2half_rn(v.y);
    __half hz = __float2half_rn(v.z), hw = __float2half_rn(v.w);
    __half lx = __float2half_rn(v.x - __half2float(hx));
    __half ly = __float2half_rn(v.y - __half2float(hy));
    __half lz = __float2half_rn(v.z - __half2float(hz));
    __half lw = __float2half_rn(v.w - __half2float(hw));
    __half2 h0 = __halves2half2(hx, hy), h1 = __halves2half2(hz, hw);
    __half2 l0 = __halves2half2(lx, ly), l1 = __halves2half2(lz, lw);
    uint2 oh, ol;
    oh.x = *(uint32_t*)&h0; oh.y = *(uint32_t*)&h1;
    ol.x = *(uint32_t*)&l0; ol.y = *(uint32_t*)&l1;
    hi[i] = oh; lo[i] = ol;
}

// -------------------- generic fp32 SGEMM (mid-attn blocks) ------------------
template<bool TRANSB, bool BIAS, bool RESID>
__global__ __launch_bounds__(256)
void sgemm_k(const float* __restrict__ A, int lda, long long sA,
             const float* __restrict__ Bm, int ldb, long long sB,
             float* __restrict__ C, int ldc, long long sC,
             const float* __restrict__ bias,
             const float* __restrict__ Rm, int ldr, long long sR,
             int M, int N, int K)
{
    constexpr int Bb = 128, Bn = 128, Bk = 16;
    __shared__ float As[2][Bk][Bb];
    __shared__ float Bs[2][Bk][Bn];

    A  += (long long)blockIdx.z * sA;
    Bm += (long long)blockIdx.z * sB;
    C  += (long long)blockIdx.z * sC;
    if (RESID) Rm += (long long)blockIdx.z * sR;

    const int tid = threadIdx.x;
    const int bx = blockIdx.x, by = blockIdx.y;
    const int ar = tid >> 2;
    const int ac = (tid & 3) << 2;
    const int br = tid >> 5;
    const int bc = (tid & 31) << 2;

    const int warp = tid >> 5, lane = tid & 31;
    const int mb = (warp & 3) * 32 + (lane >> 3) * 8;
    const int nb = (warp >> 2) * 64 + (lane & 7) * 8;

    float4 aR[2], bR[2];
    float acc[8][8];
    #pragma unroll
    for (int i = 0; i < 8; i++)
        #pragma unroll
        for (int j = 0; j < 8; j++) acc[i][j] = 0.f;

    const int nk = K / Bk;
    {
        #pragma unroll
        for (int p = 0; p < 2; p++) {
            int m = by * Bb + ar + p * 64;
            aR[p] = (m < M) ? *(const float4*)(A + (long long)m * lda + ac)
                            : make_float4(0.f, 0.f, 0.f, 0.f);
        }
        if (TRANSB) {
            #pragma unroll
            for (int p = 0; p < 2; p++) {
                int n = bx * Bn + ar + p * 64;
                bR[p] = *(const float4*)(Bm + (long long)n * ldb + ac);
            }
        } else {
            #pragma unroll
            for (int p = 0; p < 2; p++) {
                int kk = br + p * 8;
                bR[p] = *(const float4*)(Bm + (long long)kk * ldb + bx * Bn + bc);
            }
        }
    }
    int buf = 0;
    #pragma unroll
    for (int p = 0; p < 2; p++) {
        As[buf][ac + 0][ar + p * 64] = aR[p].x;
        As[buf][ac + 1][ar + p * 64] = aR[p].y;
        As[buf][ac + 2][ar + p * 64] = aR[p].z;
        As[buf][ac + 3][ar + p * 64] = aR[p].w;
    }
    if (TRANSB) {
        #pragma unroll
        for (int p = 0; p < 2; p++) {
            Bs[buf][ac + 0][ar + p * 64] = bR[p].x;
            Bs[buf][ac + 1][ar + p * 64] = bR[p].y;
            Bs[buf][ac + 2][ar + p * 64] = bR[p].z;
            Bs[buf][ac + 3][ar + p * 64] = bR[p].w;
        }
    } else {
        #pragma unroll
        for (int p = 0; p < 2; p++)
            *(float4*)&Bs[buf][br + p * 8][bc] = bR[p];
    }
    __syncthreads();

    for (int kt = 0; kt < nk; kt++) {
        const bool more = (kt + 1 < nk);
        if (more) {
            const int k0 = (kt + 1) * Bk;
            #pragma unroll
            for (int p = 0; p < 2; p++) {
                int m = by * Bb + ar + p * 64;
                aR[p] = (m < M) ? *(const float4*)(A + (long long)m * lda + k0 + ac)
                                : make_float4(0.f, 0.f, 0.f, 0.f);
            }
            if (TRANSB) {
                #pragma unroll
                for (int p = 0; p < 2; p++) {
                    int n = bx * Bn + ar + p * 64;
                    bR[p] = *(const float4*)(Bm + (long long)n * ldb + k0 + ac);
                }
            } else {
                #pragma unroll
                for (int p = 0; p < 2; p++) {
                    int kk = br + p * 8;
                    bR[p] = *(const float4*)(Bm + (long long)(k0 + kk) * ldb + bx * Bn + bc);
                }
            }
        }
        #pragma unroll
        for (int k = 0; k < Bk; k++) {
            float a[8], bv2[8];
            *(float4*)&a[0]   = *(const float4*)&As[buf][k][mb];
            *(float4*)&a[4]   = *(const float4*)&As[buf][k][mb + 4];
            *(float4*)&bv2[0] = *(const float4*)&Bs[buf][k][nb];
            *(float4*)&bv2[4] = *(const float4*)&Bs[buf][k][nb + 4];
            #pragma unroll
            for (int i = 0; i < 8; i++)
                #pragma unroll
                for (int j = 0; j < 8; j++)
                    acc[i][j] += a[i] * bv2[j];
        }
        if (more) {
            buf ^= 1;
            #pragma unroll
            for (int p = 0; p < 2; p++) {
                As[buf][ac + 0][ar + p * 64] = aR[p].x;
                As[buf][ac + 1][ar + p * 64] = aR[p].y;
                As[buf][ac + 2][ar + p * 64] = aR[p].z;
                As[buf][ac + 3][ar + p * 64] = aR[p].w;
            }
            if (TRANSB) {
                #pragma unroll
                for (int p = 0; p < 2; p++) {
                    Bs[buf][ac + 0][ar + p * 64] = bR[p].x;
                    Bs[buf][ac + 1][ar + p * 64] = bR[p].y;
                    Bs[buf][ac + 2][ar + p * 64] = bR[p].z;
                    Bs[buf][ac + 3][ar + p * 64] = bR[p].w;
                }
            } else {
                #pragma unroll
                for (int p = 0; p < 2; p++)
                    *(float4*)&Bs[buf][br + p * 8][bc] = bR[p];
            }
            __syncthreads();
        }
    }

    float bvv[8];
    if (BIAS) {
        #pragma unroll
        for (int j = 0; j < 8; j++) bvv[j] = bias[bx * Bn + nb + j];
    }
    #pragma unroll
    for (int i = 0; i < 8; i++) {
        int m = by * Bb + mb + i;
        if (m < M) {
            float* Cp = C + (long long)m * ldc + bx * Bn + nb;
            const float* Rp = RESID ? (Rm + (long long)m * ldr + bx * Bn + nb) : (const float*)0;
            #pragma unroll
            for (int j = 0; j < 8; j += 4) {
                float4 v;
                v.x = acc[i][j + 0]; v.y = acc[i][j + 1];
                v.z = acc[i][j + 2]; v.w = acc[i][j + 3];
                if (BIAS) { v.x += bvv[j]; v.y += bvv[j + 1]; v.z += bvv[j + 2]; v.w += bvv[j + 3]; }
                if (RESID) {
                    float4 rv = *(const float4*)(Rp + j);
                    v.x += rv.x; v.y += rv.y; v.z += rv.z; v.w += rv.w;
                }
                *(float4*)(Cp + j) = v;
            }
        }
    }
}

// -------------------- copy text features into concat buffer ----------------
__global__ void copy_text(const float4* __restrict__ src, float4* __restrict__ dst)
{
    int idx = blockIdx.x * 256 + threadIdx.x;
    int b = idx >> 18;
    int r = idx & 262143;
    dst[(long long)b * 524288 + 262144 + r] = src[idx];
}

// -------------------- v2t attention (<=13 keys/row) + residual --------------
__global__ __launch_bounds__(128) void v2t_attn(
    const float* __restrict__ qvis, const float* __restrict__ ktext,
    const float* __restrict__ vtext, const float* __restrict__ visf,
    float* __restrict__ att)
{
    const int i = blockIdx.x, b = blockIdx.y;
    const int tid = threadIdx.x, lane = tid & 31, warp = tid >> 5;
    const int s0 = (i < 1016) ? i : 1016;
    const int nk = (i < 5) ? (i + 8) : 13;

    const float* q = qvis + ((long long)b * SS + i) * HH;
    float qr[8];
    #pragma unroll
    for (int r = 0; r < 8; r++) qr[r] = q[r * 128 + tid];

    const float* kb = ktext + (long long)b * SS * HH;
    float p[13];
    #pragma unroll
    for (int j = 0; j < 13; j++) {
        float s = 0.f;
        if (j < nk) {
            int kj = (i < 5) ? j : ((j < 5) ? j : (s0 + j - 5));
            const float* kp = kb + (long long)kj * HH + tid;
            #pragma unroll
            for (int r = 0; r < 8; r++) s += qr[r] * kp[r * 128];
        }
        p[j] = s;
    }
    #pragma unroll
    for (int j = 0; j < 13; j++) {
        #pragma unroll
        for (int off = 16; off; off >>= 1) p[j] += __shfl_xor_sync(0xffffffffu, p[j], off);
    }
    __shared__ float red[4][13];
    if (lane == 0) {
        #pragma unroll
        for (int j = 0; j < 13; j++) red[warp][j] = p[j];
    }
    __syncthreads();

    float sc[13];
    float mx = -3.4e38f;
    #pragma unroll
    for (int j = 0; j < 13; j++) {
        sc[j] = red[0][j] + red[1][j] + red[2][j] + red[3][j];
        if (j < nk) mx = fmaxf(mx, sc[j]);
    }
    float sum = 0.f;
    #pragma unroll
    for (int j = 0; j < 13; j++) {
        float e = (j < nk) ? expf(sc[j] - mx) : 0.f;
        sc[j] = e; sum += e;
    }
    const float inv = 1.f / sum;

    const float* vf = visf + ((long long)b * SS + i) * HH;
    const float* vb = vtext + (long long)b * SS * HH;
    float* op = att + ((long long)b * LL + i) * HH;
    #pragma unroll
    for (int r = 0; r < 8; r++) {
        int h = r * 128 + tid;
        float a2 = vf[h];
        #pragma unroll
        for (int j = 0; j < 13; j++) {
            if (j < nk) {
                int kj = (i < 5) ? j : ((j < 5) ? j : (s0 + j - 5));
                a2 += sc[j] * inv * vb[(long long)kj * HH + h];
            }
        }
        op[h] = a2;
    }
}

// -------------------- t2v rows 0..4 (full softmax over 1024 keys) -----------
__global__ __launch_bounds__(256) void t2v_full_rows(
    const float* __restrict__ qtext, const float* __restrict__ kvis,
    const float* __restrict__ vvis, float* __restrict__ att)
{
    const int r = blockIdx.x, b = blockIdx.y;
    const int tid = threadIdx.x, lane = tid & 31, warp = tid >> 5;
    __shared__ float qs[1024];
    __shared__ float sc[1024];
    __shared__ float red[8];

    const float* q = qtext + ((long long)b * SS + r) * HH;
    for (int h = tid; h < 1024; h += 256) qs[h] = q[h];
    __syncthreads();

    const float* kb = kvis + (long long)b * SS * HH;
    for (int t = warp * 128; t < warp * 128 + 128; t++) {
        const float* kp = kb + (long long)t * HH;
        float p = 0.f;
        #pragma unroll
        for (int c = 0; c < 32; c++) p += qs[c * 32 + lane] * kp[c * 32 + lane];
        #pragma unroll
        for (int off = 16; off; off >>= 1) p += __shfl_xor_sync(0xffffffffu, p, off);
        if (lane == 0) sc[t] = p;
    }
    __syncthreads();

    float m = -3.4e38f;
    for (int t = tid; t < 1024; t += 256) m = fmaxf(m, sc[t]);
    #pragma unroll
    for (int off = 16; off; off >>= 1) m = fmaxf(m, __shfl_xor_sync(0xffffffffu, m, off));
    if (lane == 0) red[warp] = m;
    __syncthreads();
    float mx = red[0];
    #pragma unroll
    for (int k = 1; k < 8; k++) mx = fmaxf(mx, red[k]);

    float s = 0.f;
    for (int t = tid; t < 1024; t += 256) { float e = expf(sc[t] - mx); sc[t] = e; s += e; }
    #pragma unroll
    for (int off = 16; off; off >>= 1) s += __shfl_xor_sync(0xffffffffu, s, off);
    __syncthreads();
    if (lane == 0) red[warp] = s;
    __syncthreads();
    float tot = 0.f;
    #pragma unroll
    for (int k = 0; k < 8; k++) tot += red[k];
    const float inv = 1.f / tot;

    const float* vb = vvis + (long long)b * SS * HH;
    float* op = att + ((long long)b * LL + 1024 + r) * HH;
    float accv[4] = {0.f, 0.f, 0.f, 0.f};
    for (int t = 0; t < 1024; t++) {
        float pw = sc[t];
        const float* vr = vb + (long long)t * HH + tid;
        accv[0] += pw * vr[0];
        accv[1] += pw * vr[256];
        accv[2] += pw * vr[512];
        accv[3] += pw * vr[768];
    }
    #pragma unroll
    for (int k = 0; k < 4; k++) op[tid + k * 256] += accv[k] * inv;
}

// -------------------- softmax over 512-col rows (t2v mid block) -------------
__global__ __launch_bounds__(256) void softmax512(float* __restrict__ S)
{
    float* row = S + (long long)blockIdx.x * 512;
    const int tid = threadIdx.x, lane = tid & 31, warp = tid >> 5;
    __shared__ float red[8];
    float a = row[tid], b2 = row[tid + 256];
    float m = fmaxf(a, b2);
    #pragma unroll
    for (int off = 16; off; off >>= 1) m = fmaxf(m, __shfl_xor_sync(0xffffffffu, m, off));
    if (lane == 0) red[warp] = m;
    __syncthreads();
    float mx = red[0];
    #pragma unroll
    for (int k = 1; k < 8; k++) mx = fmaxf(mx, red[k]);
    float e0 = expf(a - mx), e1 = expf(b2 - mx);
    float s = e0 + e1;
    #pragma unroll
    for (int off = 16; off; off >>= 1) s += __shfl_xor_sync(0xffffffffu, s, off);
    __syncthreads();
    if (lane == 0) red[warp] = s;
    __syncthreads();
    float tot = 0.f;
    #pragma unroll
    for (int k = 0; k < 8; k++) tot += red[k];
    float inv = 1.f / tot;
    row[tid] = e0 * inv;
    row[tid + 256] = e1 * inv;
}

// --------- grouped conv1 (k=3, groups=8) + exact GELU -> split fp16 ---------
__global__ __launch_bounds__(128) void conv1_gelu(
    const float* __restrict__ att, const float* __restrict__ W,
    const float* __restrict__ bias, __half* __restrict__ ohi, __half* __restrict__ olo)
{
    __shared__ float s[34][128];
    __shared__ float Ws[128][49];
    const int b = blockIdx.z, g = blockIdx.y;
    const int l0 = blockIdx.x * 32;
    const int tid = threadIdx.x;

    const float* base = att + (long long)b * LL * HH + g * 128;
    #pragma unroll
    for (int j = 0; j < 34; j++) {
        int l = l0 - 1 + j;
        s[j][tid] = (l >= 0 && l < LL) ? base[(long long)l * HH + tid] : 0.f;
    }
    const int o = g * 128 + tid;
    float acc[32];
    #pragma unroll
    for (int l = 0; l < 32; l++) acc[l] = 0.f;

    for (int ic = 0; ic < 8; ic++) {
        __syncthreads();
        for (int t = tid; t < 128 * 48; t += 128) {
            int oo = t / 48, j = t % 48;
            Ws[oo][j] = W[((long long)(g * 128 + oo)) * 384 + ic * 48 + j];
        }
        __syncthreads();
        #pragma unroll
        for (int ii = 0; ii < 16; ii++) {
            int i = ic * 16 + ii;
            float w0 = Ws[tid][ii * 3 + 0];
            float w1 = Ws[tid][ii * 3 + 1];
            float w2 = Ws[tid][ii * 3 + 2];
            #pragma unroll
            for (int l = 0; l < 32; l++)
                acc[l] += w0 * s[l][i] + w1 * s[l + 1][i] + w2 * s[l + 2][i];
        }
    }
    const float bo = bias[o];
    long long obase = ((long long)b * LL + l0) * HH + o;
    #pragma unroll
    for (int l = 0; l < 32; l++) {
        float x = acc[l] + bo;
        float y = 0.5f * x * (1.0f + erff(x * 0.70710678118654752f));
        __half h = __float2half_rn(y);
        ohi[obase + (long long)l * HH] = h;
        olo[obase + (long long)l * HH] = __float2half_rn(y - __half2float(h));
    }
}

// -------------------- launcher ----------------------------------------------
extern "C" void kernel_launch(void* const* d_in, const int* in_sizes, int n_in,
                              void* d_out, int out_size)
{
    (void)in_sizes; (void)n_in; (void)out_size;
    const float* vis = (const float*)d_in[0];
    const float* txt = (const float*)d_in[1];
    const float* Wq  = (const float*)d_in[2];  const float* bq  = (const float*)d_in[3];
    const float* Wk  = (const float*)d_in[4];  const float* bk  = (const float*)d_in[5];
    const float* Wv  = (const float*)d_in[6];  const float* bv  = (const float*)d_in[7];
    const float* Wc1 = (const float*)d_in[8];  const float* bc1 = (const float*)d_in[9];
    const float* Wc2 = (const float*)d_in[10]; const float* bc2 = (const float*)d_in[11];
    float* out = (float*)d_out;

    float *qt, *kv, *vv, *qv, *kt, *vt, *attb, *scb;
    __half *vish, *visl, *txth, *txtl, *c1h, *c1l, *wh, *wl;
    cudaGetSymbolAddress((void**)&qt,  g_q_text);
    cudaGetSymbolAddress((void**)&kv,  g_k_vis);
    cudaGetSymbolAddress((void**)&vv,  g_v_vis);
    cudaGetSymbolAddress((void**)&qv,  g_q_vis);
    cudaGetSymbolAddress((void**)&kt,  g_k_text);
    cudaGetSymbolAddress((void**)&vt,  g_v_text);
    cudaGetSymbolAddress((void**)&attb, g_att);
    cudaGetSymbolAddress((void**)&scb, g_scores);
    cudaGetSymbolAddress((void**)&vish, g_vis_hi);
    cudaGetSymbolAddress((void**)&visl, g_vis_lo);
    cudaGetSymbolAddress((void**)&txth, g_txt_hi);
    cudaGetSymbolAddress((void**)&txtl, g_txt_lo);
    cudaGetSymbolAddress((void**)&c1h, g_c1_hi);
    cudaGetSymbolAddress((void**)&c1l, g_c1_lo);
    cudaGetSymbolAddress((void**)&wh,  g_w_hi);
    cudaGetSymbolAddress((void**)&wl,  g_w_lo);

    cudaFuncSetAttribute(mma_gemm, cudaFuncAttributeMaxDynamicSharedMemorySize, MG_SMEM);

    const long long SH = (long long)SS * HH;
    const long long LH = (long long)LL * HH;
    const long long SCs = (long long)MID_M * MID_N;

    // 0) split inputs & weights into fp16 hi/lo
    int n4in = BB * SS * HH / 4;
    split_fp16<<<(n4in + 255) / 256, 256>>>((const float4*)vis, (uint2*)vish, (uint2*)visl, n4in);
    split_fp16<<<(n4in + 255) / 256, 256>>>((const float4*)txt, (uint2*)txth, (uint2*)txtl, n4in);
    int n4w = WW / 4;
    split_fp16<<<(n4w + 255) / 256, 256>>>((const float4*)Wq,  (uint2*)(wh + 0 * WW), (uint2*)(wl + 0 * WW), n4w);
    split_fp16<<<(n4w + 255) / 256, 256>>>((const float4*)Wk,  (uint2*)(wh + 1 * WW), (uint2*)(wl + 1 * WW), n4w);
    split_fp16<<<(n4w + 255) / 256, 256>>>((const float4*)Wv,  (uint2*)(wh + 2 * WW), (uint2*)(wl + 2 * WW), n4w);
    split_fp16<<<(n4w + 255) / 256, 256>>>((const float4*)Wc2, (uint2*)(wh + 3 * WW), (uint2*)(wl + 3 * WW), n4w);

    // 1) projections on tensor cores (split-fp16, 3-term mma.sync)
    dim3 gp(HH / 128, BB * SS / 128);
    mma_gemm<<<gp, 256, MG_SMEM>>>(txth, txtl, wh + 0 * WW, wl + 0 * WW, bq, qt);
    mma_gemm<<<gp, 256, MG_SMEM>>>(vish, visl, wh + 1 * WW, wl + 1 * WW, bk, kv);
    mma_gemm<<<gp, 256, MG_SMEM>>>(vish, visl, wh + 2 * WW, wl + 2 * WW, bv, vv);
    mma_gemm<<<gp, 256, MG_SMEM>>>(vish, visl, wh + 0 * WW, wl + 0 * WW, bq, qv);
    mma_gemm<<<gp, 256, MG_SMEM>>>(txth, txtl, wh + 1 * WW, wl + 1 * WW, bk, kt);
    mma_gemm<<<gp, 256, MG_SMEM>>>(txth, txtl, wh + 2 * WW, wl + 2 * WW, bv, vt);

    // 2) init text half of concat buffer with residual text features
    copy_text<<<8192, 256>>>((const float4*)txt, (float4*)attb);

    // 3) v2t sparse attention (<=13 keys) + visual residual
    v2t_attn<<<dim3(SS, BB), 128>>>(qv, kt, vt, vis, attb);

    // 4) t2v rows 0..4: full softmax over all visual keys
    t2v_full_rows<<<dim3(5, BB), 256>>>(qt, kv, vv, attb);

    // 5) t2v mid block scores (fp32 SIMT — precision critical, small)
    sgemm_k<true, false, false><<<dim3(MID_N / 128, 3, BB), 256>>>(
        qt + 341 * HH, HH, SH, kv + 256 * HH, HH, SH,
        scb, MID_N, SCs, nullptr, nullptr, 0, 0, MID_M, MID_N, HH);

    // 6) row softmax
    softmax512<<<BB * MID_M, 256>>>(scb);

    // 7) AV + text residual
    sgemm_k<false, false, true><<<dim3(HH / 128, 3, BB), 256>>>(
        scb, MID_N, SCs, vv + 256 * HH, HH, SH,
        attb + (long long)(1024 + 341) * HH, HH, LH,
        nullptr, txt + 341 * HH, HH, SH, MID_M, HH, MID_N);

    // 8) grouped conv1 + exact GELU -> split fp16 directly
    conv1_gelu<<<dim3(LL / 32, 8, BB), 128>>>(attb, Wc1, bc1, c1h, c1l);

    // 9) pointwise conv2 on tensor cores -> output
    mma_gemm<<<dim3(HH / 128, BB * LL / 128), 256, MG_SMEM>>>(
        c1h, c1l, wh + 3 * WW, wl + 3 * WW, bc2, out);
}

// round 5
// speedup vs baseline: 2.6247x; 1.2617x over previous
#include <cuda_runtime.h>
#include <cuda_fp16.h>
#include <math.h>
#include <stdint.h>

// Problem constants (B=8, V=T=1024, H=1024, L=V+T=2048)
#define BB 8
#define SS 1024
#define HH 1024
#define LL 2048
#define MID_M 341   // t2v active mid rows: 341..681
#define MID_N 512   // keys 256..767
#define WW (HH*HH)

// -------------------- scratch (device globals; no runtime alloc) ------------
__device__ __align__(128) float g_q_text[BB*SS*HH];
__device__ __align__(128) float g_k_vis [BB*SS*HH];
__device__ __align__(128) float g_v_vis [BB*SS*HH];
__device__ __align__(128) float g_q_vis [BB*SS*HH];
__device__ __align__(128) float g_k_text[BB*SS*HH];
__device__ __align__(128) float g_v_text[BB*SS*HH];
__device__ __align__(128) float g_att   [BB*LL*HH];   // attended concat [b, l, h]
__device__ __align__(128) float g_scores[BB*MID_M*MID_N];
// split-fp16 operand buffers
__device__ __align__(128) __half g_vis_hi[BB*SS*HH];
__device__ __align__(128) __half g_vis_lo[BB*SS*HH];
__device__ __align__(128) __half g_txt_hi[BB*SS*HH];
__device__ __align__(128) __half g_txt_lo[BB*SS*HH];
__device__ __align__(128) __half g_c1_hi [BB*LL*HH];
__device__ __align__(128) __half g_c1_lo [BB*LL*HH];
__device__ __align__(128) __half g_w_hi  [4*WW];      // Wq, Wk, Wv, Wc2
__device__ __align__(128) __half g_w_lo  [4*WW];
__device__ __align__(128) __half g_qt_hi [BB*SS*HH];
__device__ __align__(128) __half g_qt_lo [BB*SS*HH];
__device__ __align__(128) __half g_kv_hi [BB*SS*HH];
__device__ __align__(128) __half g_kv_lo [BB*SS*HH];
__device__ __align__(128) __half g_att_hi[BB*LL*HH];
__device__ __align__(128) __half g_att_lo[BB*LL*HH];
__device__ __align__(128) __half g_wc1r_hi[HH*384];   // conv1 weights reordered [oc, tap*128+ic]
__device__ __align__(128) __half g_wc1r_lo[HH*384];

// ===================== low-level helpers ====================================
__device__ __forceinline__ uint32_t smem_to_u32(const void* p) {
    uint32_t a;
    asm("{ .reg .u64 t; cvta.to.shared.u64 t, %1; cvt.u32.u64 %0, t; }" : "=r"(a) : "l"(p));
    return a;
}
__device__ __forceinline__ void cp_async16(uint32_t saddr, const void* gptr) {
    asm volatile("cp.async.cg.shared.global [%0], [%1], 16;" :: "r"(saddr), "l"(gptr));
}
#define CP_COMMIT() asm volatile("cp.async.commit_group;" ::: "memory")
#define CP_WAIT1()  asm volatile("cp.async.wait_group 1;" ::: "memory")
#define CP_WAIT0()  asm volatile("cp.async.wait_group 0;" ::: "memory")

__device__ __forceinline__ void ldm_x4(uint32_t& r0, uint32_t& r1, uint32_t& r2, uint32_t& r3,
                                       uint32_t addr) {
    asm volatile("ldmatrix.sync.aligned.m8n8.x4.shared.b16 {%0,%1,%2,%3}, [%4];"
                 : "=r"(r0), "=r"(r1), "=r"(r2), "=r"(r3) : "r"(addr));
}
__device__ __forceinline__ void ldm_x2(uint32_t& r0, uint32_t& r1, uint32_t addr) {
    asm volatile("ldmatrix.sync.aligned.m8n8.x2.shared.b16 {%0,%1}, [%2];"
                 : "=r"(r0), "=r"(r1) : "r"(addr));
}
__device__ __forceinline__ void mma16816(float* c, const uint32_t* a, const uint32_t* b) {
    asm volatile("mma.sync.aligned.m16n8k16.row.col.f32.f16.f16.f32 "
                 "{%0,%1,%2,%3}, {%4,%5,%6,%7}, {%8,%9}, {%0,%1,%2,%3};"
                 : "+f"(c[0]), "+f"(c[1]), "+f"(c[2]), "+f"(c[3])
                 : "r"(a[0]), "r"(a[1]), "r"(a[2]), "r"(a[3]), "r"(b[0]), "r"(b[1]));
}
__device__ __forceinline__ void split2(float v, __half& h, __half& l) {
    h = __float2half_rn(v);
    l = __float2half_rn(v - __half2float(h));
}

// =================== tensor-core split-fp16 GEMM (mma.sync) =================
// C[M,N] = A[M,K] @ B[N,K]^T (+bias) (+nothing), 3-term split-fp16, fp32 out.
// A/B row stride = K. grid = (N/128, ceil(M/128), batch). 256 threads.
// 3-stage cp.async pipeline, 192KB dynamic smem.
#define MG_SMEM (3 * 65536)

template<bool BIAS, bool HALFOUT, bool GUARD>
__global__ __launch_bounds__(256, 1)
void mma_gemm(const __half* __restrict__ Ahi, const __half* __restrict__ Alo, long long sA,
              const __half* __restrict__ Bhi, const __half* __restrict__ Blo, long long sB,
              float* __restrict__ C, long long sC, int ldc,
              const float* __restrict__ bias,
              __half* __restrict__ Chi, __half* __restrict__ Clo,
              int M, int K)
{
    extern __shared__ char smem[];
    const uint32_t sbase = smem_to_u32(smem);
    const int tid = threadIdx.x;
    const int wid = tid >> 5, lane = tid & 31;
    const int m0 = blockIdx.y * 128, n0 = blockIdx.x * 128;
    const int m_w = (wid & 1) * 64;
    const int n_w = (wid >> 1) * 32;
    const int z = blockIdx.z;
    Ahi += z * sA; Alo += z * sA;
    Bhi += z * sB; Blo += z * sB;
    C   += z * sC;
    if (HALFOUT) { Chi += z * sC; Clo += z * sC; }

    const int crow = tid >> 3;             // 0..31
    const int cc16 = tid & 7;              // 16B unit in 128B row
    const int nk = K >> 6;

    auto issue_stage = [&](int kc, int s) {
        const int k0 = kc * 64;
        const uint32_t st = sbase + (uint32_t)s * 65536u;
        #pragma unroll
        for (int p = 0; p < 4; p++) {
            int row = p * 32 + crow;
            uint32_t soff = (uint32_t)(row * 128) + (uint32_t)((cc16 * 16) ^ ((row & 7) << 4));
            int gm = m0 + row;
            if (GUARD) gm = (gm < M) ? gm : (M - 1);
            long long ga = (long long)gm * K + k0 + cc16 * 8;
            long long gb = (long long)(n0 + row) * K + k0 + cc16 * 8;
            cp_async16(st + soff,          Ahi + ga);
            cp_async16(st + 16384 + soff,  Alo + ga);
            cp_async16(st + 32768 + soff,  Bhi + gb);
            cp_async16(st + 49152 + soff,  Blo + gb);
        }
    };

    uint32_t aRow[4], aXor[4];
    #pragma unroll
    for (int mt = 0; mt < 4; mt++) {
        int r = m_w + 16 * mt + (lane & 15);
        aRow[mt] = (uint32_t)(r * 128);
        aXor[mt] = (uint32_t)((r & 7) << 4);
    }
    const uint32_t aCol = (uint32_t)((lane >> 4) * 16);
    uint32_t bRow[4], bXor[4];
    #pragma unroll
    for (int nt = 0; nt < 4; nt++) {
        int r = n_w + 8 * nt + (lane & 7);
        bRow[nt] = (uint32_t)(r * 128);
        bXor[nt] = (uint32_t)((r & 7) << 4);
    }
    const uint32_t bCol = (uint32_t)(((lane >> 3) & 1) * 16);

    float acc[4][4][4];
    #pragma unroll
    for (int mt = 0; mt < 4; mt++)
        #pragma unroll
        for (int nt = 0; nt < 4; nt++)
            #pragma unroll
            for (int q = 0; q < 4; q++) acc[mt][nt][q] = 0.f;

    auto compute = [&](int s) {
        const uint32_t st = sbase + (uint32_t)s * 65536u;
        #pragma unroll
        for (int ks = 0; ks < 4; ks++) {
            const uint32_t kb = (uint32_t)(ks * 32);
            uint32_t ah[4][4], al[4][4], bh[4][2], bl[4][2];
            #pragma unroll
            for (int mt = 0; mt < 4; mt++) {
                uint32_t ad = st + aRow[mt] + ((kb + aCol) ^ aXor[mt]);
                ldm_x4(ah[mt][0], ah[mt][1], ah[mt][2], ah[mt][3], ad);
                ldm_x4(al[mt][0], al[mt][1], al[mt][2], al[mt][3], ad + 16384);
            }
            #pragma unroll
            for (int nt = 0; nt < 4; nt++) {
                uint32_t bd = st + 32768 + bRow[nt] + ((kb + bCol) ^ bXor[nt]);
                ldm_x2(bh[nt][0], bh[nt][1], bd);
                ldm_x2(bl[nt][0], bl[nt][1], bd + 16384);
            }
            #pragma unroll
            for (int mt = 0; mt < 4; mt++)
                #pragma unroll
                for (int nt = 0; nt < 4; nt++) {
                    mma16816(acc[mt][nt], ah[mt], bh[nt]);
                    mma16816(acc[mt][nt], ah[mt], bl[nt]);
                    mma16816(acc[mt][nt], al[mt], bh[nt]);
                }
        }
    };

    // ---- 3-stage pipelined mainloop ----
    issue_stage(0, 0); CP_COMMIT();
    issue_stage(1, 1); CP_COMMIT();
    for (int kc = 0; kc < nk; kc++) {
        if (kc + 1 < nk) { CP_WAIT1(); } else { CP_WAIT0(); }
        __syncthreads();
        if (kc + 2 < nk) { issue_stage(kc + 2, (kc + 2) % 3); CP_COMMIT(); }
        compute(kc % 3);
    }

    // ---- epilogue: bias + fp32 (+hi/lo) store ----
    const int rq = lane >> 2, cq = (lane & 3) * 2;
    #pragma unroll
    for (int mt = 0; mt < 4; mt++) {
        int row0 = m0 + m_w + 16 * mt + rq;
        #pragma unroll
        for (int nt = 0; nt < 4; nt++) {
            int col = n0 + n_w + 8 * nt + cq;
            float b0 = 0.f, b1 = 0.f;
            if (BIAS) { b0 = bias[col]; b1 = bias[col + 1]; }
            float v00 = acc[mt][nt][0] + b0, v01 = acc[mt][nt][1] + b1;
            float v10 = acc[mt][nt][2] + b0, v11 = acc[mt][nt][3] + b1;
            #pragma unroll
            for (int rr = 0; rr < 2; rr++) {
                int row = row0 + rr * 8;
                if (GUARD && row >= M) continue;
                float x0 = rr ? v10 : v00, x1 = rr ? v11 : v01;
                long long idx = (long long)row * ldc + col;
                *(float2*)(C + idx) = make_float2(x0, x1);
                if (HALFOUT) {
                    __half h0, l0h, h1, l1h;
                    split2(x0, h0, l0h); split2(x1, h1, l1h);
                    *(__half2*)(Chi + idx) = __halves2half2(h0, h1);
                    *(__half2*)(Clo + idx) = __halves2half2(l0h, l1h);
                }
            }
        }
    }
}

// =================== conv1 (grouped k=3) on tensor cores ====================
// out[b, l, g*128+oc] = GELU( bias + sum_{tap,ic} att[b, l+tap-1, g*128+ic] *
//                              Wr[g*128+oc, tap*128+ic] )  -> hi/lo fp16
// grid = (L/128, 8 groups, B). 256 threads. smem = x[130][128]h/l + W[128][128]h/l.
#define CV_SMEM (2*33280 + 2*32768)

__global__ __launch_bounds__(256, 1)
void conv1_mma(const __half* __restrict__ xh, const __half* __restrict__ xl,
               const __half* __restrict__ wh, const __half* __restrict__ wl,
               const float* __restrict__ bias,
               __half* __restrict__ oh, __half* __restrict__ ol)
{
    extern __shared__ char smem[];
    const uint32_t sb = smem_to_u32(smem);
    const int tid = threadIdx.x, wid = tid >> 5, lane = tid & 31;
    const int l0 = blockIdx.x * 128, g = blockIdx.y, b = blockIdx.z;
    const int m_w = (wid & 1) * 64, n_w = (wid >> 1) * 32;
    const uint32_t XH = sb, WH = sb + 66560u;

    // load x region rows l0-1 .. l0+128 (130 rows x 128 ch), swizzled 256B rows
    for (int t = tid; t < 2080; t += 256) {
        int r = t >> 4, c16 = t & 15;
        int l = l0 - 1 + r;
        uint32_t d = (uint32_t)(r * 256) + (uint32_t)((c16 * 16) ^ ((r & 7) << 4));
        uint4 vh = make_uint4(0u, 0u, 0u, 0u), vl = vh;
        if (l >= 0 && l < LL) {
            long long gidx = ((long long)b * LL + l) * HH + g * 128 + c16 * 8;
            vh = *(const uint4*)(xh + gidx);
            vl = *(const uint4*)(xl + gidx);
        }
        *(uint4*)(smem + d)         = vh;
        *(uint4*)(smem + 33280 + d) = vl;
    }

    float acc[4][4][4];
    #pragma unroll
    for (int mt = 0; mt < 4; mt++)
        #pragma unroll
        for (int nt = 0; nt < 4; nt++)
            #pragma unroll
            for (int q = 0; q < 4; q++) acc[mt][nt][q] = 0.f;

    const uint32_t aCol = (uint32_t)((lane >> 4) * 16);
    const uint32_t bCol = (uint32_t)(((lane >> 3) & 1) * 16);

    for (int tap = 0; tap < 3; tap++) {
        __syncthreads();   // previous tap's W reads complete
        for (int t = tid; t < 2048; t += 256) {
            int r = t >> 4, c16 = t & 15;
            uint32_t d = (uint32_t)(r * 256) + (uint32_t)((c16 * 16) ^ ((r & 7) << 4));
            long long widx = (long long)(g * 128 + r) * 384 + tap * 128 + c16 * 8;
            *(uint4*)(smem + 66560 + d) = *(const uint4*)(wh + widx);
            *(uint4*)(smem + 99328 + d) = *(const uint4*)(wl + widx);
        }
        __syncthreads();   // W (and x, first pass) visible

        #pragma unroll
        for (int ks = 0; ks < 8; ks++) {
            const uint32_t kb = (uint32_t)(ks * 32);
            uint32_t ah[4][4], al[4][4], bh[4][2], bl[4][2];
            #pragma unroll
            for (int mt = 0; mt < 4; mt++) {
                int ar = m_w + 16 * mt + (lane & 15) + tap;
                uint32_t ad = XH + (uint32_t)(ar * 256) + ((kb + aCol) ^ (uint32_t)((ar & 7) << 4));
                ldm_x4(ah[mt][0], ah[mt][1], ah[mt][2], ah[mt][3], ad);
                ldm_x4(al[mt][0], al[mt][1], al[mt][2], al[mt][3], ad + 33280u);
            }
            #pragma unroll
            for (int nt = 0; nt < 4; nt++) {
                int br = n_w + 8 * nt + (lane & 7);
                uint32_t bd = WH + (uint32_t)(br * 256) + ((kb + bCol) ^ (uint32_t)((br & 7) << 4));
                ldm_x2(bh[nt][0], bh[nt][1], bd);
                ldm_x2(bl[nt][0], bl[nt][1], bd + 32768u);
            }
            #pragma unroll
            for (int mt = 0; mt < 4; mt++)
                #pragma unroll
                for (int nt = 0; nt < 4; nt++) {
                    mma16816(acc[mt][nt], ah[mt], bh[nt]);
                    mma16816(acc[mt][nt], ah[mt], bl[nt]);
                    mma16816(acc[mt][nt], al[mt], bh[nt]);
                }
        }
    }

    // epilogue: bias + exact GELU -> hi/lo halves
    const int rq = lane >> 2, cq = (lane & 3) * 2;
    #pragma unroll
    for (int mt = 0; mt < 4; mt++) {
        int row0 = l0 + m_w + 16 * mt + rq;
        #pragma unroll
        for (int nt = 0; nt < 4; nt++) {
            int ch = g * 128 + n_w + 8 * nt + cq;
            float b0 = bias[ch], b1 = bias[ch + 1];
            #pragma unroll
            for (int rr = 0; rr < 2; rr++) {
                int row = row0 + rr * 8;
                float x0 = acc[mt][nt][rr * 2 + 0] + b0;
                float x1 = acc[mt][nt][rr * 2 + 1] + b1;
                float y0 = 0.5f * x0 * (1.0f + erff(x0 * 0.70710678118654752f));
                float y1 = 0.5f * x1 * (1.0f + erff(x1 * 0.70710678118654752f));
                __half h0, l0h, h1, l1h;
                split2(y0, h0, l0h); split2(y1, h1, l1h);
                long long idx = ((long long)b * LL + row) * HH + ch;
                *(__half2*)(oh + idx) = __halves2half2(h0, h1);
                *(__half2*)(ol + idx) = __halves2half2(l0h, l1h);
            }
        }
    }
}

// -------------------- fp32 -> (hi, lo) fp16 split ---------------------------
__global__ void split_fp16(const float4* __restrict__ x, uint2* __restrict__ hi,
                           uint2* __restrict__ lo, int n4)
{
    int i = blockIdx.x * 256 + threadIdx.x;
    if (i >= n4) return;
    float4 v = x[i];
    __half hx, lx, hy, ly, hz, lz, hw, lw;
    split2(v.x, hx, lx); split2(v.y, hy, ly);
    split2(v.z, hz, lz); split2(v.w, hw, lw);
    __half2 h0 = __halves2half2(hx, hy), h1 = __halves2half2(hz, hw);
    __half2 l0 = __halves2half2(lx, ly), l1 = __halves2half2(lz, lw);
    uint2 oh2, ol2;
    oh2.x = *(uint32_t*)&h0; oh2.y = *(uint32_t*)&h1;
    ol2.x = *(uint32_t*)&l0; ol2.y = *(uint32_t*)&l1;
    hi[i] = oh2; lo[i] = ol2;
}

// -------------- conv1 weight reorder + split: W[o, ic, 3] -> [o, tap*128+ic]
__global__ void wc1_transform(const float* __restrict__ W, __half* __restrict__ wh,
                              __half* __restrict__ wl)
{
    int idx = blockIdx.x * 256 + threadIdx.x;   // total 1024*384
    if (idx >= HH * 384) return;
    int o = idx / 384, k = idx % 384;
    int tap = k >> 7, ic = k & 127;
    float v = W[(long long)o * 384 + ic * 3 + tap];
    __half h, l;
    split2(v, h, l);
    wh[idx] = h; wl[idx] = l;
}

// -------------------- generic fp32 SGEMM (AV block) -------------------------
template<bool TRANSB, bool BIAS, bool RESID, bool HALFOUT>
__global__ __launch_bounds__(256)
void sgemm_k(const float* __restrict__ A, int lda, long long sA,
             const float* __restrict__ Bm, int ldb, long long sB,
             float* __restrict__ C, int ldc, long long sC,
             const float* __restrict__ bias,
             const float* __restrict__ Rm, int ldr, long long sR,
             __half* __restrict__ Chi, __half* __restrict__ Clo,
             int M, int N, int K)
{
    constexpr int Bb = 128, Bn = 128, Bk = 16;
    __shared__ float As[2][Bk][Bb];
    __shared__ float Bs[2][Bk][Bn];

    A  += (long long)blockIdx.z * sA;
    Bm += (long long)blockIdx.z * sB;
    C  += (long long)blockIdx.z * sC;
    if (RESID) Rm += (long long)blockIdx.z * sR;
    if (HALFOUT) { Chi += (long long)blockIdx.z * sC; Clo += (long long)blockIdx.z * sC; }

    const int tid = threadIdx.x;
    const int bx = blockIdx.x, by = blockIdx.y;
    const int ar = tid >> 2;
    const int ac = (tid & 3) << 2;
    const int br = tid >> 5;
    const int bc = (tid & 31) << 2;

    const int warp = tid >> 5, lane = tid & 31;
    const int mb = (warp & 3) * 32 + (lane >> 3) * 8;
    const int nb = (warp >> 2) * 64 + (lane & 7) * 8;

    float4 aR[2], bR[2];
    float acc[8][8];
    #pragma unroll
    for (int i = 0; i < 8; i++)
        #pragma unroll
        for (int j = 0; j < 8; j++) acc[i][j] = 0.f;

    const int nk = K / Bk;
    {
        #pragma unroll
        for (int p = 0; p < 2; p++) {
            int m = by * Bb + ar + p * 64;
            aR[p] = (m < M) ? *(const float4*)(A + (long long)m * lda + ac)
                            : make_float4(0.f, 0.f, 0.f, 0.f);
        }
        if (TRANSB) {
            #pragma unroll
            for (int p = 0; p < 2; p++) {
                int n = bx * Bn + ar + p * 64;
                bR[p] = *(const float4*)(Bm + (long long)n * ldb + ac);
            }
        } else {
            #pragma unroll
            for (int p = 0; p < 2; p++) {
                int kk = br + p * 8;
                bR[p] = *(const float4*)(Bm + (long long)kk * ldb + bx * Bn + bc);
            }
        }
    }
    int buf = 0;
    #pragma unroll
    for (int p = 0; p < 2; p++) {
        As[buf][ac + 0][ar + p * 64] = aR[p].x;
        As[buf][ac + 1][ar + p * 64] = aR[p].y;
        As[buf][ac + 2][ar + p * 64] = aR[p].z;
        As[buf][ac + 3][ar + p * 64] = aR[p].w;
    }
    if (TRANSB) {
        #pragma unroll
        for (int p = 0; p < 2; p++) {
            Bs[buf][ac + 0][ar + p * 64] = bR[p].x;
            Bs[buf][ac + 1][ar + p * 64] = bR[p].y;
            Bs[buf][ac + 2][ar + p * 64] = bR[p].z;
            Bs[buf][ac + 3][ar + p * 64] = bR[p].w;
        }
    } else {
        #pragma unroll
        for (int p = 0; p < 2; p++)
            *(float4*)&Bs[buf][br + p * 8][bc] = bR[p];
    }
    __syncthreads();

    for (int kt = 0; kt < nk; kt++) {
        const bool more = (kt + 1 < nk);
        if (more) {
            const int k0 = (kt + 1) * Bk;
            #pragma unroll
            for (int p = 0; p < 2; p++) {
                int m = by * Bb + ar + p * 64;
                aR[p] = (m < M) ? *(const float4*)(A + (long long)m * lda + k0 + ac)
                                : make_float4(0.f, 0.f, 0.f, 0.f);
            }
            if (TRANSB) {
                #pragma unroll
                for (int p = 0; p < 2; p++) {
                    int n = bx * Bn + ar + p * 64;
                    bR[p] = *(const float4*)(Bm + (long long)n * ldb + k0 + ac);
                }
            } else {
                #pragma unroll
                for (int p = 0; p < 2; p++) {
                    int kk = br + p * 8;
                    bR[p] = *(const float4*)(Bm + (long long)(k0 + kk) * ldb + bx * Bn + bc);
                }
            }
        }
        #pragma unroll
        for (int k = 0; k < Bk; k++) {
            float a[8], bv2[8];
            *(float4*)&a[0]   = *(const float4*)&As[buf][k][mb];
            *(float4*)&a[4]   = *(const float4*)&As[buf][k][mb + 4];
            *(float4*)&bv2[0] = *(const float4*)&Bs[buf][k][nb];
            *(float4*)&bv2[4] = *(const float4*)&Bs[buf][k][nb + 4];
            #pragma unroll
            for (int i = 0; i < 8; i++)
                #pragma unroll
                for (int j = 0; j < 8; j++)
                    acc[i][j] += a[i] * bv2[j];
        }
        if (more) {
            buf ^= 1;
            #pragma unroll
            for (int p = 0; p < 2; p++) {
                As[buf][ac + 0][ar + p * 64] = aR[p].x;
                As[buf][ac + 1][ar + p * 64] = aR[p].y;
                As[buf][ac + 2][ar + p * 64] = aR[p].z;
                As[buf][ac + 3][ar + p * 64] = aR[p].w;
            }
            if (TRANSB) {
                #pragma unroll
                for (int p = 0; p < 2; p++) {
                    Bs[buf][ac + 0][ar + p * 64] = bR[p].x;
                    Bs[buf][ac + 1][ar + p * 64] = bR[p].y;
                    Bs[buf][ac + 2][ar + p * 64] = bR[p].z;
                    Bs[buf][ac + 3][ar + p * 64] = bR[p].w;
                }
            } else {
                #pragma unroll
                for (int p = 0; p < 2; p++)
                    *(float4*)&Bs[buf][br + p * 8][bc] = bR[p];
            }
            __syncthreads();
        }
    }

    float bvv[8];
    if (BIAS) {
        #pragma unroll
        for (int j = 0; j < 8; j++) bvv[j] = bias[bx * Bn + nb + j];
    }
    #pragma unroll
    for (int i = 0; i < 8; i++) {
        int m = by * Bb + mb + i;
        if (m < M) {
            long long base = (long long)m * ldc + bx * Bn + nb;
            const float* Rp = RESID ? (Rm + (long long)m * ldr + bx * Bn + nb) : (const float*)0;
            #pragma unroll
            for (int j = 0; j < 8; j += 4) {
                float4 v;
                v.x = acc[i][j + 0]; v.y = acc[i][j + 1];
                v.z = acc[i][j + 2]; v.w = acc[i][j + 3];
                if (BIAS) { v.x += bvv[j]; v.y += bvv[j + 1]; v.z += bvv[j + 2]; v.w += bvv[j + 3]; }
                if (RESID) {
                    float4 rv = *(const float4*)(Rp + j);
                    v.x += rv.x; v.y += rv.y; v.z += rv.z; v.w += rv.w;
                }
                *(float4*)(C + base + j) = v;
                if (HALFOUT) {
                    __half h0, l0h, h1, l1h, h2, l2h, h3, l3h;
                    split2(v.x, h0, l0h); split2(v.y, h1, l1h);
                    split2(v.z, h2, l2h); split2(v.w, h3, l3h);
                    *(__half2*)(Chi + base + j)     = __halves2half2(h0, h1);
                    *(__half2*)(Chi + base + j + 2) = __halves2half2(h2, h3);
                    *(__half2*)(Clo + base + j)     = __halves2half2(l0h, l1h);
                    *(__half2*)(Clo + base + j + 2) = __halves2half2(l2h, l3h);
                }
            }
        }
    }
}

// -------------------- copy text features into concat buffer (+hi/lo) --------
__global__ void copy_text(const float4* __restrict__ src, float4* __restrict__ dst,
                          __half* __restrict__ atth, __half* __restrict__ attl)
{
    int idx = blockIdx.x * 256 + threadIdx.x;
    int b = idx >> 18;
    int r = idx & 262143;
    float4 v = src[idx];
    long long d4 = (long long)b * 524288 + 262144 + r;
    dst[d4] = v;
    __half hx, lx, hy, ly, hz, lz, hw, lw;
    split2(v.x, hx, lx); split2(v.y, hy, ly);
    split2(v.z, hz, lz); split2(v.w, hw, lw);
    long long he = d4 * 4;
    *(__half2*)(atth + he)     = __halves2half2(hx, hy);
    *(__half2*)(atth + he + 2) = __halves2half2(hz, hw);
    *(__half2*)(attl + he)     = __halves2half2(lx, ly);
    *(__half2*)(attl + he + 2) = __halves2half2(lz, lw);
}

// -------------------- v2t attention (<=13 keys/row) + residual (+hi/lo) -----
__global__ __launch_bounds__(128) void v2t_attn(
    const float* __restrict__ qvis, const float* __restrict__ ktext,
    const float* __restrict__ vtext, const float* __restrict__ visf,
    float* __restrict__ att, __half* __restrict__ atth, __half* __restrict__ attl)
{
    const int i = blockIdx.x, b = blockIdx.y;
    const int tid = threadIdx.x, lane = tid & 31, warp = tid >> 5;
    const int s0 = (i < 1016) ? i : 1016;
    const int nk = (i < 5) ? (i + 8) : 13;

    const float* q = qvis + ((long long)b * SS + i) * HH;
    float qr[8];
    #pragma unroll
    for (int r = 0; r < 8; r++) qr[r] = q[r * 128 + tid];

    const float* kb = ktext + (long long)b * SS * HH;
    float p[13];
    #pragma unroll
    for (int j = 0; j < 13; j++) {
        float s = 0.f;
        if (j < nk) {
            int kj = (i < 5) ? j : ((j < 5) ? j : (s0 + j - 5));
            const float* kp = kb + (long long)kj * HH + tid;
            #pragma unroll
            for (int r = 0; r < 8; r++) s += qr[r] * kp[r * 128];
        }
        p[j] = s;
    }
    #pragma unroll
    for (int j = 0; j < 13; j++) {
        #pragma unroll
        for (int off = 16; off; off >>= 1) p[j] += __shfl_xor_sync(0xffffffffu, p[j], off);
    }
    __shared__ float red[4][13];
    if (lane == 0) {
        #pragma unroll
        for (int j = 0; j < 13; j++) red[warp][j] = p[j];
    }
    __syncthreads();

    float sc[13];
    float mx = -3.4e38f;
    #pragma unroll
    for (int j = 0; j < 13; j++) {
        sc[j] = red[0][j] + red[1][j] + red[2][j] + red[3][j];
        if (j < nk) mx = fmaxf(mx, sc[j]);
    }
    float sum = 0.f;
    #pragma unroll
    for (int j = 0; j < 13; j++) {
        float e = (j < nk) ? expf(sc[j] - mx) : 0.f;
        sc[j] = e; sum += e;
    }
    const float inv = 1.f / sum;

    const float* vf = visf + ((long long)b * SS + i) * HH;
    const float* vb = vtext + (long long)b * SS * HH;
    long long ob = ((long long)b * LL + i) * HH;
    #pragma unroll
    for (int r = 0; r < 8; r++) {
        int h = r * 128 + tid;
        float a2 = vf[h];
        #pragma unroll
        for (int j = 0; j < 13; j++) {
            if (j < nk) {
                int kj = (i < 5) ? j : ((j < 5) ? j : (s0 + j - 5));
                a2 += sc[j] * inv * vb[(long long)kj * HH + h];
            }
        }
        att[ob + h] = a2;
        __half hh, lh;
        split2(a2, hh, lh);
        atth[ob + h] = hh;
        attl[ob + h] = lh;
    }
}

// -------------------- t2v rows 0..4 (final-write + hi/lo) -------------------
__global__ __launch_bounds__(256) void t2v_full_rows(
    const float* __restrict__ qtext, const float* __restrict__ kvis,
    const float* __restrict__ vvis, const float* __restrict__ txt,
    float* __restrict__ att, __half* __restrict__ atth, __half* __restrict__ attl)
{
    const int r = blockIdx.x, b = blockIdx.y;
    const int tid = threadIdx.x, lane = tid & 31, warp = tid >> 5;
    __shared__ float qs[1024];
    __shared__ float sc[1024];
    __shared__ float red[8];

    const float* q = qtext + ((long long)b * SS + r) * HH;
    for (int h = tid; h < 1024; h += 256) qs[h] = q[h];
    __syncthreads();

    const float* kb = kvis + (long long)b * SS * HH;
    for (int t = warp * 128; t < warp * 128 + 128; t++) {
        const float* kp = kb + (long long)t * HH;
        float p = 0.f;
        #pragma unroll
        for (int c = 0; c < 32; c++) p += qs[c * 32 + lane] * kp[c * 32 + lane];
        #pragma unroll
        for (int off = 16; off; off >>= 1) p += __shfl_xor_sync(0xffffffffu, p, off);
        if (lane == 0) sc[t] = p;
    }
    __syncthreads();

    float m = -3.4e38f;
    for (int t = tid; t < 1024; t += 256) m = fmaxf(m, sc[t]);
    #pragma unroll
    for (int off = 16; off; off >>= 1) m = fmaxf(m, __shfl_xor_sync(0xffffffffu, m, off));
    if (lane == 0) red[warp] = m;
    __syncthreads();
    float mx = red[0];
    #pragma unroll
    for (int k = 1; k < 8; k++) mx = fmaxf(mx, red[k]);

    float s = 0.f;
    for (int t = tid; t < 1024; t += 256) { float e = expf(sc[t] - mx); sc[t] = e; s += e; }
    #pragma unroll
    for (int off = 16; off; off >>= 1) s += __shfl_xor_sync(0xffffffffu, s, off);
    __syncthreads();
    if (lane == 0) red[warp] = s;
    __syncthreads();
    float tot = 0.f;
    #pragma unroll
    for (int k = 0; k < 8; k++) tot += red[k];
    const float inv = 1.f / tot;

    const float* vb = vvis + (long long)b * SS * HH;
    const float* tx = txt + ((long long)b * SS + r) * HH;
    long long ob = ((long long)b * LL + 1024 + r) * HH;
    float accv[4] = {0.f, 0.f, 0.f, 0.f};
    for (int t = 0; t < 1024; t++) {
        float pw = sc[t];
        const float* vr = vb + (long long)t * HH + tid;
        accv[0] += pw * vr[0];
        accv[1] += pw * vr[256];
        accv[2] += pw * vr[512];
        accv[3] += pw * vr[768];
    }
    #pragma unroll
    for (int k = 0; k < 4; k++) {
        int h = tid + k * 256;
        float v = tx[h] + accv[k] * inv;
        att[ob + h] = v;
        __half hh, lh;
        split2(v, hh, lh);
        atth[ob + h] = hh;
        attl[ob + h] = lh;
    }
}

// -------------------- softmax over 512-col rows (t2v mid block) -------------
__global__ __launch_bounds__(256) void softmax512(float* __restrict__ S)
{
    float* row = S + (long long)blockIdx.x * 512;
    const int tid = threadIdx.x, lane = tid & 31, warp = tid >> 5;
    __shared__ float red[8];
    float a = row[tid], b2 = row[tid + 256];
    float m = fmaxf(a, b2);
    #pragma unroll
    for (int off = 16; off; off >>= 1) m = fmaxf(m, __shfl_xor_sync(0xffffffffu, m, off));
    if (lane == 0) red[warp] = m;
    __syncthreads();
    float mx = red[0];
    #pragma unroll
    for (int k = 1; k < 8; k++) mx = fmaxf(mx, red[k]);
    float e0 = expf(a - mx), e1 = expf(b2 - mx);
    float s = e0 + e1;
    #pragma unroll
    for (int off = 16; off; off >>= 1) s += __shfl_xor_sync(0xffffffffu, s, off);
    __syncthreads();
    if (lane == 0) red[warp] = s;
    __syncthreads();
    float tot = 0.f;
    #pragma unroll
    for (int k = 0; k < 8; k++) tot += red[k];
    float inv = 1.f / tot;
    row[tid] = e0 * inv;
    row[tid + 256] = e1 * inv;
}

// -------------------- launcher ----------------------------------------------
extern "C" void kernel_launch(void* const* d_in, const int* in_sizes, int n_in,
                              void* d_out, int out_size)
{
    (void)in_sizes; (void)n_in; (void)out_size;
    const float* vis = (const float*)d_in[0];
    const float* txt = (const float*)d_in[1];
    const float* Wq  = (const float*)d_in[2];  const float* bq  = (const float*)d_in[3];
    const float* Wk  = (const float*)d_in[4];  const float* bk  = (const float*)d_in[5];
    const float* Wv  = (const float*)d_in[6];  const float* bv  = (const float*)d_in[7];
    const float* Wc1 = (const float*)d_in[8];  const float* bc1 = (const float*)d_in[9];
    const float* Wc2 = (const float*)d_in[10]; const float* bc2 = (const float*)d_in[11];
    float* out = (float*)d_out;

    float *qt, *kv, *vv, *qv, *kt, *vt, *attb, *scb;
    __half *vish, *visl, *txth, *txtl, *c1h, *c1l, *wh, *wl;
    __half *qth, *qtl, *kvh, *kvl, *atth, *attl, *wc1h, *wc1l;
    cudaGetSymbolAddress((void**)&qt,  g_q_text);
    cudaGetSymbolAddress((void**)&kv,  g_k_vis);
    cudaGetSymbolAddress((void**)&vv,  g_v_vis);
    cudaGetSymbolAddress((void**)&qv,  g_q_vis);
    cudaGetSymbolAddress((void**)&kt,  g_k_text);
    cudaGetSymbolAddress((void**)&vt,  g_v_text);
    cudaGetSymbolAddress((void**)&attb, g_att);
    cudaGetSymbolAddress((void**)&scb, g_scores);
    cudaGetSymbolAddress((void**)&vish, g_vis_hi);
    cudaGetSymbolAddress((void**)&visl, g_vis_lo);
    cudaGetSymbolAddress((void**)&txth, g_txt_hi);
    cudaGetSymbolAddress((void**)&txtl, g_txt_lo);
    cudaGetSymbolAddress((void**)&c1h, g_c1_hi);
    cudaGetSymbolAddress((void**)&c1l, g_c1_lo);
    cudaGetSymbolAddress((void**)&wh,  g_w_hi);
    cudaGetSymbolAddress((void**)&wl,  g_w_lo);
    cudaGetSymbolAddress((void**)&qth, g_qt_hi);
    cudaGetSymbolAddress((void**)&qtl, g_qt_lo);
    cudaGetSymbolAddress((void**)&kvh, g_kv_hi);
    cudaGetSymbolAddress((void**)&kvl, g_kv_lo);
    cudaGetSymbolAddress((void**)&atth, g_att_hi);
    cudaGetSymbolAddress((void**)&attl, g_att_lo);
    cudaGetSymbolAddress((void**)&wc1h, g_wc1r_hi);
    cudaGetSymbolAddress((void**)&wc1l, g_wc1r_lo);

    cudaFuncSetAttribute((const void*)&mma_gemm<true,  true,  false>,
                         cudaFuncAttributeMaxDynamicSharedMemorySize, MG_SMEM);
    cudaFuncSetAttribute((const void*)&mma_gemm<true,  false, false>,
                         cudaFuncAttributeMaxDynamicSharedMemorySize, MG_SMEM);
    cudaFuncSetAttribute((const void*)&mma_gemm<false, false, true>,
                         cudaFuncAttributeMaxDynamicSharedMemorySize, MG_SMEM);
    cudaFuncSetAttribute((const void*)&conv1_mma,
                         cudaFuncAttributeMaxDynamicSharedMemorySize, CV_SMEM);

    const long long SH = (long long)SS * HH;
    const long long LH = (long long)LL * HH;
    const long long SCs = (long long)MID_M * MID_N;

    // 0) split inputs & weights into fp16 hi/lo; reorder conv1 weights
    int n4in = BB * SS * HH / 4;
    split_fp16<<<(n4in + 255) / 256, 256>>>((const float4*)vis, (uint2*)vish, (uint2*)visl, n4in);
    split_fp16<<<(n4in + 255) / 256, 256>>>((const float4*)txt, (uint2*)txth, (uint2*)txtl, n4in);
    int n4w = WW / 4;
    split_fp16<<<(n4w + 255) / 256, 256>>>((const float4*)Wq,  (uint2*)(wh + 0 * WW), (uint2*)(wl + 0 * WW), n4w);
    split_fp16<<<(n4w + 255) / 256, 256>>>((const float4*)Wk,  (uint2*)(wh + 1 * WW), (uint2*)(wl + 1 * WW), n4w);
    split_fp16<<<(n4w + 255) / 256, 256>>>((const float4*)Wv,  (uint2*)(wh + 2 * WW), (uint2*)(wl + 2 * WW), n4w);
    split_fp16<<<(n4w + 255) / 256, 256>>>((const float4*)Wc2, (uint2*)(wh + 3 * WW), (uint2*)(wl + 3 * WW), n4w);
    wc1_transform<<<(HH * 384 + 255) / 256, 256>>>(Wc1, wc1h, wc1l);

    // 1) projections on tensor cores; qt & kv also emit hi/lo for mid scores
    dim3 gp(HH / 128, BB * SS / 128, 1);
    mma_gemm<true, true,  false><<<gp, 256, MG_SMEM>>>(txth, txtl, 0, wh + 0*WW, wl + 0*WW, 0,
        qt, 0, HH, bq, qth, qtl, BB*SS, HH);
    mma_gemm<true, true,  false><<<gp, 256, MG_SMEM>>>(vish, visl, 0, wh + 1*WW, wl + 1*WW, 0,
        kv, 0, HH, bk, kvh, kvl, BB*SS, HH);
    mma_gemm<true, false, false><<<gp, 256, MG_SMEM>>>(vish, visl, 0, wh + 2*WW, wl + 2*WW, 0,
        vv, 0, HH, bv, nullptr, nullptr, BB*SS, HH);
    mma_gemm<true, false, false><<<gp, 256, MG_SMEM>>>(vish, visl, 0, wh + 0*WW, wl + 0*WW, 0,
        qv, 0, HH, bq, nullptr, nullptr, BB*SS, HH);
    mma_gemm<true, false, false><<<gp, 256, MG_SMEM>>>(txth, txtl, 0, wh + 1*WW, wl + 1*WW, 0,
        kt, 0, HH, bk, nullptr, nullptr, BB*SS, HH);
    mma_gemm<true, false, false><<<gp, 256, MG_SMEM>>>(txth, txtl, 0, wh + 2*WW, wl + 2*WW, 0,
        vt, 0, HH, bv, nullptr, nullptr, BB*SS, HH);

    // 2) text residual rows -> att (fp32 + hi/lo)
    copy_text<<<8192, 256>>>((const float4*)txt, (float4*)attb, atth, attl);

    // 3) v2t sparse attention (+hi/lo)
    v2t_attn<<<dim3(SS, BB), 128>>>(qv, kt, vt, vis, attb, atth, attl);

    // 4) t2v rows 0..4: final write txt + attn (+hi/lo)
    t2v_full_rows<<<dim3(5, BB), 256>>>(qt, kv, vv, txt, attb, atth, attl);

    // 5) t2v mid scores on tensor cores: [341,512] = q[341:682] @ k[256:768]^T
    mma_gemm<false, false, true><<<dim3(MID_N / 128, 3, BB), 256, MG_SMEM>>>(
        qth + 341 * HH, qtl + 341 * HH, SH,
        kvh + 256 * HH, kvl + 256 * HH, SH,
        scb, SCs, MID_N, nullptr, nullptr, nullptr, MID_M, HH);

    // 6) row softmax
    softmax512<<<BB * MID_M, 256>>>(scb);

    // 7) AV + text residual (fp32 SIMT, K=512) -> att rows 1365..1705 (+hi/lo)
    sgemm_k<false, false, true, true><<<dim3(HH / 128, 3, BB), 256>>>(
        scb, MID_N, SCs, vv + 256 * HH, HH, SH,
        attb + (long long)(1024 + 341) * HH, HH, LH,
        nullptr, txt + 341 * HH, HH, SH,
        atth + (long long)(1024 + 341) * HH, attl + (long long)(1024 + 341) * HH,
        MID_M, HH, MID_N);

    // 8) conv1 (grouped, k=3) + GELU on tensor cores -> c1 hi/lo
    conv1_mma<<<dim3(LL / 128, 8, BB), 256, CV_SMEM>>>(atth, attl, wc1h, wc1l, bc1, c1h, c1l);

    // 9) pointwise conv2 on tensor cores -> output
    mma_gemm<true, false, false><<<dim3(HH / 128, BB * LL / 128, 1), 256, MG_SMEM>>>(
        c1h, c1l, 0, wh + 3 * WW, wl + 3 * WW, 0,
        out, 0, HH, bc2, nullptr, nullptr, BB * LL, HH);
}

// round 6
// speedup vs baseline: 2.7556x; 1.0499x over previous
#include <cuda_runtime.h>
#include <cuda_fp16.h>
#include <math.h>
#include <stdint.h>

// Problem constants (B=8, V=T=1024, H=1024, L=V+T=2048)
#define BB 8
#define SS 1024
#define HH 1024
#define LL 2048
#define MID_M 341   // t2v active mid rows: 341..681
#define MID_N 512   // keys 256..767
#define WW (HH*HH)

// -------------------- scratch (device globals; no runtime alloc) ------------
__device__ __align__(128) float g_q_text[BB*SS*HH];
__device__ __align__(128) float g_k_vis [BB*SS*HH];
__device__ __align__(128) float g_v_vis [BB*SS*HH];
__device__ __align__(128) float g_q_vis [BB*SS*HH];
__device__ __align__(128) float g_k_text[BB*SS*HH];
__device__ __align__(128) float g_v_text[BB*SS*HH];
__device__ __align__(128) float g_att   [BB*LL*HH];   // fp32 dump for AV epilogue
__device__ __align__(128) float g_scores[BB*MID_M*MID_N];
// split-fp16 operand buffers
__device__ __align__(128) __half g_vis_hi[BB*SS*HH];
__device__ __align__(128) __half g_vis_lo[BB*SS*HH];
__device__ __align__(128) __half g_txt_hi[BB*SS*HH];
__device__ __align__(128) __half g_txt_lo[BB*SS*HH];
__device__ __align__(128) __half g_c1_hi [BB*LL*HH];
__device__ __align__(128) __half g_c1_lo [BB*LL*HH];
__device__ __align__(128) __half g_w_hi  [4*WW];      // Wq, Wk, Wv (stacked), Wc2
__device__ __align__(128) __half g_w_lo  [4*WW];
__device__ __align__(128) __half g_qt_hi [BB*SS*HH];
__device__ __align__(128) __half g_qt_lo [BB*SS*HH];
__device__ __align__(128) __half g_kv_hi [BB*SS*HH];
__device__ __align__(128) __half g_kv_lo [BB*SS*HH];
__device__ __align__(128) __half g_att_hi[BB*LL*HH];
__device__ __align__(128) __half g_att_lo[BB*LL*HH];
__device__ __align__(128) __half g_wc1r_hi[HH*384];   // conv1 weights [oc, tap*128+ic]
__device__ __align__(128) __half g_wc1r_lo[HH*384];
__device__ __align__(128) __half g_sc_hi [BB*MID_M*MID_N];
__device__ __align__(128) __half g_sc_lo [BB*MID_M*MID_N];
__device__ __align__(128) __half g_vvT_hi[BB*HH*MID_N];  // V slice transposed [b, h, t]
__device__ __align__(128) __half g_vvT_lo[BB*HH*MID_N];

// ===================== low-level helpers ====================================
__device__ __forceinline__ uint32_t smem_to_u32(const void* p) {
    uint32_t a;
    asm("{ .reg .u64 t; cvta.to.shared.u64 t, %1; cvt.u32.u64 %0, t; }" : "=r"(a) : "l"(p));
    return a;
}
__device__ __forceinline__ void cp_async16(uint32_t saddr, const void* gptr) {
    asm volatile("cp.async.cg.shared.global [%0], [%1], 16;" :: "r"(saddr), "l"(gptr));
}
#define CP_COMMIT() asm volatile("cp.async.commit_group;" ::: "memory")
#define CP_WAIT1()  asm volatile("cp.async.wait_group 1;" ::: "memory")
#define CP_WAIT0()  asm volatile("cp.async.wait_group 0;" ::: "memory")

__device__ __forceinline__ void ldm_x4(uint32_t& r0, uint32_t& r1, uint32_t& r2, uint32_t& r3,
                                       uint32_t addr) {
    asm volatile("ldmatrix.sync.aligned.m8n8.x4.shared.b16 {%0,%1,%2,%3}, [%4];"
                 : "=r"(r0), "=r"(r1), "=r"(r2), "=r"(r3) : "r"(addr));
}
__device__ __forceinline__ void ldm_x2(uint32_t& r0, uint32_t& r1, uint32_t addr) {
    asm volatile("ldmatrix.sync.aligned.m8n8.x2.shared.b16 {%0,%1}, [%2];"
                 : "=r"(r0), "=r"(r1) : "r"(addr));
}
__device__ __forceinline__ void mma16816(float* c, const uint32_t* a, const uint32_t* b) {
    asm volatile("mma.sync.aligned.m16n8k16.row.col.f32.f16.f16.f32 "
                 "{%0,%1,%2,%3}, {%4,%5,%6,%7}, {%8,%9}, {%0,%1,%2,%3};"
                 : "+f"(c[0]), "+f"(c[1]), "+f"(c[2]), "+f"(c[3])
                 : "r"(a[0]), "r"(a[1]), "r"(a[2]), "r"(a[3]), "r"(b[0]), "r"(b[1]));
}
__device__ __forceinline__ void split2(float v, __half& h, __half& l) {
    h = __float2half_rn(v);
    l = __float2half_rn(v - __half2float(h));
}

#define MG_SMEM (3 * 65536)

// ============ shared GEMM core pieces (macros avoid code dup) ===============
// (tile geometry identical across GEMM kernels: 128x128 CTA tile, 8 warps of
//  64x32, 64-wide K chunks, 3-term split-fp16)

// =================== generic tensor-core GEMM ===============================
// C[M,N] = A[M,K] @ B[N,K]^T (+bias) (+residual), fp32 out (+hi/lo).
template<bool BIAS, bool HALFOUT, bool GUARD, bool RESID>
__global__ __launch_bounds__(256, 1)
void mma_gemm(const __half* __restrict__ Ahi, const __half* __restrict__ Alo, long long sA,
              const __half* __restrict__ Bhi, const __half* __restrict__ Blo, long long sB,
              float* __restrict__ C, long long sC, int ldc,
              const float* __restrict__ bias,
              __half* __restrict__ Chi, __half* __restrict__ Clo,
              const float* __restrict__ Rm, long long sR, int ldr,
              int M, int K)
{
    extern __shared__ char smem[];
    const uint32_t sbase = smem_to_u32(smem);
    const int tid = threadIdx.x;
    const int wid = tid >> 5, lane = tid & 31;
    const int m0 = blockIdx.y * 128, n0 = blockIdx.x * 128;
    const int m_w = (wid & 1) * 64;
    const int n_w = (wid >> 1) * 32;
    const int z = blockIdx.z;
    Ahi += z * sA; Alo += z * sA;
    Bhi += z * sB; Blo += z * sB;
    C   += z * sC;
    if (HALFOUT) { Chi += z * sC; Clo += z * sC; }
    if (RESID)   { Rm  += z * sR; }

    const int crow = tid >> 3;
    const int cc16 = tid & 7;
    const int nk = K >> 6;

    auto issue_stage = [&](int kc, int s) {
        const int k0 = kc * 64;
        const uint32_t st = sbase + (uint32_t)s * 65536u;
        #pragma unroll
        for (int p = 0; p < 4; p++) {
            int row = p * 32 + crow;
            uint32_t soff = (uint32_t)(row * 128) + (uint32_t)((cc16 * 16) ^ ((row & 7) << 4));
            int gm = m0 + row;
            if (GUARD) gm = (gm < M) ? gm : (M - 1);
            long long ga = (long long)gm * K + k0 + cc16 * 8;
            long long gb = (long long)(n0 + row) * K + k0 + cc16 * 8;
            cp_async16(st + soff,          Ahi + ga);
            cp_async16(st + 16384 + soff,  Alo + ga);
            cp_async16(st + 32768 + soff,  Bhi + gb);
            cp_async16(st + 49152 + soff,  Blo + gb);
        }
    };

    uint32_t aRow[4], aXor[4];
    #pragma unroll
    for (int mt = 0; mt < 4; mt++) {
        int r = m_w + 16 * mt + (lane & 15);
        aRow[mt] = (uint32_t)(r * 128);
        aXor[mt] = (uint32_t)((r & 7) << 4);
    }
    const uint32_t aCol = (uint32_t)((lane >> 4) * 16);
    uint32_t bRow[4], bXor[4];
    #pragma unroll
    for (int nt = 0; nt < 4; nt++) {
        int r = n_w + 8 * nt + (lane & 7);
        bRow[nt] = (uint32_t)(r * 128);
        bXor[nt] = (uint32_t)((r & 7) << 4);
    }
    const uint32_t bCol = (uint32_t)(((lane >> 3) & 1) * 16);

    float acc[4][4][4];
    #pragma unroll
    for (int mt = 0; mt < 4; mt++)
        #pragma unroll
        for (int nt = 0; nt < 4; nt++)
            #pragma unroll
            for (int q = 0; q < 4; q++) acc[mt][nt][q] = 0.f;

    auto compute = [&](int s) {
        const uint32_t st = sbase + (uint32_t)s * 65536u;
        #pragma unroll
        for (int ks = 0; ks < 4; ks++) {
            const uint32_t kb = (uint32_t)(ks * 32);
            uint32_t ah[4][4], al[4][4], bh[4][2], bl[4][2];
            #pragma unroll
            for (int mt = 0; mt < 4; mt++) {
                uint32_t ad = st + aRow[mt] + ((kb + aCol) ^ aXor[mt]);
                ldm_x4(ah[mt][0], ah[mt][1], ah[mt][2], ah[mt][3], ad);
                ldm_x4(al[mt][0], al[mt][1], al[mt][2], al[mt][3], ad + 16384);
            }
            #pragma unroll
            for (int nt = 0; nt < 4; nt++) {
                uint32_t bd = st + 32768 + bRow[nt] + ((kb + bCol) ^ bXor[nt]);
                ldm_x2(bh[nt][0], bh[nt][1], bd);
                ldm_x2(bl[nt][0], bl[nt][1], bd + 16384);
            }
            #pragma unroll
            for (int mt = 0; mt < 4; mt++)
                #pragma unroll
                for (int nt = 0; nt < 4; nt++) {
                    mma16816(acc[mt][nt], ah[mt], bh[nt]);
                    mma16816(acc[mt][nt], ah[mt], bl[nt]);
                    mma16816(acc[mt][nt], al[mt], bh[nt]);
                }
        }
    };

    issue_stage(0, 0); CP_COMMIT();
    issue_stage(1, 1); CP_COMMIT();
    for (int kc = 0; kc < nk; kc++) {
        if (kc + 1 < nk) { CP_WAIT1(); } else { CP_WAIT0(); }
        __syncthreads();
        if (kc + 2 < nk) { issue_stage(kc + 2, (kc + 2) % 3); CP_COMMIT(); }
        compute(kc % 3);
    }

    const int rq = lane >> 2, cq = (lane & 3) * 2;
    #pragma unroll
    for (int mt = 0; mt < 4; mt++) {
        int row0 = m0 + m_w + 16 * mt + rq;
        #pragma unroll
        for (int nt = 0; nt < 4; nt++) {
            int col = n0 + n_w + 8 * nt + cq;
            float b0 = 0.f, b1 = 0.f;
            if (BIAS) { b0 = bias[col]; b1 = bias[col + 1]; }
            #pragma unroll
            for (int rr = 0; rr < 2; rr++) {
                int row = row0 + rr * 8;
                if (GUARD && row >= M) continue;
                float x0 = acc[mt][nt][rr * 2 + 0] + b0;
                float x1 = acc[mt][nt][rr * 2 + 1] + b1;
                if (RESID) {
                    const float* Rp = Rm + (long long)row * ldr + col;
                    x0 += Rp[0]; x1 += Rp[1];
                }
                long long idx = (long long)row * ldc + col;
                *(float2*)(C + idx) = make_float2(x0, x1);
                if (HALFOUT) {
                    __half h0, l0h, h1, l1h;
                    split2(x0, h0, l0h); split2(x1, h1, l1h);
                    *(__half2*)(Chi + idx) = __halves2half2(h0, h1);
                    *(__half2*)(Clo + idx) = __halves2half2(l0h, l1h);
                }
            }
        }
    }
}

// ============ fused QKV projection: N=3072 stacked weights ==================
// grid = (24, 64). Segment seg = n-tile/1024 routes to C0/C1/C2 (+hi/lo when
// seg == hseg). All outputs ldc = 1024.
__global__ __launch_bounds__(256, 1)
void mma_qkv(const __half* __restrict__ Ahi, const __half* __restrict__ Alo,
             const __half* __restrict__ Bhi, const __half* __restrict__ Blo,
             const float* __restrict__ b0p, const float* __restrict__ b1p,
             const float* __restrict__ b2p,
             float* __restrict__ C0, float* __restrict__ C1, float* __restrict__ C2,
             __half* __restrict__ Chi, __half* __restrict__ Clo, int hseg)
{
    extern __shared__ char smem[];
    const uint32_t sbase = smem_to_u32(smem);
    const int tid = threadIdx.x;
    const int wid = tid >> 5, lane = tid & 31;
    const int m0 = blockIdx.y * 128, n0 = blockIdx.x * 128;
    const int m_w = (wid & 1) * 64;
    const int n_w = (wid >> 1) * 32;
    const int seg = n0 >> 10;
    const int ncol0 = n0 & 1023;
    float* C = (seg == 0) ? C0 : (seg == 1) ? C1 : C2;
    const float* bias = (seg == 0) ? b0p : (seg == 1) ? b1p : b2p;
    const bool doHalf = (seg == hseg);

    const int crow = tid >> 3;
    const int cc16 = tid & 7;

    auto issue_stage = [&](int kc, int s) {
        const int k0 = kc * 64;
        const uint32_t st = sbase + (uint32_t)s * 65536u;
        #pragma unroll
        for (int p = 0; p < 4; p++) {
            int row = p * 32 + crow;
            uint32_t soff = (uint32_t)(row * 128) + (uint32_t)((cc16 * 16) ^ ((row & 7) << 4));
            long long ga = (long long)(m0 + row) * 1024 + k0 + cc16 * 8;
            long long gb = (long long)(n0 + row) * 1024 + k0 + cc16 * 8;
            cp_async16(st + soff,          Ahi + ga);
            cp_async16(st + 16384 + soff,  Alo + ga);
            cp_async16(st + 32768 + soff,  Bhi + gb);
            cp_async16(st + 49152 + soff,  Blo + gb);
        }
    };

    uint32_t aRow[4], aXor[4];
    #pragma unroll
    for (int mt = 0; mt < 4; mt++) {
        int r = m_w + 16 * mt + (lane & 15);
        aRow[mt] = (uint32_t)(r * 128);
        aXor[mt] = (uint32_t)((r & 7) << 4);
    }
    const uint32_t aCol = (uint32_t)((lane >> 4) * 16);
    uint32_t bRow[4], bXor[4];
    #pragma unroll
    for (int nt = 0; nt < 4; nt++) {
        int r = n_w + 8 * nt + (lane & 7);
        bRow[nt] = (uint32_t)(r * 128);
        bXor[nt] = (uint32_t)((r & 7) << 4);
    }
    const uint32_t bCol = (uint32_t)(((lane >> 3) & 1) * 16);

    float acc[4][4][4];
    #pragma unroll
    for (int mt = 0; mt < 4; mt++)
        #pragma unroll
        for (int nt = 0; nt < 4; nt++)
            #pragma unroll
            for (int q = 0; q < 4; q++) acc[mt][nt][q] = 0.f;

    auto compute = [&](int s) {
        const uint32_t st = sbase + (uint32_t)s * 65536u;
        #pragma unroll
        for (int ks = 0; ks < 4; ks++) {
            const uint32_t kb = (uint32_t)(ks * 32);
            uint32_t ah[4][4], al[4][4], bh[4][2], bl[4][2];
            #pragma unroll
            for (int mt = 0; mt < 4; mt++) {
                uint32_t ad = st + aRow[mt] + ((kb + aCol) ^ aXor[mt]);
                ldm_x4(ah[mt][0], ah[mt][1], ah[mt][2], ah[mt][3], ad);
                ldm_x4(al[mt][0], al[mt][1], al[mt][2], al[mt][3], ad + 16384);
            }
            #pragma unroll
            for (int nt = 0; nt < 4; nt++) {
                uint32_t bd = st + 32768 + bRow[nt] + ((kb + bCol) ^ bXor[nt]);
                ldm_x2(bh[nt][0], bh[nt][1], bd);
                ldm_x2(bl[nt][0], bl[nt][1], bd + 16384);
            }
            #pragma unroll
            for (int mt = 0; mt < 4; mt++)
                #pragma unroll
                for (int nt = 0; nt < 4; nt++) {
                    mma16816(acc[mt][nt], ah[mt], bh[nt]);
                    mma16816(acc[mt][nt], ah[mt], bl[nt]);
                    mma16816(acc[mt][nt], al[mt], bh[nt]);
                }
        }
    };

    issue_stage(0, 0); CP_COMMIT();
    issue_stage(1, 1); CP_COMMIT();
    for (int kc = 0; kc < 16; kc++) {
        if (kc + 1 < 16) { CP_WAIT1(); } else { CP_WAIT0(); }
        __syncthreads();
        if (kc + 2 < 16) { issue_stage(kc + 2, (kc + 2) % 3); CP_COMMIT(); }
        compute(kc % 3);
    }

    const int rq = lane >> 2, cq = (lane & 3) * 2;
    #pragma unroll
    for (int mt = 0; mt < 4; mt++) {
        int row0 = m0 + m_w + 16 * mt + rq;
        #pragma unroll
        for (int nt = 0; nt < 4; nt++) {
            int col = ncol0 + n_w + 8 * nt + cq;
            float b0 = bias[col], b1 = bias[col + 1];
            #pragma unroll
            for (int rr = 0; rr < 2; rr++) {
                int row = row0 + rr * 8;
                float x0 = acc[mt][nt][rr * 2 + 0] + b0;
                float x1 = acc[mt][nt][rr * 2 + 1] + b1;
                long long idx = (long long)row * 1024 + col;
                *(float2*)(C + idx) = make_float2(x0, x1);
                if (doHalf) {
                    __half h0, l0h, h1, l1h;
                    split2(x0, h0, l0h); split2(x1, h1, l1h);
                    *(__half2*)(Chi + idx) = __halves2half2(h0, h1);
                    *(__half2*)(Clo + idx) = __halves2half2(l0h, l1h);
                }
            }
        }
    }
}

// =================== conv1 (grouped k=3) on tensor cores ====================
#define CV_SMEM (2*33280 + 2*32768)

__global__ __launch_bounds__(256, 1)
void conv1_mma(const __half* __restrict__ xh, const __half* __restrict__ xl,
               const __half* __restrict__ wh, const __half* __restrict__ wl,
               const float* __restrict__ bias,
               __half* __restrict__ oh, __half* __restrict__ ol)
{
    extern __shared__ char smem[];
    const uint32_t sb = smem_to_u32(smem);
    const int tid = threadIdx.x, wid = tid >> 5, lane = tid & 31;
    const int l0 = blockIdx.x * 128, g = blockIdx.y, b = blockIdx.z;
    const int m_w = (wid & 1) * 64, n_w = (wid >> 1) * 32;
    const uint32_t XH = sb, WH = sb + 66560u;

    for (int t = tid; t < 2080; t += 256) {
        int r = t >> 4, c16 = t & 15;
        int l = l0 - 1 + r;
        uint32_t d = (uint32_t)(r * 256) + (uint32_t)((c16 * 16) ^ ((r & 7) << 4));
        uint4 vh = make_uint4(0u, 0u, 0u, 0u), vl = vh;
        if (l >= 0 && l < LL) {
            long long gidx = ((long long)b * LL + l) * HH + g * 128 + c16 * 8;
            vh = *(const uint4*)(xh + gidx);
            vl = *(const uint4*)(xl + gidx);
        }
        *(uint4*)(smem + d)         = vh;
        *(uint4*)(smem + 33280 + d) = vl;
    }

    float acc[4][4][4];
    #pragma unroll
    for (int mt = 0; mt < 4; mt++)
        #pragma unroll
        for (int nt = 0; nt < 4; nt++)
            #pragma unroll
            for (int q = 0; q < 4; q++) acc[mt][nt][q] = 0.f;

    const uint32_t aCol = (uint32_t)((lane >> 4) * 16);
    const uint32_t bCol = (uint32_t)(((lane >> 3) & 1) * 16);

    for (int tap = 0; tap < 3; tap++) {
        __syncthreads();
        for (int t = tid; t < 2048; t += 256) {
            int r = t >> 4, c16 = t & 15;
            uint32_t d = (uint32_t)(r * 256) + (uint32_t)((c16 * 16) ^ ((r & 7) << 4));
            long long widx = (long long)(g * 128 + r) * 384 + tap * 128 + c16 * 8;
            *(uint4*)(smem + 66560 + d) = *(const uint4*)(wh + widx);
            *(uint4*)(smem + 99328 + d) = *(const uint4*)(wl + widx);
        }
        __syncthreads();

        #pragma unroll
        for (int ks = 0; ks < 8; ks++) {
            const uint32_t kb = (uint32_t)(ks * 32);
            uint32_t ah[4][4], al[4][4], bh[4][2], bl[4][2];
            #pragma unroll
            for (int mt = 0; mt < 4; mt++) {
                int ar = m_w + 16 * mt + (lane & 15) + tap;
                uint32_t ad = XH + (uint32_t)(ar * 256) + ((kb + aCol) ^ (uint32_t)((ar & 7) << 4));
                ldm_x4(ah[mt][0], ah[mt][1], ah[mt][2], ah[mt][3], ad);
                ldm_x4(al[mt][0], al[mt][1], al[mt][2], al[mt][3], ad + 33280u);
            }
            #pragma unroll
            for (int nt = 0; nt < 4; nt++) {
                int br = n_w + 8 * nt + (lane & 7);
                uint32_t bd = WH + (uint32_t)(br * 256) + ((kb + bCol) ^ (uint32_t)((br & 7) << 4));
                ldm_x2(bh[nt][0], bh[nt][1], bd);
                ldm_x2(bl[nt][0], bl[nt][1], bd + 32768u);
            }
            #pragma unroll
            for (int mt = 0; mt < 4; mt++)
                #pragma unroll
                for (int nt = 0; nt < 4; nt++) {
                    mma16816(acc[mt][nt], ah[mt], bh[nt]);
                    mma16816(acc[mt][nt], ah[mt], bl[nt]);
                    mma16816(acc[mt][nt], al[mt], bh[nt]);
                }
        }
    }

    const int rq = lane >> 2, cq = (lane & 3) * 2;
    #pragma unroll
    for (int mt = 0; mt < 4; mt++) {
        int row0 = l0 + m_w + 16 * mt + rq;
        #pragma unroll
        for (int nt = 0; nt < 4; nt++) {
            int ch = g * 128 + n_w + 8 * nt + cq;
            float b0 = bias[ch], b1 = bias[ch + 1];
            #pragma unroll
            for (int rr = 0; rr < 2; rr++) {
                int row = row0 + rr * 8;
                float x0 = acc[mt][nt][rr * 2 + 0] + b0;
                float x1 = acc[mt][nt][rr * 2 + 1] + b1;
                float y0 = 0.5f * x0 * (1.0f + erff(x0 * 0.70710678118654752f));
                float y1 = 0.5f * x1 * (1.0f + erff(x1 * 0.70710678118654752f));
                __half h0, l0h, h1, l1h;
                split2(y0, h0, l0h); split2(y1, h1, l1h);
                long long idx = ((long long)b * LL + row) * HH + ch;
                *(__half2*)(oh + idx) = __halves2half2(h0, h1);
                *(__half2*)(ol + idx) = __halves2half2(l0h, l1h);
            }
        }
    }
}

// -------------------- fp32 -> (hi, lo) fp16 split ---------------------------
__global__ void split_fp16(const float4* __restrict__ x, uint2* __restrict__ hi,
                           uint2* __restrict__ lo, int n4)
{
    int i = blockIdx.x * 256 + threadIdx.x;
    if (i >= n4) return;
    float4 v = x[i];
    __half hx, lx, hy, ly, hz, lz, hw, lw;
    split2(v.x, hx, lx); split2(v.y, hy, ly);
    split2(v.z, hz, lz); split2(v.w, hw, lw);
    __half2 h0 = __halves2half2(hx, hy), h1 = __halves2half2(hz, hw);
    __half2 l0 = __halves2half2(lx, ly), l1 = __halves2half2(lz, lw);
    uint2 oh2, ol2;
    oh2.x = *(uint32_t*)&h0; oh2.y = *(uint32_t*)&h1;
    ol2.x = *(uint32_t*)&l0; ol2.y = *(uint32_t*)&l1;
    hi[i] = oh2; lo[i] = ol2;
}

// -------------- conv1 weight reorder + split: W[o, ic, 3] -> [o, tap*128+ic]
__global__ void wc1_transform(const float* __restrict__ W, __half* __restrict__ wh,
                              __half* __restrict__ wl)
{
    int idx = blockIdx.x * 256 + threadIdx.x;
    if (idx >= HH * 384) return;
    int o = idx / 384, k = idx % 384;
    int tap = k >> 7, ic = k & 127;
    float v = W[(long long)o * 384 + ic * 3 + tap];
    __half h, l;
    split2(v, h, l);
    wh[idx] = h; wl[idx] = l;
}

// ---------- V-slice transpose: vvT[b, h, t] = vv[b, 256+t, h] (hi/lo) -------
__global__ void transpose_vslice(const float* __restrict__ vv,
                                 __half* __restrict__ th, __half* __restrict__ tl)
{
    __shared__ float tile[32][33];
    const int t0 = blockIdx.x * 32, h0 = blockIdx.y * 32, b = blockIdx.z;
    const int tx = threadIdx.x, ty = threadIdx.y;
    #pragma unroll
    for (int y = ty; y < 32; y += 8)
        tile[y][tx] = vv[((long long)b * SS + 256 + t0 + y) * HH + h0 + tx];
    __syncthreads();
    #pragma unroll
    for (int y = ty; y < 32; y += 8) {
        float v = tile[tx][y];
        __half h, l;
        split2(v, h, l);
        long long o = ((long long)b * HH + h0 + y) * MID_N + t0 + tx;
        th[o] = h; tl[o] = l;
    }
}

// -------------------- copy text features hi/lo into att ---------------------
__global__ void copy_text(const float4* __restrict__ src,
                          __half* __restrict__ atth, __half* __restrict__ attl)
{
    int idx = blockIdx.x * 256 + threadIdx.x;
    int b = idx >> 18;
    int r = idx & 262143;
    float4 v = src[idx];
    long long he = ((long long)b * 524288 + 262144 + r) * 4;
    __half hx, lx, hy, ly, hz, lz, hw, lw;
    split2(v.x, hx, lx); split2(v.y, hy, ly);
    split2(v.z, hz, lz); split2(v.w, hw, lw);
    *(__half2*)(atth + he)     = __halves2half2(hx, hy);
    *(__half2*)(atth + he + 2) = __halves2half2(hz, hw);
    *(__half2*)(attl + he)     = __halves2half2(lx, ly);
    *(__half2*)(attl + he + 2) = __halves2half2(lz, lw);
}

// -------- v2t attention, tiled: 8 query rows per block, shared K/V smem -----
#define V2T_SMEM (40 * 1024 * 4)

__global__ __launch_bounds__(256, 1) void v2t_tile(
    const float* __restrict__ qvis, const float* __restrict__ ktext,
    const float* __restrict__ vtext, const float* __restrict__ visf,
    __half* __restrict__ atth, __half* __restrict__ attl)
{
    extern __shared__ float sm[];
    float* ks = sm;                // [20][1024]
    float* vs = sm + 20 * 1024;    // [20][1024]
    const int b = blockIdx.y, i0 = blockIdx.x * 8;
    const int tid = threadIdx.x, w = tid >> 5, lane = tid & 31;
    const int w0 = (i0 < 1016) ? i0 : 1016;

    const float* kb = ktext + (long long)b * SS * HH;
    const float* vb = vtext + (long long)b * SS * HH;
    for (int t = tid; t < 20 * 256; t += 256) {
        int slot = t >> 8, c4 = (t & 255) * 4;
        int row = (slot < 5) ? slot : (w0 + slot - 5);
        row = (row < 1023) ? row : 1023;
        *(float4*)(ks + slot * 1024 + c4) = *(const float4*)(kb + (long long)row * HH + c4);
        *(float4*)(vs + slot * 1024 + c4) = *(const float4*)(vb + (long long)row * HH + c4);
    }
    __syncthreads();

    const int i = i0 + w;
    const int s0 = (i < 1016) ? i : 1016;
    const int nk = (i < 5) ? (i + 8) : 13;

    const float* q = qvis + ((long long)b * SS + i) * HH;
    float qr[32];
    #pragma unroll
    for (int c = 0; c < 32; c++) qr[c] = q[c * 32 + lane];

    int sl[13];
    float p[13];
    #pragma unroll
    for (int j = 0; j < 13; j++) {
        int row = (i < 5) ? j : ((j < 5) ? j : (s0 + j - 5));
        sl[j] = (row < 5) ? row : (5 + row - w0);
        float s = 0.f;
        if (j < nk) {
            const float* kr = ks + sl[j] * 1024;
            #pragma unroll
            for (int c = 0; c < 32; c++) s += qr[c] * kr[c * 32 + lane];
        }
        #pragma unroll
        for (int off = 16; off; off >>= 1) s += __shfl_xor_sync(0xffffffffu, s, off);
        p[j] = s;
    }

    float mx = -3.4e38f;
    #pragma unroll
    for (int j = 0; j < 13; j++) if (j < nk) mx = fmaxf(mx, p[j]);
    float sum = 0.f;
    #pragma unroll
    for (int j = 0; j < 13; j++) {
        float e = (j < nk) ? expf(p[j] - mx) : 0.f;
        p[j] = e; sum += e;
    }
    const float inv = 1.f / sum;
    #pragma unroll
    for (int j = 0; j < 13; j++) p[j] *= inv;

    const float* vf = visf + ((long long)b * SS + i) * HH;
    long long ob = ((long long)b * LL + i) * HH;
    #pragma unroll 4
    for (int r = 0; r < 32; r++) {
        int h = r * 32 + lane;
        float a = vf[h];
        #pragma unroll
        for (int j = 0; j < 13; j++) a += p[j] * vs[sl[j] * 1024 + h];
        __half hh, lh;
        split2(a, hh, lh);
        atth[ob + h] = hh;
        attl[ob + h] = lh;
    }
}

// -------------------- t2v rows 0..4 (final-write hi/lo) ---------------------
__global__ __launch_bounds__(256) void t2v_full_rows(
    const float* __restrict__ qtext, const float* __restrict__ kvis,
    const float* __restrict__ vvis, const float* __restrict__ txt,
    __half* __restrict__ atth, __half* __restrict__ attl)
{
    const int r = blockIdx.x, b = blockIdx.y;
    const int tid = threadIdx.x, lane = tid & 31, warp = tid >> 5;
    __shared__ float qs[1024];
    __shared__ float sc[1024];
    __shared__ float red[8];

    const float* q = qtext + ((long long)b * SS + r) * HH;
    for (int h = tid; h < 1024; h += 256) qs[h] = q[h];
    __syncthreads();

    const float* kb = kvis + (long long)b * SS * HH;
    for (int t = warp * 128; t < warp * 128 + 128; t++) {
        const float* kp = kb + (long long)t * HH;
        float p = 0.f;
        #pragma unroll
        for (int c = 0; c < 32; c++) p += qs[c * 32 + lane] * kp[c * 32 + lane];
        #pragma unroll
        for (int off = 16; off; off >>= 1) p += __shfl_xor_sync(0xffffffffu, p, off);
        if (lane == 0) sc[t] = p;
    }
    __syncthreads();

    float m = -3.4e38f;
    for (int t = tid; t < 1024; t += 256) m = fmaxf(m, sc[t]);
    #pragma unroll
    for (int off = 16; off; off >>= 1) m = fmaxf(m, __shfl_xor_sync(0xffffffffu, m, off));
    if (lane == 0) red[warp] = m;
    __syncthreads();
    float mx = red[0];
    #pragma unroll
    for (int k = 1; k < 8; k++) mx = fmaxf(mx, red[k]);

    float s = 0.f;
    for (int t = tid; t < 1024; t += 256) { float e = expf(sc[t] - mx); sc[t] = e; s += e; }
    #pragma unroll
    for (int off = 16; off; off >>= 1) s += __shfl_xor_sync(0xffffffffu, s, off);
    __syncthreads();
    if (lane == 0) red[warp] = s;
    __syncthreads();
    float tot = 0.f;
    #pragma unroll
    for (int k = 0; k < 8; k++) tot += red[k];
    const float inv = 1.f / tot;

    const float* vb = vvis + (long long)b * SS * HH;
    const float* tx = txt + ((long long)b * SS + r) * HH;
    long long ob = ((long long)b * LL + 1024 + r) * HH;
    float accv[4] = {0.f, 0.f, 0.f, 0.f};
    for (int t = 0; t < 1024; t++) {
        float pw = sc[t];
        const float* vr = vb + (long long)t * HH + tid;
        accv[0] += pw * vr[0];
        accv[1] += pw * vr[256];
        accv[2] += pw * vr[512];
        accv[3] += pw * vr[768];
    }
    #pragma unroll
    for (int k = 0; k < 4; k++) {
        int h = tid + k * 256;
        float v = tx[h] + accv[k] * inv;
        __half hh, lh;
        split2(v, hh, lh);
        atth[ob + h] = hh;
        attl[ob + h] = lh;
    }
}

// -------------------- softmax over 512-col rows -> probs hi/lo --------------
__global__ __launch_bounds__(256) void softmax512(const float* __restrict__ S,
                                                  __half* __restrict__ ph,
                                                  __half* __restrict__ pl)
{
    const float* row = S + (long long)blockIdx.x * 512;
    const int tid = threadIdx.x, lane = tid & 31, warp = tid >> 5;
    __shared__ float red[8];
    float a = row[tid], b2 = row[tid + 256];
    float m = fmaxf(a, b2);
    #pragma unroll
    for (int off = 16; off; off >>= 1) m = fmaxf(m, __shfl_xor_sync(0xffffffffu, m, off));
    if (lane == 0) red[warp] = m;
    __syncthreads();
    float mx = red[0];
    #pragma unroll
    for (int k = 1; k < 8; k++) mx = fmaxf(mx, red[k]);
    float e0 = expf(a - mx), e1 = expf(b2 - mx);
    float s = e0 + e1;
    #pragma unroll
    for (int off = 16; off; off >>= 1) s += __shfl_xor_sync(0xffffffffu, s, off);
    __syncthreads();
    if (lane == 0) red[warp] = s;
    __syncthreads();
    float tot = 0.f;
    #pragma unroll
    for (int k = 0; k < 8; k++) tot += red[k];
    float inv = 1.f / tot;
    long long base = (long long)blockIdx.x * 512;
    __half h0, l0, h1, l1;
    split2(e0 * inv, h0, l0);
    split2(e1 * inv, h1, l1);
    ph[base + tid] = h0; pl[base + tid] = l0;
    ph[base + tid + 256] = h1; pl[base + tid + 256] = l1;
}

// -------------------- launcher ----------------------------------------------
extern "C" void kernel_launch(void* const* d_in, const int* in_sizes, int n_in,
                              void* d_out, int out_size)
{
    (void)in_sizes; (void)n_in; (void)out_size;
    const float* vis = (const float*)d_in[0];
    const float* txt = (const float*)d_in[1];
    const float* Wq  = (const float*)d_in[2];  const float* bq  = (const float*)d_in[3];
    const float* Wk  = (const float*)d_in[4];  const float* bk  = (const float*)d_in[5];
    const float* Wv  = (const float*)d_in[6];  const float* bv  = (const float*)d_in[7];
    const float* Wc1 = (const float*)d_in[8];  const float* bc1 = (const float*)d_in[9];
    const float* Wc2 = (const float*)d_in[10]; const float* bc2 = (const float*)d_in[11];
    float* out = (float*)d_out;

    float *qt, *kv, *vv, *qv, *kt, *vt, *attb, *scb;
    __half *vish, *visl, *txth, *txtl, *c1h, *c1l, *wh, *wl;
    __half *qth, *qtl, *kvh, *kvl, *atth, *attl, *wc1h, *wc1l;
    __half *sch, *scl, *vvTh, *vvTl;
    cudaGetSymbolAddress((void**)&qt,  g_q_text);
    cudaGetSymbolAddress((void**)&kv,  g_k_vis);
    cudaGetSymbolAddress((void**)&vv,  g_v_vis);
    cudaGetSymbolAddress((void**)&qv,  g_q_vis);
    cudaGetSymbolAddress((void**)&kt,  g_k_text);
    cudaGetSymbolAddress((void**)&vt,  g_v_text);
    cudaGetSymbolAddress((void**)&attb, g_att);
    cudaGetSymbolAddress((void**)&scb, g_scores);
    cudaGetSymbolAddress((void**)&vish, g_vis_hi);
    cudaGetSymbolAddress((void**)&visl, g_vis_lo);
    cudaGetSymbolAddress((void**)&txth, g_txt_hi);
    cudaGetSymbolAddress((void**)&txtl, g_txt_lo);
    cudaGetSymbolAddress((void**)&c1h, g_c1_hi);
    cudaGetSymbolAddress((void**)&c1l, g_c1_lo);
    cudaGetSymbolAddress((void**)&wh,  g_w_hi);
    cudaGetSymbolAddress((void**)&wl,  g_w_lo);
    cudaGetSymbolAddress((void**)&qth, g_qt_hi);
    cudaGetSymbolAddress((void**)&qtl, g_qt_lo);
    cudaGetSymbolAddress((void**)&kvh, g_kv_hi);
    cudaGetSymbolAddress((void**)&kvl, g_kv_lo);
    cudaGetSymbolAddress((void**)&atth, g_att_hi);
    cudaGetSymbolAddress((void**)&attl, g_att_lo);
    cudaGetSymbolAddress((void**)&wc1h, g_wc1r_hi);
    cudaGetSymbolAddress((void**)&wc1l, g_wc1r_lo);
    cudaGetSymbolAddress((void**)&sch, g_sc_hi);
    cudaGetSymbolAddress((void**)&scl, g_sc_lo);
    cudaGetSymbolAddress((void**)&vvTh, g_vvT_hi);
    cudaGetSymbolAddress((void**)&vvTl, g_vvT_lo);

    cudaFuncSetAttribute((const void*)&mma_qkv,
                         cudaFuncAttributeMaxDynamicSharedMemorySize, MG_SMEM);
    cudaFuncSetAttribute((const void*)&mma_gemm<false, false, true,  false>,
                         cudaFuncAttributeMaxDynamicSharedMemorySize, MG_SMEM);
    cudaFuncSetAttribute((const void*)&mma_gemm<false, true,  true,  true>,
                         cudaFuncAttributeMaxDynamicSharedMemorySize, MG_SMEM);
    cudaFuncSetAttribute((const void*)&mma_gemm<true,  false, false, false>,
                         cudaFuncAttributeMaxDynamicSharedMemorySize, MG_SMEM);
    cudaFuncSetAttribute((const void*)&conv1_mma,
                         cudaFuncAttributeMaxDynamicSharedMemorySize, CV_SMEM);
    cudaFuncSetAttribute((const void*)&v2t_tile,
                         cudaFuncAttributeMaxDynamicSharedMemorySize, V2T_SMEM);

    const long long SH = (long long)SS * HH;
    const long long LH = (long long)LL * HH;
    const long long SCs = (long long)MID_M * MID_N;

    // 0) splits + weight transforms
    int n4in = BB * SS * HH / 4;
    split_fp16<<<(n4in + 255) / 256, 256>>>((const float4*)vis, (uint2*)vish, (uint2*)visl, n4in);
    split_fp16<<<(n4in + 255) / 256, 256>>>((const float4*)txt, (uint2*)txth, (uint2*)txtl, n4in);
    int n4w = WW / 4;
    split_fp16<<<(n4w + 255) / 256, 256>>>((const float4*)Wq,  (uint2*)(wh + 0 * WW), (uint2*)(wl + 0 * WW), n4w);
    split_fp16<<<(n4w + 255) / 256, 256>>>((const float4*)Wk,  (uint2*)(wh + 1 * WW), (uint2*)(wl + 1 * WW), n4w);
    split_fp16<<<(n4w + 255) / 256, 256>>>((const float4*)Wv,  (uint2*)(wh + 2 * WW), (uint2*)(wl + 2 * WW), n4w);
    split_fp16<<<(n4w + 255) / 256, 256>>>((const float4*)Wc2, (uint2*)(wh + 3 * WW), (uint2*)(wl + 3 * WW), n4w);
    wc1_transform<<<(HH * 384 + 255) / 256, 256>>>(Wc1, wc1h, wc1l);

    // 1) fused QKV projections (stacked weights = wh[0..3*WW))
    dim3 gq(24, 64, 1);
    //   text: seg0->q_text (hi/lo), seg1->k_text, seg2->v_text
    mma_qkv<<<gq, 256, MG_SMEM>>>(txth, txtl, wh, wl, bq, bk, bv,
                                  qt, kt, vt, qth, qtl, 0);
    //   vis:  seg0->q_vis, seg1->k_vis (hi/lo), seg2->v_vis
    mma_qkv<<<gq, 256, MG_SMEM>>>(vish, visl, wh, wl, bq, bk, bv,
                                  qv, kv, vv, kvh, kvl, 1);

    // 2) text residual rows -> att hi/lo
    copy_text<<<8192, 256>>>((const float4*)txt, atth, attl);

    // 3) v2t sparse attention (tiled, 8 rows/block)
    v2t_tile<<<dim3(SS / 8, BB), 256, V2T_SMEM>>>(qv, kt, vt, vis, atth, attl);

    // 4) t2v rows 0..4
    t2v_full_rows<<<dim3(5, BB), 256>>>(qt, kv, vv, txt, atth, attl);

    // 5) t2v mid scores on tensor cores
    mma_gemm<false, false, true, false><<<dim3(MID_N / 128, 3, BB), 256, MG_SMEM>>>(
        qth + 341 * HH, qtl + 341 * HH, SH,
        kvh + 256 * HH, kvl + 256 * HH, SH,
        scb, SCs, MID_N, nullptr, nullptr, nullptr, nullptr, 0, 0, MID_M, HH);

    // 6) softmax -> probs hi/lo
    softmax512<<<BB * MID_M, 256>>>(scb, sch, scl);

    // 6b) transpose V slice -> [b, h, t] hi/lo
    transpose_vslice<<<dim3(MID_N / 32, HH / 32, BB), dim3(32, 8)>>>(vv, vvTh, vvTl);

    // 7) AV on tensor cores + text residual -> att rows 1365..1705 hi/lo
    mma_gemm<false, true, true, true><<<dim3(HH / 128, 3, BB), 256, MG_SMEM>>>(
        sch, scl, SCs,
        vvTh, vvTl, (long long)HH * MID_N,
        attb + (long long)(1024 + 341) * HH, LH, HH,
        nullptr,
        atth + (long long)(1024 + 341) * HH, attl + (long long)(1024 + 341) * HH,
        txt + 341 * HH, SH, HH,
        MID_M, MID_N);

    // 8) conv1 (grouped, k=3) + GELU on tensor cores -> c1 hi/lo
    conv1_mma<<<dim3(LL / 128, 8, BB), 256, CV_SMEM>>>(atth, attl, wc1h, wc1l, bc1, c1h, c1l);

    // 9) pointwise conv2 on tensor cores -> output
    mma_gemm<true, false, false, false><<<dim3(HH / 128, BB * LL / 128, 1), 256, MG_SMEM>>>(
        c1h, c1l, 0, wh + 3 * WW, wl + 3 * WW, 0,
        out, 0, HH, bc2, nullptr, nullptr, nullptr, 0, 0, BB * LL, HH);
}

// round 7
// speedup vs baseline: 2.8914x; 1.0493x over previous
#include <cuda_runtime.h>
#include <cuda_fp16.h>
#include <math.h>
#include <stdint.h>

// Problem constants (B=8, V=T=1024, H=1024, L=V+T=2048)
#define BB 8
#define SS 1024
#define HH 1024
#define LL 2048
#define MID_M 341
#define MID_N 512
#define WW (HH*HH)

// -------------------- scratch (device globals) ------------------------------
__device__ __align__(128) float g_q_text[BB*SS*HH];
__device__ __align__(128) float g_k_vis [BB*SS*HH];
__device__ __align__(128) float g_v_vis [BB*SS*HH];
__device__ __align__(128) float g_q_vis [BB*SS*HH];
__device__ __align__(128) float g_k_text[BB*SS*HH];
__device__ __align__(128) float g_v_text[BB*SS*HH];
__device__ __align__(128) float g_att   [BB*LL*HH];
__device__ __align__(128) float g_scores[BB*MID_M*MID_N];
__device__ __align__(128) __half g_vis_hi[BB*SS*HH];
__device__ __align__(128) __half g_vis_lo[BB*SS*HH];
__device__ __align__(128) __half g_txt_hi[BB*SS*HH];
__device__ __align__(128) __half g_txt_lo[BB*SS*HH];
__device__ __align__(128) __half g_c1_hi [BB*LL*HH];
__device__ __align__(128) __half g_c1_lo [BB*LL*HH];
__device__ __align__(128) __half g_w_hi  [4*WW];      // Wq, Wk, Wv, Wc2
__device__ __align__(128) __half g_w_lo  [4*WW];
__device__ __align__(128) __half g_qt_hi [BB*SS*HH];
__device__ __align__(128) __half g_qt_lo [BB*SS*HH];
__device__ __align__(128) __half g_kv_hi [BB*SS*HH];
__device__ __align__(128) __half g_kv_lo [BB*SS*HH];
__device__ __align__(128) __half g_att_hi[BB*LL*HH];
__device__ __align__(128) __half g_att_lo[BB*LL*HH];
__device__ __align__(128) __half g_wc1r_hi[HH*384];
__device__ __align__(128) __half g_sc_hi [BB*MID_M*MID_N];
__device__ __align__(128) __half g_sc_lo [BB*MID_M*MID_N];
__device__ __align__(128) __half g_vvT_hi[BB*HH*MID_N];

// ===================== low-level helpers ====================================
__device__ __forceinline__ uint32_t smem_to_u32(const void* p) {
    uint32_t a;
    asm("{ .reg .u64 t; cvta.to.shared.u64 t, %1; cvt.u32.u64 %0, t; }" : "=r"(a) : "l"(p));
    return a;
}
__device__ __forceinline__ void cp_async16(uint32_t saddr, const void* gptr) {
    asm volatile("cp.async.cg.shared.global [%0], [%1], 16;" :: "r"(saddr), "l"(gptr));
}
#define CP_COMMIT() asm volatile("cp.async.commit_group;" ::: "memory")
#define CP_WAIT1()  asm volatile("cp.async.wait_group 1;" ::: "memory")
#define CP_WAIT0()  asm volatile("cp.async.wait_group 0;" ::: "memory")

__device__ __forceinline__ void ldm_x4(uint32_t& r0, uint32_t& r1, uint32_t& r2, uint32_t& r3,
                                       uint32_t addr) {
    asm volatile("ldmatrix.sync.aligned.m8n8.x4.shared.b16 {%0,%1,%2,%3}, [%4];"
                 : "=r"(r0), "=r"(r1), "=r"(r2), "=r"(r3) : "r"(addr));
}
__device__ __forceinline__ void ldm_x2(uint32_t& r0, uint32_t& r1, uint32_t addr) {
    asm volatile("ldmatrix.sync.aligned.m8n8.x2.shared.b16 {%0,%1}, [%2];"
                 : "=r"(r0), "=r"(r1) : "r"(addr));
}
__device__ __forceinline__ void mma16816(float* c, const uint32_t* a, const uint32_t* b) {
    asm volatile("mma.sync.aligned.m16n8k16.row.col.f32.f16.f16.f32 "
                 "{%0,%1,%2,%3}, {%4,%5,%6,%7}, {%8,%9}, {%0,%1,%2,%3};"
                 : "+f"(c[0]), "+f"(c[1]), "+f"(c[2]), "+f"(c[3])
                 : "r"(a[0]), "r"(a[1]), "r"(a[2]), "r"(a[3]), "r"(b[0]), "r"(b[1]));
}
__device__ __forceinline__ void split2(float v, __half& h, __half& l) {
    h = __float2half_rn(v);
    l = __float2half_rn(v - __half2float(h));
}

#define MG_SMEM (3 * 65536)

// =================== generic tensor-core GEMM ===============================
// C[M,N] = A[M,K] @ B[N,K]^T (+bias)(+residual). A always hi/lo split.
// TERM3: also split B (3 mma terms); else B hi only (2 terms).
template<bool BIAS, bool HALFOUT, bool GUARD, bool RESID, bool TERM3>
__global__ __launch_bounds__(256, 1)
void mma_gemm(const __half* __restrict__ Ahi, const __half* __restrict__ Alo, long long sA,
              const __half* __restrict__ Bhi, const __half* __restrict__ Blo, long long sB,
              float* __restrict__ C, long long sC, int ldc,
              const float* __restrict__ bias,
              __half* __restrict__ Chi, __half* __restrict__ Clo,
              const float* __restrict__ Rm, long long sR, int ldr,
              int M, int K)
{
    extern __shared__ char smem[];
    const uint32_t sbase = smem_to_u32(smem);
    const int tid = threadIdx.x;
    const int wid = tid >> 5, lane = tid & 31;
    const int m0 = blockIdx.y * 128, n0 = blockIdx.x * 128;
    const int m_w = (wid & 1) * 64;
    const int n_w = (wid >> 1) * 32;
    const int z = blockIdx.z;
    Ahi += z * sA; Alo += z * sA;
    Bhi += z * sB; if (TERM3) Blo += z * sB;
    C   += z * sC;
    if (HALFOUT) { Chi += z * sC; Clo += z * sC; }
    if (RESID)   { Rm  += z * sR; }

    const int crow = tid >> 3;
    const int cc16 = tid & 7;
    const int nk = K >> 6;

    auto issue_stage = [&](int kc, int s) {
        const int k0 = kc * 64;
        const uint32_t st = sbase + (uint32_t)s * 65536u;
        #pragma unroll
        for (int p = 0; p < 4; p++) {
            int row = p * 32 + crow;
            uint32_t soff = (uint32_t)(row * 128) + (uint32_t)((cc16 * 16) ^ ((row & 7) << 4));
            int gm = m0 + row;
            if (GUARD) gm = (gm < M) ? gm : (M - 1);
            long long ga = (long long)gm * K + k0 + cc16 * 8;
            long long gb = (long long)(n0 + row) * K + k0 + cc16 * 8;
            cp_async16(st + soff,          Ahi + ga);
            cp_async16(st + 16384 + soff,  Alo + ga);
            cp_async16(st + 32768 + soff,  Bhi + gb);
            if (TERM3) cp_async16(st + 49152 + soff, Blo + gb);
        }
    };

    uint32_t aRow[4], aXor[4];
    #pragma unroll
    for (int mt = 0; mt < 4; mt++) {
        int r = m_w + 16 * mt + (lane & 15);
        aRow[mt] = (uint32_t)(r * 128);
        aXor[mt] = (uint32_t)((r & 7) << 4);
    }
    const uint32_t aCol = (uint32_t)((lane >> 4) * 16);
    uint32_t bRow[4], bXor[4];
    #pragma unroll
    for (int nt = 0; nt < 4; nt++) {
        int r = n_w + 8 * nt + (lane & 7);
        bRow[nt] = (uint32_t)(r * 128);
        bXor[nt] = (uint32_t)((r & 7) << 4);
    }
    const uint32_t bCol = (uint32_t)(((lane >> 3) & 1) * 16);

    float acc[4][4][4];
    #pragma unroll
    for (int mt = 0; mt < 4; mt++)
        #pragma unroll
        for (int nt = 0; nt < 4; nt++)
            #pragma unroll
            for (int q = 0; q < 4; q++) acc[mt][nt][q] = 0.f;

    auto compute = [&](int s) {
        const uint32_t st = sbase + (uint32_t)s * 65536u;
        #pragma unroll
        for (int ks = 0; ks < 4; ks++) {
            const uint32_t kb = (uint32_t)(ks * 32);
            uint32_t ah[4][4], al[4][4], bh[4][2], bl[4][2];
            #pragma unroll
            for (int mt = 0; mt < 4; mt++) {
                uint32_t ad = st + aRow[mt] + ((kb + aCol) ^ aXor[mt]);
                ldm_x4(ah[mt][0], ah[mt][1], ah[mt][2], ah[mt][3], ad);
                ldm_x4(al[mt][0], al[mt][1], al[mt][2], al[mt][3], ad + 16384);
            }
            #pragma unroll
            for (int nt = 0; nt < 4; nt++) {
                uint32_t bd = st + 32768 + bRow[nt] + ((kb + bCol) ^ bXor[nt]);
                ldm_x2(bh[nt][0], bh[nt][1], bd);
                if (TERM3) ldm_x2(bl[nt][0], bl[nt][1], bd + 16384);
            }
            #pragma unroll
            for (int mt = 0; mt < 4; mt++)
                #pragma unroll
                for (int nt = 0; nt < 4; nt++) {
                    mma16816(acc[mt][nt], ah[mt], bh[nt]);
                    if (TERM3) mma16816(acc[mt][nt], ah[mt], bl[nt]);
                    mma16816(acc[mt][nt], al[mt], bh[nt]);
                }
        }
    };

    issue_stage(0, 0); CP_COMMIT();
    issue_stage(1, 1); CP_COMMIT();
    for (int kc = 0; kc < nk; kc++) {
        if (kc + 1 < nk) { CP_WAIT1(); } else { CP_WAIT0(); }
        __syncthreads();
        if (kc + 2 < nk) { issue_stage(kc + 2, (kc + 2) % 3); CP_COMMIT(); }
        compute(kc % 3);
    }

    const int rq = lane >> 2, cq = (lane & 3) * 2;
    #pragma unroll
    for (int mt = 0; mt < 4; mt++) {
        int row0 = m0 + m_w + 16 * mt + rq;
        #pragma unroll
        for (int nt = 0; nt < 4; nt++) {
            int col = n0 + n_w + 8 * nt + cq;
            float b0 = 0.f, b1 = 0.f;
            if (BIAS) { b0 = bias[col]; b1 = bias[col + 1]; }
            #pragma unroll
            for (int rr = 0; rr < 2; rr++) {
                int row = row0 + rr * 8;
                if (GUARD && row >= M) continue;
                float x0 = acc[mt][nt][rr * 2 + 0] + b0;
                float x1 = acc[mt][nt][rr * 2 + 1] + b1;
                if (RESID) {
                    const float* Rp = Rm + (long long)row * ldr + col;
                    x0 += Rp[0]; x1 += Rp[1];
                }
                long long idx = (long long)row * ldc + col;
                *(float2*)(C + idx) = make_float2(x0, x1);
                if (HALFOUT) {
                    __half h0, l0h, h1, l1h;
                    split2(x0, h0, l0h); split2(x1, h1, l1h);
                    *(__half2*)(Chi + idx) = __halves2half2(h0, h1);
                    *(__half2*)(Clo + idx) = __halves2half2(l0h, l1h);
                }
            }
        }
    }
}

// ============ fused QKV projection: N=3072 stacked weights ==================
// seg = n-tile/1024 routes outputs. seg 0,1 (q,k) use 3-term; seg 2 (v) 2-term.
__global__ __launch_bounds__(256, 1)
void mma_qkv(const __half* __restrict__ Ahi, const __half* __restrict__ Alo,
             const __half* __restrict__ Bhi, const __half* __restrict__ Blo,
             const float* __restrict__ b0p, const float* __restrict__ b1p,
             const float* __restrict__ b2p,
             float* __restrict__ C0, float* __restrict__ C1, float* __restrict__ C2,
             __half* __restrict__ Chi, __half* __restrict__ Clo, int hseg)
{
    extern __shared__ char smem[];
    const uint32_t sbase = smem_to_u32(smem);
    const int tid = threadIdx.x;
    const int wid = tid >> 5, lane = tid & 31;
    const int m0 = blockIdx.y * 128, n0 = blockIdx.x * 128;
    const int m_w = (wid & 1) * 64;
    const int n_w = (wid >> 1) * 32;
    const int seg = n0 >> 10;
    const int ncol0 = n0 & 1023;
    const bool t3 = (seg < 2);
    float* C = (seg == 0) ? C0 : (seg == 1) ? C1 : C2;
    const float* bias = (seg == 0) ? b0p : (seg == 1) ? b1p : b2p;
    const bool doHalf = (seg == hseg);

    const int crow = tid >> 3;
    const int cc16 = tid & 7;

    auto issue_stage = [&](int kc, int s) {
        const int k0 = kc * 64;
        const uint32_t st = sbase + (uint32_t)s * 65536u;
        #pragma unroll
        for (int p = 0; p < 4; p++) {
            int row = p * 32 + crow;
            uint32_t soff = (uint32_t)(row * 128) + (uint32_t)((cc16 * 16) ^ ((row & 7) << 4));
            long long ga = (long long)(m0 + row) * 1024 + k0 + cc16 * 8;
            long long gb = (long long)(n0 + row) * 1024 + k0 + cc16 * 8;
            cp_async16(st + soff,          Ahi + ga);
            cp_async16(st + 16384 + soff,  Alo + ga);
            cp_async16(st + 32768 + soff,  Bhi + gb);
            if (t3) cp_async16(st + 49152 + soff, Blo + gb);
        }
    };

    uint32_t aRow[4], aXor[4];
    #pragma unroll
    for (int mt = 0; mt < 4; mt++) {
        int r = m_w + 16 * mt + (lane & 15);
        aRow[mt] = (uint32_t)(r * 128);
        aXor[mt] = (uint32_t)((r & 7) << 4);
    }
    const uint32_t aCol = (uint32_t)((lane >> 4) * 16);
    uint32_t bRow[4], bXor[4];
    #pragma unroll
    for (int nt = 0; nt < 4; nt++) {
        int r = n_w + 8 * nt + (lane & 7);
        bRow[nt] = (uint32_t)(r * 128);
        bXor[nt] = (uint32_t)((r & 7) << 4);
    }
    const uint32_t bCol = (uint32_t)(((lane >> 3) & 1) * 16);

    float acc[4][4][4];
    #pragma unroll
    for (int mt = 0; mt < 4; mt++)
        #pragma unroll
        for (int nt = 0; nt < 4; nt++)
            #pragma unroll
            for (int q = 0; q < 4; q++) acc[mt][nt][q] = 0.f;

    auto compute = [&](int s) {
        const uint32_t st = sbase + (uint32_t)s * 65536u;
        #pragma unroll
        for (int ks = 0; ks < 4; ks++) {
            const uint32_t kb = (uint32_t)(ks * 32);
            uint32_t ah[4][4], al[4][4], bh[4][2], bl[4][2];
            #pragma unroll
            for (int mt = 0; mt < 4; mt++) {
                uint32_t ad = st + aRow[mt] + ((kb + aCol) ^ aXor[mt]);
                ldm_x4(ah[mt][0], ah[mt][1], ah[mt][2], ah[mt][3], ad);
                ldm_x4(al[mt][0], al[mt][1], al[mt][2], al[mt][3], ad + 16384);
            }
            #pragma unroll
            for (int nt = 0; nt < 4; nt++) {
                uint32_t bd = st + 32768 + bRow[nt] + ((kb + bCol) ^ bXor[nt]);
                ldm_x2(bh[nt][0], bh[nt][1], bd);
                if (t3) ldm_x2(bl[nt][0], bl[nt][1], bd + 16384);
            }
            #pragma unroll
            for (int mt = 0; mt < 4; mt++)
                #pragma unroll
                for (int nt = 0; nt < 4; nt++) {
                    mma16816(acc[mt][nt], ah[mt], bh[nt]);
                    if (t3) mma16816(acc[mt][nt], ah[mt], bl[nt]);
                    mma16816(acc[mt][nt], al[mt], bh[nt]);
                }
        }
    };

    issue_stage(0, 0); CP_COMMIT();
    issue_stage(1, 1); CP_COMMIT();
    for (int kc = 0; kc < 16; kc++) {
        if (kc + 1 < 16) { CP_WAIT1(); } else { CP_WAIT0(); }
        __syncthreads();
        if (kc + 2 < 16) { issue_stage(kc + 2, (kc + 2) % 3); CP_COMMIT(); }
        compute(kc % 3);
    }

    const int rq = lane >> 2, cq = (lane & 3) * 2;
    #pragma unroll
    for (int mt = 0; mt < 4; mt++) {
        int row0 = m0 + m_w + 16 * mt + rq;
        #pragma unroll
        for (int nt = 0; nt < 4; nt++) {
            int col = ncol0 + n_w + 8 * nt + cq;
            float b0 = bias[col], b1 = bias[col + 1];
            #pragma unroll
            for (int rr = 0; rr < 2; rr++) {
                int row = row0 + rr * 8;
                float x0 = acc[mt][nt][rr * 2 + 0] + b0;
                float x1 = acc[mt][nt][rr * 2 + 1] + b1;
                long long idx = (long long)row * 1024 + col;
                *(float2*)(C + idx) = make_float2(x0, x1);
                if (doHalf) {
                    __half h0, l0h, h1, l1h;
                    split2(x0, h0, l0h); split2(x1, h1, l1h);
                    *(__half2*)(Chi + idx) = __halves2half2(h0, h1);
                    *(__half2*)(Clo + idx) = __halves2half2(l0h, l1h);
                }
            }
        }
    }
}

// =================== conv1 (grouped k=3), 2-term (x split, w hi) ============
#define CV_SMEM (2*33280 + 32768)

__global__ __launch_bounds__(256, 1)
void conv1_mma(const __half* __restrict__ xh, const __half* __restrict__ xl,
               const __half* __restrict__ wh,
               const float* __restrict__ bias,
               __half* __restrict__ oh, __half* __restrict__ ol)
{
    extern __shared__ char smem[];
    const uint32_t sb = smem_to_u32(smem);
    const int tid = threadIdx.x, wid = tid >> 5, lane = tid & 31;
    const int l0 = blockIdx.x * 128, g = blockIdx.y, b = blockIdx.z;
    const int m_w = (wid & 1) * 64, n_w = (wid >> 1) * 32;
    const uint32_t XH = sb, WH = sb + 66560u;

    for (int t = tid; t < 2080; t += 256) {
        int r = t >> 4, c16 = t & 15;
        int l = l0 - 1 + r;
        uint32_t d = (uint32_t)(r * 256) + (uint32_t)((c16 * 16) ^ ((r & 7) << 4));
        uint4 vh = make_uint4(0u, 0u, 0u, 0u), vl = vh;
        if (l >= 0 && l < LL) {
            long long gidx = ((long long)b * LL + l) * HH + g * 128 + c16 * 8;
            vh = *(const uint4*)(xh + gidx);
            vl = *(const uint4*)(xl + gidx);
        }
        *(uint4*)(smem + d)         = vh;
        *(uint4*)(smem + 33280 + d) = vl;
    }

    float acc[4][4][4];
    #pragma unroll
    for (int mt = 0; mt < 4; mt++)
        #pragma unroll
        for (int nt = 0; nt < 4; nt++)
            #pragma unroll
            for (int q = 0; q < 4; q++) acc[mt][nt][q] = 0.f;

    const uint32_t aCol = (uint32_t)((lane >> 4) * 16);
    const uint32_t bCol = (uint32_t)(((lane >> 3) & 1) * 16);

    for (int tap = 0; tap < 3; tap++) {
        __syncthreads();
        for (int t = tid; t < 2048; t += 256) {
            int r = t >> 4, c16 = t & 15;
            uint32_t d = (uint32_t)(r * 256) + (uint32_t)((c16 * 16) ^ ((r & 7) << 4));
            long long widx = (long long)(g * 128 + r) * 384 + tap * 128 + c16 * 8;
            *(uint4*)(smem + 66560 + d) = *(const uint4*)(wh + widx);
        }
        __syncthreads();

        #pragma unroll
        for (int ks = 0; ks < 8; ks++) {
            const uint32_t kb = (uint32_t)(ks * 32);
            uint32_t ah[4][4], al[4][4], bh[4][2];
            #pragma unroll
            for (int mt = 0; mt < 4; mt++) {
                int ar = m_w + 16 * mt + (lane & 15) + tap;
                uint32_t ad = XH + (uint32_t)(ar * 256) + ((kb + aCol) ^ (uint32_t)((ar & 7) << 4));
                ldm_x4(ah[mt][0], ah[mt][1], ah[mt][2], ah[mt][3], ad);
                ldm_x4(al[mt][0], al[mt][1], al[mt][2], al[mt][3], ad + 33280u);
            }
            #pragma unroll
            for (int nt = 0; nt < 4; nt++) {
                int br = n_w + 8 * nt + (lane & 7);
                uint32_t bd = WH + (uint32_t)(br * 256) + ((kb + bCol) ^ (uint32_t)((br & 7) << 4));
                ldm_x2(bh[nt][0], bh[nt][1], bd);
            }
            #pragma unroll
            for (int mt = 0; mt < 4; mt++)
                #pragma unroll
                for (int nt = 0; nt < 4; nt++) {
                    mma16816(acc[mt][nt], ah[mt], bh[nt]);
                    mma16816(acc[mt][nt], al[mt], bh[nt]);
                }
        }
    }

    const int rq = lane >> 2, cq = (lane & 3) * 2;
    #pragma unroll
    for (int mt = 0; mt < 4; mt++) {
        int row0 = l0 + m_w + 16 * mt + rq;
        #pragma unroll
        for (int nt = 0; nt < 4; nt++) {
            int ch = g * 128 + n_w + 8 * nt + cq;
            float b0 = bias[ch], b1 = bias[ch + 1];
            #pragma unroll
            for (int rr = 0; rr < 2; rr++) {
                int row = row0 + rr * 8;
                float x0 = acc[mt][nt][rr * 2 + 0] + b0;
                float x1 = acc[mt][nt][rr * 2 + 1] + b1;
                float y0 = 0.5f * x0 * (1.0f + erff(x0 * 0.70710678118654752f));
                float y1 = 0.5f * x1 * (1.0f + erff(x1 * 0.70710678118654752f));
                __half h0, l0h, h1, l1h;
                split2(y0, h0, l0h); split2(y1, h1, l1h);
                long long idx = ((long long)b * LL + row) * HH + ch;
                *(__half2*)(oh + idx) = __halves2half2(h0, h1);
                *(__half2*)(ol + idx) = __halves2half2(l0h, l1h);
            }
        }
    }
}

// -------------------- fused fp32 -> (hi, lo) splits -------------------------
__global__ void split_fp16_2(const float4* __restrict__ x0, uint2* __restrict__ h0,
                             uint2* __restrict__ l0, const float4* __restrict__ x1,
                             uint2* __restrict__ h1, uint2* __restrict__ l1, int n4)
{
    int i = blockIdx.x * 256 + threadIdx.x;
    const float4* x; uint2 *hp, *lp;
    if (i >= n4) { i -= n4; if (i >= n4) return; x = x1; hp = h1; lp = l1; }
    else { x = x0; hp = h0; lp = l0; }
    float4 v = x[i];
    __half hx, lx, hy, ly, hz, lz, hw, lw;
    split2(v.x, hx, lx); split2(v.y, hy, ly);
    split2(v.z, hz, lz); split2(v.w, hw, lw);
    __half2 a0 = __halves2half2(hx, hy), a1 = __halves2half2(hz, hw);
    __half2 b0 = __halves2half2(lx, ly), b1 = __halves2half2(lz, lw);
    uint2 oh2, ol2;
    oh2.x = *(uint32_t*)&a0; oh2.y = *(uint32_t*)&a1;
    ol2.x = *(uint32_t*)&b0; ol2.y = *(uint32_t*)&b1;
    hp[i] = oh2; lp[i] = ol2;
}

__global__ void split_w4(const float4* __restrict__ wq, const float4* __restrict__ wk,
                         const float4* __restrict__ wv, const float4* __restrict__ wc2,
                         uint2* __restrict__ hi, uint2* __restrict__ lo)
{
    int idx = blockIdx.x * 256 + threadIdx.x;      // 4 * WW/4 total
    int seg = idx >> 18, i = idx & 262143;         // WW/4 = 262144
    const float4* src = (seg == 0) ? wq : (seg == 1) ? wk : (seg == 2) ? wv : wc2;
    float4 v = src[i];
    __half hx, lx, hy, ly, hz, lz, hw, lw;
    split2(v.x, hx, lx); split2(v.y, hy, ly);
    split2(v.z, hz, lz); split2(v.w, hw, lw);
    __half2 a0 = __halves2half2(hx, hy), a1 = __halves2half2(hz, hw);
    __half2 b0 = __halves2half2(lx, ly), b1 = __halves2half2(lz, lw);
    uint2 oh2, ol2;
    oh2.x = *(uint32_t*)&a0; oh2.y = *(uint32_t*)&a1;
    ol2.x = *(uint32_t*)&b0; ol2.y = *(uint32_t*)&b1;
    hi[idx] = oh2; lo[idx] = ol2;
}

// -------------- conv1 weight reorder (hi only) ------------------------------
__global__ void wc1_transform(const float* __restrict__ W, __half* __restrict__ wh)
{
    int idx = blockIdx.x * 256 + threadIdx.x;
    if (idx >= HH * 384) return;
    int o = idx / 384, k = idx % 384;
    int tap = k >> 7, ic = k & 127;
    wh[idx] = __float2half_rn(W[(long long)o * 384 + ic * 3 + tap]);
}

// ---------- V-slice transpose (hi only): vvT[b, h, t] = vv[b, 256+t, h] -----
__global__ void transpose_vslice(const float* __restrict__ vv, __half* __restrict__ th)
{
    __shared__ float tile[32][33];
    const int t0 = blockIdx.x * 32, h0 = blockIdx.y * 32, b = blockIdx.z;
    const int tx = threadIdx.x, ty = threadIdx.y;
    #pragma unroll
    for (int y = ty; y < 32; y += 8)
        tile[y][tx] = vv[((long long)b * SS + 256 + t0 + y) * HH + h0 + tx];
    __syncthreads();
    #pragma unroll
    for (int y = ty; y < 32; y += 8) {
        long long o = ((long long)b * HH + h0 + y) * MID_N + t0 + tx;
        th[o] = __float2half_rn(tile[tx][y]);
    }
}

// -------------------- copy text features hi/lo into att ---------------------
__global__ void copy_text(const float4* __restrict__ src,
                          __half* __restrict__ atth, __half* __restrict__ attl)
{
    int idx = blockIdx.x * 256 + threadIdx.x;
    int b = idx >> 18;
    int r = idx & 262143;
    float4 v = src[idx];
    long long he = ((long long)b * 524288 + 262144 + r) * 4;
    __half hx, lx, hy, ly, hz, lz, hw, lw;
    split2(v.x, hx, lx); split2(v.y, hy, ly);
    split2(v.z, hz, lz); split2(v.w, hw, lw);
    *(__half2*)(atth + he)     = __halves2half2(hx, hy);
    *(__half2*)(atth + he + 2) = __halves2half2(hz, hw);
    *(__half2*)(attl + he)     = __halves2half2(lx, ly);
    *(__half2*)(attl + he + 2) = __halves2half2(lz, lw);
}

// -------- v2t attention, tiled: 8 query rows per block ----------------------
#define V2T_SMEM (40 * 1024 * 4)

__global__ __launch_bounds__(256, 1) void v2t_tile(
    const float* __restrict__ qvis, const float* __restrict__ ktext,
    const float* __restrict__ vtext, const float* __restrict__ visf,
    __half* __restrict__ atth, __half* __restrict__ attl)
{
    extern __shared__ float sm[];
    float* ks = sm;
    float* vs = sm + 20 * 1024;
    const int b = blockIdx.y, i0 = blockIdx.x * 8;
    const int tid = threadIdx.x, w = tid >> 5, lane = tid & 31;
    const int w0 = (i0 < 1016) ? i0 : 1016;

    const float* kb = ktext + (long long)b * SS * HH;
    const float* vb = vtext + (long long)b * SS * HH;
    for (int t = tid; t < 20 * 256; t += 256) {
        int slot = t >> 8, c4 = (t & 255) * 4;
        int row = (slot < 5) ? slot : (w0 + slot - 5);
        row = (row < 1023) ? row : 1023;
        *(float4*)(ks + slot * 1024 + c4) = *(const float4*)(kb + (long long)row * HH + c4);
        *(float4*)(vs + slot * 1024 + c4) = *(const float4*)(vb + (long long)row * HH + c4);
    }
    __syncthreads();

    const int i = i0 + w;
    const int s0 = (i < 1016) ? i : 1016;
    const int nk = (i < 5) ? (i + 8) : 13;

    const float* q = qvis + ((long long)b * SS + i) * HH;
    float qr[32];
    #pragma unroll
    for (int c = 0; c < 32; c++) qr[c] = q[c * 32 + lane];

    int sl[13];
    float p[13];
    #pragma unroll
    for (int j = 0; j < 13; j++) {
        int row = (i < 5) ? j : ((j < 5) ? j : (s0 + j - 5));
        sl[j] = (row < 5) ? row : (5 + row - w0);
        float s = 0.f;
        if (j < nk) {
            const float* kr = ks + sl[j] * 1024;
            #pragma unroll
            for (int c = 0; c < 32; c++) s += qr[c] * kr[c * 32 + lane];
        }
        #pragma unroll
        for (int off = 16; off; off >>= 1) s += __shfl_xor_sync(0xffffffffu, s, off);
        p[j] = s;
    }

    float mx = -3.4e38f;
    #pragma unroll
    for (int j = 0; j < 13; j++) if (j < nk) mx = fmaxf(mx, p[j]);
    float sum = 0.f;
    #pragma unroll
    for (int j = 0; j < 13; j++) {
        float e = (j < nk) ? expf(p[j] - mx) : 0.f;
        p[j] = e; sum += e;
    }
    const float inv = 1.f / sum;
    #pragma unroll
    for (int j = 0; j < 13; j++) p[j] *= inv;

    const float* vf = visf + ((long long)b * SS + i) * HH;
    long long ob = ((long long)b * LL + i) * HH;
    #pragma unroll 4
    for (int r = 0; r < 32; r++) {
        int h = r * 32 + lane;
        float a = vf[h];
        #pragma unroll
        for (int j = 0; j < 13; j++) a += p[j] * vs[sl[j] * 1024 + h];
        __half hh, lh;
        split2(a, hh, lh);
        atth[ob + h] = hh;
        attl[ob + h] = lh;
    }
}

// -------------------- t2v rows 0..4 -----------------------------------------
__global__ __launch_bounds__(256) void t2v_full_rows(
    const float* __restrict__ qtext, const float* __restrict__ kvis,
    const float* __restrict__ vvis, const float* __restrict__ txt,
    __half* __restrict__ atth, __half* __restrict__ attl)
{
    const int r = blockIdx.x, b = blockIdx.y;
    const int tid = threadIdx.x, lane = tid & 31, warp = tid >> 5;
    __shared__ float qs[1024];
    __shared__ float sc[1024];
    __shared__ float red[8];

    const float* q = qtext + ((long long)b * SS + r) * HH;
    for (int h = tid; h < 1024; h += 256) qs[h] = q[h];
    __syncthreads();

    const float* kb = kvis + (long long)b * SS * HH;
    for (int t = warp * 128; t < warp * 128 + 128; t++) {
        const float* kp = kb + (long long)t * HH;
        float p = 0.f;
        #pragma unroll
        for (int c = 0; c < 32; c++) p += qs[c * 32 + lane] * kp[c * 32 + lane];
        #pragma unroll
        for (int off = 16; off; off >>= 1) p += __shfl_xor_sync(0xffffffffu, p, off);
        if (lane == 0) sc[t] = p;
    }
    __syncthreads();

    float m = -3.4e38f;
    for (int t = tid; t < 1024; t += 256) m = fmaxf(m, sc[t]);
    #pragma unroll
    for (int off = 16; off; off >>= 1) m = fmaxf(m, __shfl_xor_sync(0xffffffffu, m, off));
    if (lane == 0) red[warp] = m;
    __syncthreads();
    float mx = red[0];
    #pragma unroll
    for (int k = 1; k < 8; k++) mx = fmaxf(mx, red[k]);

    float s = 0.f;
    for (int t = tid; t < 1024; t += 256) { float e = expf(sc[t] - mx); sc[t] = e; s += e; }
    #pragma unroll
    for (int off = 16; off; off >>= 1) s += __shfl_xor_sync(0xffffffffu, s, off);
    __syncthreads();
    if (lane == 0) red[warp] = s;
    __syncthreads();
    float tot = 0.f;
    #pragma unroll
    for (int k = 0; k < 8; k++) tot += red[k];
    const float inv = 1.f / tot;

    const float* vb = vvis + (long long)b * SS * HH;
    const float* tx = txt + ((long long)b * SS + r) * HH;
    long long ob = ((long long)b * LL + 1024 + r) * HH;
    float accv[4] = {0.f, 0.f, 0.f, 0.f};
    for (int t = 0; t < 1024; t++) {
        float pw = sc[t];
        const float* vr = vb + (long long)t * HH + tid;
        accv[0] += pw * vr[0];
        accv[1] += pw * vr[256];
        accv[2] += pw * vr[512];
        accv[3] += pw * vr[768];
    }
    #pragma unroll
    for (int k = 0; k < 4; k++) {
        int h = tid + k * 256;
        float v = tx[h] + accv[k] * inv;
        __half hh, lh;
        split2(v, hh, lh);
        atth[ob + h] = hh;
        attl[ob + h] = lh;
    }
}

// -------------------- softmax over 512-col rows -> probs hi/lo --------------
__global__ __launch_bounds__(256) void softmax512(const float* __restrict__ S,
                                                  __half* __restrict__ ph,
                                                  __half* __restrict__ pl)
{
    const float* row = S + (long long)blockIdx.x * 512;
    const int tid = threadIdx.x, lane = tid & 31, warp = tid >> 5;
    __shared__ float red[8];
    float a = row[tid], b2 = row[tid + 256];
    float m = fmaxf(a, b2);
    #pragma unroll
    for (int off = 16; off; off >>= 1) m = fmaxf(m, __shfl_xor_sync(0xffffffffu, m, off));
    if (lane == 0) red[warp] = m;
    __syncthreads();
    float mx = red[0];
    #pragma unroll
    for (int k = 1; k < 8; k++) mx = fmaxf(mx, red[k]);
    float e0 = expf(a - mx), e1 = expf(b2 - mx);
    float s = e0 + e1;
    #pragma unroll
    for (int off = 16; off; off >>= 1) s += __shfl_xor_sync(0xffffffffu, s, off);
    __syncthreads();
    if (lane == 0) red[warp] = s;
    __syncthreads();
    float tot = 0.f;
    #pragma unroll
    for (int k = 0; k < 8; k++) tot += red[k];
    float inv = 1.f / tot;
    long long base = (long long)blockIdx.x * 512;
    __half h0, l0, h1, l1;
    split2(e0 * inv, h0, l0);
    split2(e1 * inv, h1, l1);
    ph[base + tid] = h0; pl[base + tid] = l0;
    ph[base + tid + 256] = h1; pl[base + tid + 256] = l1;
}

// -------------------- launcher ----------------------------------------------
extern "C" void kernel_launch(void* const* d_in, const int* in_sizes, int n_in,
                              void* d_out, int out_size)
{
    (void)in_sizes; (void)n_in; (void)out_size;
    const float* vis = (const float*)d_in[0];
    const float* txt = (const float*)d_in[1];
    const float* Wq  = (const float*)d_in[2];  const float* bq  = (const float*)d_in[3];
    const float* Wk  = (const float*)d_in[4];  const float* bk  = (const float*)d_in[5];
    const float* Wv  = (const float*)d_in[6];  const float* bv  = (const float*)d_in[7];
    const float* Wc1 = (const float*)d_in[8];  const float* bc1 = (const float*)d_in[9];
    const float* Wc2 = (const float*)d_in[10]; const float* bc2 = (const float*)d_in[11];
    float* out = (float*)d_out;

    float *qt, *kv, *vv, *qv, *kt, *vt, *attb, *scb;
    __half *vish, *visl, *txth, *txtl, *c1h, *c1l, *wh, *wl;
    __half *qth, *qtl, *kvh, *kvl, *atth, *attl, *wc1h;
    __half *sch, *scl, *vvTh;
    cudaGetSymbolAddress((void**)&qt,  g_q_text);
    cudaGetSymbolAddress((void**)&kv,  g_k_vis);
    cudaGetSymbolAddress((void**)&vv,  g_v_vis);
    cudaGetSymbolAddress((void**)&qv,  g_q_vis);
    cudaGetSymbolAddress((void**)&kt,  g_k_text);
    cudaGetSymbolAddress((void**)&vt,  g_v_text);
    cudaGetSymbolAddress((void**)&attb, g_att);
    cudaGetSymbolAddress((void**)&scb, g_scores);
    cudaGetSymbolAddress((void**)&vish, g_vis_hi);
    cudaGetSymbolAddress((void**)&visl, g_vis_lo);
    cudaGetSymbolAddress((void**)&txth, g_txt_hi);
    cudaGetSymbolAddress((void**)&txtl, g_txt_lo);
    cudaGetSymbolAddress((void**)&c1h, g_c1_hi);
    cudaGetSymbolAddress((void**)&c1l, g_c1_lo);
    cudaGetSymbolAddress((void**)&wh,  g_w_hi);
    cudaGetSymbolAddress((void**)&wl,  g_w_lo);
    cudaGetSymbolAddress((void**)&qth, g_qt_hi);
    cudaGetSymbolAddress((void**)&qtl, g_qt_lo);
    cudaGetSymbolAddress((void**)&kvh, g_kv_hi);
    cudaGetSymbolAddress((void**)&kvl, g_kv_lo);
    cudaGetSymbolAddress((void**)&atth, g_att_hi);
    cudaGetSymbolAddress((void**)&attl, g_att_lo);
    cudaGetSymbolAddress((void**)&wc1h, g_wc1r_hi);
    cudaGetSymbolAddress((void**)&sch, g_sc_hi);
    cudaGetSymbolAddress((void**)&scl, g_sc_lo);
    cudaGetSymbolAddress((void**)&vvTh, g_vvT_hi);

    cudaFuncSetAttribute((const void*)&mma_qkv,
                         cudaFuncAttributeMaxDynamicSharedMemorySize, MG_SMEM);
    cudaFuncSetAttribute((const void*)&mma_gemm<false, false, true,  false, true>,
                         cudaFuncAttributeMaxDynamicSharedMemorySize, MG_SMEM);
    cudaFuncSetAttribute((const void*)&mma_gemm<false, true,  true,  true,  false>,
                         cudaFuncAttributeMaxDynamicSharedMemorySize, MG_SMEM);
    cudaFuncSetAttribute((const void*)&mma_gemm<true,  false, false, false, false>,
                         cudaFuncAttributeMaxDynamicSharedMemorySize, MG_SMEM);
    cudaFuncSetAttribute((const void*)&conv1_mma,
                         cudaFuncAttributeMaxDynamicSharedMemorySize, CV_SMEM);
    cudaFuncSetAttribute((const void*)&v2t_tile,
                         cudaFuncAttributeMaxDynamicSharedMemorySize, V2T_SMEM);

    const long long SH = (long long)SS * HH;
    const long long LH = (long long)LL * HH;
    const long long SCs = (long long)MID_M * MID_N;

    // 0) splits + weight transforms (fused)
    int n4in = BB * SS * HH / 4;
    split_fp16_2<<<(2 * n4in + 255) / 256, 256>>>(
        (const float4*)vis, (uint2*)vish, (uint2*)visl,
        (const float4*)txt, (uint2*)txth, (uint2*)txtl, n4in);
    split_w4<<<(WW + 255) / 256, 256>>>(
        (const float4*)Wq, (const float4*)Wk, (const float4*)Wv, (const float4*)Wc2,
        (uint2*)wh, (uint2*)wl);
    wc1_transform<<<(HH * 384 + 255) / 256, 256>>>(Wc1, wc1h);

    // 1) fused QKV projections (q,k 3-term; v 2-term)
    dim3 gq(24, 64, 1);
    mma_qkv<<<gq, 256, MG_SMEM>>>(txth, txtl, wh, wl, bq, bk, bv,
                                  qt, kt, vt, qth, qtl, 0);
    mma_qkv<<<gq, 256, MG_SMEM>>>(vish, visl, wh, wl, bq, bk, bv,
                                  qv, kv, vv, kvh, kvl, 1);

    // 2) text residual rows -> att hi/lo
    copy_text<<<8192, 256>>>((const float4*)txt, atth, attl);

    // 3) v2t sparse attention (tiled)
    v2t_tile<<<dim3(SS / 8, BB), 256, V2T_SMEM>>>(qv, kt, vt, vis, atth, attl);

    // 4) t2v rows 0..4
    t2v_full_rows<<<dim3(5, BB), 256>>>(qt, kv, vv, txt, atth, attl);

    // 5) t2v mid scores (3-term: precision critical)
    mma_gemm<false, false, true, false, true><<<dim3(MID_N / 128, 3, BB), 256, MG_SMEM>>>(
        qth + 341 * HH, qtl + 341 * HH, SH,
        kvh + 256 * HH, kvl + 256 * HH, SH,
        scb, SCs, MID_N, nullptr, nullptr, nullptr, nullptr, 0, 0, MID_M, HH);

    // 6) softmax -> probs hi/lo
    softmax512<<<BB * MID_M, 256>>>(scb, sch, scl);

    // 6b) transpose V slice (hi only)
    transpose_vslice<<<dim3(MID_N / 32, HH / 32, BB), dim3(32, 8)>>>(vv, vvTh);

    // 7) AV (2-term: probs split, V hi) + text residual -> att rows hi/lo
    mma_gemm<false, true, true, true, false><<<dim3(HH / 128, 3, BB), 256, MG_SMEM>>>(
        sch, scl, SCs,
        vvTh, vvTh, (long long)HH * MID_N,
        attb + (long long)(1024 + 341) * HH, LH, HH,
        nullptr,
        atth + (long long)(1024 + 341) * HH, attl + (long long)(1024 + 341) * HH,
        txt + 341 * HH, SH, HH,
        MID_M, MID_N);

    // 8) conv1 (2-term) + GELU -> c1 hi/lo
    conv1_mma<<<dim3(LL / 128, 8, BB), 256, CV_SMEM>>>(atth, attl, wc1h, bc1, c1h, c1l);

    // 9) conv2 (2-term: c1 split, Wc2 hi) -> output
    mma_gemm<true, false, false, false, false><<<dim3(HH / 128, BB * LL / 128, 1), 256, MG_SMEM>>>(
        c1h, c1l, 0, wh + 3 * WW, wh + 3 * WW, 0,
        out, 0, HH, bc2, nullptr, nullptr, nullptr, 0, 0, BB * LL, HH);
}

// round 8
// speedup vs baseline: 2.9384x; 1.0163x over previous
#include <cuda_runtime.h>
#include <cuda_fp16.h>
#include <math.h>
#include <stdint.h>

#define BB 8
#define SS 1024
#define HH 1024
#define LL 2048
#define MID_M 341
#define MID_N 512
#define WW (HH*HH)

// -------------------- scratch (device globals) ------------------------------
__device__ __align__(128) float g_q_text[BB*SS*HH];
__device__ __align__(128) float g_k_vis [BB*SS*HH];
__device__ __align__(128) float g_v_vis [BB*SS*HH];
__device__ __align__(128) float g_q_vis [BB*SS*HH];
__device__ __align__(128) float g_k_text[BB*SS*HH];
__device__ __align__(128) float g_v_text[BB*SS*HH];
__device__ __align__(128) float g_att   [BB*LL*HH];
__device__ __align__(128) float g_scores[BB*MID_M*MID_N];
__device__ __align__(128) __half g_vis_hi[BB*SS*HH];
__device__ __align__(128) __half g_vis_lo[BB*SS*HH];
__device__ __align__(128) __half g_txt_hi[BB*SS*HH];
__device__ __align__(128) __half g_txt_lo[BB*SS*HH];
__device__ __align__(128) __half g_c1_hi [BB*LL*HH];
__device__ __align__(128) __half g_c1_lo [BB*LL*HH];
__device__ __align__(128) __half g_w_hi  [4*WW];      // Wq, Wk, Wv, Wc2
__device__ __align__(128) __half g_w_lo  [4*WW];
__device__ __align__(128) __half g_qt_hi [BB*SS*HH];
__device__ __align__(128) __half g_qt_lo [BB*SS*HH];
__device__ __align__(128) __half g_kv_hi [BB*SS*HH];
__device__ __align__(128) __half g_kv_lo [BB*SS*HH];
__device__ __align__(128) __half g_att_hi[BB*LL*HH];
__device__ __align__(128) __half g_att_lo[BB*LL*HH];
__device__ __align__(128) __half g_wc1r_hi[HH*384];
__device__ __align__(128) __half g_sc_hi [BB*MID_M*MID_N];
__device__ __align__(128) __half g_sc_lo [BB*MID_M*MID_N];
__device__ __align__(128) __half g_vvT_hi[BB*HH*MID_N];

// ===================== low-level helpers ====================================
__device__ __forceinline__ uint32_t smem_to_u32(const void* p) {
    uint32_t a;
    asm("{ .reg .u64 t; cvta.to.shared.u64 t, %1; cvt.u32.u64 %0, t; }" : "=r"(a) : "l"(p));
    return a;
}
__device__ __forceinline__ void cp_async16(uint32_t saddr, const void* gptr) {
    asm volatile("cp.async.cg.shared.global [%0], [%1], 16;" :: "r"(saddr), "l"(gptr));
}
#define CP_COMMIT() asm volatile("cp.async.commit_group;" ::: "memory")
#define CP_WAIT1()  asm volatile("cp.async.wait_group 1;" ::: "memory")
#define CP_WAIT0()  asm volatile("cp.async.wait_group 0;" ::: "memory")

__device__ __forceinline__ void ldm_x4(uint32_t& r0, uint32_t& r1, uint32_t& r2, uint32_t& r3,
                                       uint32_t addr) {
    asm volatile("ldmatrix.sync.aligned.m8n8.x4.shared.b16 {%0,%1,%2,%3}, [%4];"
                 : "=r"(r0), "=r"(r1), "=r"(r2), "=r"(r3) : "r"(addr));
}
__device__ __forceinline__ void ldm_x2(uint32_t& r0, uint32_t& r1, uint32_t addr) {
    asm volatile("ldmatrix.sync.aligned.m8n8.x2.shared.b16 {%0,%1}, [%2];"
                 : "=r"(r0), "=r"(r1) : "r"(addr));
}
__device__ __forceinline__ void mma16816(float* c, const uint32_t* a, const uint32_t* b) {
    asm volatile("mma.sync.aligned.m16n8k16.row.col.f32.f16.f16.f32 "
                 "{%0,%1,%2,%3}, {%4,%5,%6,%7}, {%8,%9}, {%0,%1,%2,%3};"
                 : "+f"(c[0]), "+f"(c[1]), "+f"(c[2]), "+f"(c[3])
                 : "r"(a[0]), "r"(a[1]), "r"(a[2]), "r"(a[3]), "r"(b[0]), "r"(b[1]));
}
__device__ __forceinline__ void split2(float v, __half& h, __half& l) {
    h = __float2half_rn(v);
    l = __float2half_rn(v - __half2float(h));
}

#define MG_SMEM (3 * 65536)

// =================== generic tensor-core GEMM ===============================
// C[M,N] = A[M,K] @ B[N,K]^T (+bias)(+residual). A hi/lo split.
// TERM3: also split B (3 mma terms); else B hi only (2 terms).
// ks-pipelined fragment loads (double buffered).
template<bool BIAS, bool HALFOUT, bool GUARD, bool RESID, bool TERM3>
__global__ __launch_bounds__(256, 1)
void mma_gemm(const __half* __restrict__ Ahi, const __half* __restrict__ Alo, long long sA,
              const __half* __restrict__ Bhi, const __half* __restrict__ Blo, long long sB,
              float* __restrict__ C, long long sC, int ldc,
              const float* __restrict__ bias,
              __half* __restrict__ Chi, __half* __restrict__ Clo,
              const float* __restrict__ Rm, long long sR, int ldr,
              int M, int K)
{
    extern __shared__ char smem[];
    const uint32_t sbase = smem_to_u32(smem);
    const int tid = threadIdx.x;
    const int wid = tid >> 5, lane = tid & 31;
    const int m0 = blockIdx.y * 128, n0 = blockIdx.x * 128;
    const int m_w = (wid & 1) * 64;
    const int n_w = (wid >> 1) * 32;
    const int z = blockIdx.z;
    Ahi += z * sA; Alo += z * sA;
    Bhi += z * sB; if (TERM3) Blo += z * sB;
    C   += z * sC;
    if (HALFOUT) { Chi += z * sC; Clo += z * sC; }
    if (RESID)   { Rm  += z * sR; }

    const int crow = tid >> 3;
    const int cc16 = tid & 7;
    const int nk = K >> 6;

    auto issue_stage = [&](int kc, int s) {
        const int k0 = kc * 64;
        const uint32_t st = sbase + (uint32_t)s * 65536u;
        #pragma unroll
        for (int p = 0; p < 4; p++) {
            int row = p * 32 + crow;
            uint32_t soff = (uint32_t)(row * 128) + (uint32_t)((cc16 * 16) ^ ((row & 7) << 4));
            int gm = m0 + row;
            if (GUARD) gm = (gm < M) ? gm : (M - 1);
            long long ga = (long long)gm * K + k0 + cc16 * 8;
            long long gb = (long long)(n0 + row) * K + k0 + cc16 * 8;
            cp_async16(st + soff,          Ahi + ga);
            cp_async16(st + 16384 + soff,  Alo + ga);
            cp_async16(st + 32768 + soff,  Bhi + gb);
            if (TERM3) cp_async16(st + 49152 + soff, Blo + gb);
        }
    };

    uint32_t aRow[4], aXor[4];
    #pragma unroll
    for (int mt = 0; mt < 4; mt++) {
        int r = m_w + 16 * mt + (lane & 15);
        aRow[mt] = (uint32_t)(r * 128);
        aXor[mt] = (uint32_t)((r & 7) << 4);
    }
    const uint32_t aCol = (uint32_t)((lane >> 4) * 16);
    uint32_t bRow[4], bXor[4];
    #pragma unroll
    for (int nt = 0; nt < 4; nt++) {
        int r = n_w + 8 * nt + (lane & 7);
        bRow[nt] = (uint32_t)(r * 128);
        bXor[nt] = (uint32_t)((r & 7) << 4);
    }
    const uint32_t bCol = (uint32_t)(((lane >> 3) & 1) * 16);

    float acc[4][4][4];
    #pragma unroll
    for (int mt = 0; mt < 4; mt++)
        #pragma unroll
        for (int nt = 0; nt < 4; nt++)
            #pragma unroll
            for (int q = 0; q < 4; q++) acc[mt][nt][q] = 0.f;

    uint32_t ah[2][4][4], al[2][4][4], bh[2][4][2], bl[2][4][2];

    auto load_frags = [&](int s, int ks, int pb) {
        const uint32_t st = sbase + (uint32_t)s * 65536u;
        const uint32_t kb = (uint32_t)(ks * 32);
        #pragma unroll
        for (int mt = 0; mt < 4; mt++) {
            uint32_t ad = st + aRow[mt] + ((kb + aCol) ^ aXor[mt]);
            ldm_x4(ah[pb][mt][0], ah[pb][mt][1], ah[pb][mt][2], ah[pb][mt][3], ad);
            ldm_x4(al[pb][mt][0], al[pb][mt][1], al[pb][mt][2], al[pb][mt][3], ad + 16384);
        }
        #pragma unroll
        for (int nt = 0; nt < 4; nt++) {
            uint32_t bd = st + 32768 + bRow[nt] + ((kb + bCol) ^ bXor[nt]);
            ldm_x2(bh[pb][nt][0], bh[pb][nt][1], bd);
            if (TERM3) ldm_x2(bl[pb][nt][0], bl[pb][nt][1], bd + 16384);
        }
    };
    auto do_mma = [&](int pb) {
        #pragma unroll
        for (int mt = 0; mt < 4; mt++)
            #pragma unroll
            for (int nt = 0; nt < 4; nt++) {
                mma16816(acc[mt][nt], ah[pb][mt], bh[pb][nt]);
                if (TERM3) mma16816(acc[mt][nt], ah[pb][mt], bl[pb][nt]);
                mma16816(acc[mt][nt], al[pb][mt], bh[pb][nt]);
            }
    };

    issue_stage(0, 0); CP_COMMIT();
    issue_stage(1, 1); CP_COMMIT();
    for (int kc = 0; kc < nk; kc++) {
        if (kc + 1 < nk) { CP_WAIT1(); } else { CP_WAIT0(); }
        __syncthreads();
        if (kc + 2 < nk) { issue_stage(kc + 2, (kc + 2) % 3); CP_COMMIT(); }
        const int s = kc % 3;
        load_frags(s, 0, 0);
        #pragma unroll
        for (int ks = 0; ks < 4; ks++) {
            if (ks < 3) load_frags(s, ks + 1, (ks + 1) & 1);
            do_mma(ks & 1);
        }
    }

    const int rq = lane >> 2, cq = (lane & 3) * 2;
    #pragma unroll
    for (int mt = 0; mt < 4; mt++) {
        int row0 = m0 + m_w + 16 * mt + rq;
        #pragma unroll
        for (int nt = 0; nt < 4; nt++) {
            int col = n0 + n_w + 8 * nt + cq;
            float b0 = 0.f, b1 = 0.f;
            if (BIAS) { b0 = bias[col]; b1 = bias[col + 1]; }
            #pragma unroll
            for (int rr = 0; rr < 2; rr++) {
                int row = row0 + rr * 8;
                if (GUARD && row >= M) continue;
                float x0 = acc[mt][nt][rr * 2 + 0] + b0;
                float x1 = acc[mt][nt][rr * 2 + 1] + b1;
                if (RESID) {
                    const float* Rp = Rm + (long long)row * ldr + col;
                    x0 += Rp[0]; x1 += Rp[1];
                }
                long long idx = (long long)row * ldc + col;
                *(float2*)(C + idx) = make_float2(x0, x1);
                if (HALFOUT) {
                    __half h0, l0h, h1, l1h;
                    split2(x0, h0, l0h); split2(x1, h1, l1h);
                    *(__half2*)(Chi + idx) = __halves2half2(h0, h1);
                    *(__half2*)(Clo + idx) = __halves2half2(l0h, l1h);
                }
            }
        }
    }
}

// ============ fused QKV projection for BOTH inputs ==========================
// grid = (24, 64, 2). z=0: text -> (qt,kt,vt), hi/lo on seg0 (q_text).
//                     z=1: vis  -> (qv,kv,vv), hi/lo on seg1 (k_vis).
// seg = n-tile/1024; seg 0,1 (q,k) 3-term; seg 2 (v) 2-term.
__global__ __launch_bounds__(256, 1)
void mma_qkv(const __half* __restrict__ A0h, const __half* __restrict__ A0l,
             const __half* __restrict__ A1h, const __half* __restrict__ A1l,
             const __half* __restrict__ Bhi, const __half* __restrict__ Blo,
             const float* __restrict__ b0p, const float* __restrict__ b1p,
             const float* __restrict__ b2p,
             float* __restrict__ Cq0, float* __restrict__ Ck0, float* __restrict__ Cv0,
             float* __restrict__ Cq1, float* __restrict__ Ck1, float* __restrict__ Cv1,
             __half* __restrict__ C0hi, __half* __restrict__ C0lo,
             __half* __restrict__ C1hi, __half* __restrict__ C1lo)
{
    extern __shared__ char smem[];
    const uint32_t sbase = smem_to_u32(smem);
    const int tid = threadIdx.x;
    const int wid = tid >> 5, lane = tid & 31;
    const int m0 = blockIdx.y * 128, n0 = blockIdx.x * 128;
    const int m_w = (wid & 1) * 64;
    const int n_w = (wid >> 1) * 32;
    const int z = blockIdx.z;
    const int seg = n0 >> 10;
    const int ncol0 = n0 & 1023;
    const bool t3 = (seg < 2);
    const __half* Ahi = z ? A1h : A0h;
    const __half* Alo = z ? A1l : A0l;
    float* C = z ? ((seg == 0) ? Cq1 : (seg == 1) ? Ck1 : Cv1)
                 : ((seg == 0) ? Cq0 : (seg == 1) ? Ck0 : Cv0);
    const float* bias = (seg == 0) ? b0p : (seg == 1) ? b1p : b2p;
    const bool doHalf = (seg == (z ? 1 : 0));
    __half* Chi = z ? C1hi : C0hi;
    __half* Clo = z ? C1lo : C0lo;

    const int crow = tid >> 3;
    const int cc16 = tid & 7;

    auto issue_stage = [&](int kc, int s) {
        const int k0 = kc * 64;
        const uint32_t st = sbase + (uint32_t)s * 65536u;
        #pragma unroll
        for (int p = 0; p < 4; p++) {
            int row = p * 32 + crow;
            uint32_t soff = (uint32_t)(row * 128) + (uint32_t)((cc16 * 16) ^ ((row & 7) << 4));
            long long ga = (long long)(m0 + row) * 1024 + k0 + cc16 * 8;
            long long gb = (long long)(n0 + row) * 1024 + k0 + cc16 * 8;
            cp_async16(st + soff,          Ahi + ga);
            cp_async16(st + 16384 + soff,  Alo + ga);
            cp_async16(st + 32768 + soff,  Bhi + gb);
            if (t3) cp_async16(st + 49152 + soff, Blo + gb);
        }
    };

    uint32_t aRow[4], aXor[4];
    #pragma unroll
    for (int mt = 0; mt < 4; mt++) {
        int r = m_w + 16 * mt + (lane & 15);
        aRow[mt] = (uint32_t)(r * 128);
        aXor[mt] = (uint32_t)((r & 7) << 4);
    }
    const uint32_t aCol = (uint32_t)((lane >> 4) * 16);
    uint32_t bRow[4], bXor[4];
    #pragma unroll
    for (int nt = 0; nt < 4; nt++) {
        int r = n_w + 8 * nt + (lane & 7);
        bRow[nt] = (uint32_t)(r * 128);
        bXor[nt] = (uint32_t)((r & 7) << 4);
    }
    const uint32_t bCol = (uint32_t)(((lane >> 3) & 1) * 16);

    float acc[4][4][4];
    #pragma unroll
    for (int mt = 0; mt < 4; mt++)
        #pragma unroll
        for (int nt = 0; nt < 4; nt++)
            #pragma unroll
            for (int q = 0; q < 4; q++) acc[mt][nt][q] = 0.f;

    uint32_t ah[2][4][4], al[2][4][4], bh[2][4][2], bl[2][4][2];

    auto load_frags = [&](int s, int ks, int pb) {
        const uint32_t st = sbase + (uint32_t)s * 65536u;
        const uint32_t kb = (uint32_t)(ks * 32);
        #pragma unroll
        for (int mt = 0; mt < 4; mt++) {
            uint32_t ad = st + aRow[mt] + ((kb + aCol) ^ aXor[mt]);
            ldm_x4(ah[pb][mt][0], ah[pb][mt][1], ah[pb][mt][2], ah[pb][mt][3], ad);
            ldm_x4(al[pb][mt][0], al[pb][mt][1], al[pb][mt][2], al[pb][mt][3], ad + 16384);
        }
        #pragma unroll
        for (int nt = 0; nt < 4; nt++) {
            uint32_t bd = st + 32768 + bRow[nt] + ((kb + bCol) ^ bXor[nt]);
            ldm_x2(bh[pb][nt][0], bh[pb][nt][1], bd);
            if (t3) ldm_x2(bl[pb][nt][0], bl[pb][nt][1], bd + 16384);
        }
    };
    auto do_mma = [&](int pb) {
        #pragma unroll
        for (int mt = 0; mt < 4; mt++)
            #pragma unroll
            for (int nt = 0; nt < 4; nt++) {
                mma16816(acc[mt][nt], ah[pb][mt], bh[pb][nt]);
                if (t3) mma16816(acc[mt][nt], ah[pb][mt], bl[pb][nt]);
                mma16816(acc[mt][nt], al[pb][mt], bh[pb][nt]);
            }
    };

    issue_stage(0, 0); CP_COMMIT();
    issue_stage(1, 1); CP_COMMIT();
    for (int kc = 0; kc < 16; kc++) {
        if (kc + 1 < 16) { CP_WAIT1(); } else { CP_WAIT0(); }
        __syncthreads();
        if (kc + 2 < 16) { issue_stage(kc + 2, (kc + 2) % 3); CP_COMMIT(); }
        const int s = kc % 3;
        load_frags(s, 0, 0);
        #pragma unroll
        for (int ks = 0; ks < 4; ks++) {
            if (ks < 3) load_frags(s, ks + 1, (ks + 1) & 1);
            do_mma(ks & 1);
        }
    }

    const int rq = lane >> 2, cq = (lane & 3) * 2;
    #pragma unroll
    for (int mt = 0; mt < 4; mt++) {
        int row0 = m0 + m_w + 16 * mt + rq;
        #pragma unroll
        for (int nt = 0; nt < 4; nt++) {
            int col = ncol0 + n_w + 8 * nt + cq;
            float b0 = bias[col], b1 = bias[col + 1];
            #pragma unroll
            for (int rr = 0; rr < 2; rr++) {
                int row = row0 + rr * 8;
                float x0 = acc[mt][nt][rr * 2 + 0] + b0;
                float x1 = acc[mt][nt][rr * 2 + 1] + b1;
                long long idx = (long long)row * 1024 + col;
                *(float2*)(C + idx) = make_float2(x0, x1);
                if (doHalf) {
                    __half h0, l0h, h1, l1h;
                    split2(x0, h0, l0h); split2(x1, h1, l1h);
                    *(__half2*)(Chi + idx) = __halves2half2(h0, h1);
                    *(__half2*)(Clo + idx) = __halves2half2(l0h, l1h);
                }
            }
        }
    }
}

// =================== conv1 (grouped k=3), single-shot smem ==================
// x tile (130 rows x 256B, hi+lo) + all 3 weight taps (3 x 32KB) resident.
#define CV_SMEM (2*33280 + 3*32768)

__global__ __launch_bounds__(256, 1)
void conv1_mma(const __half* __restrict__ xh, const __half* __restrict__ xl,
               const __half* __restrict__ wh,
               const float* __restrict__ bias,
               __half* __restrict__ oh, __half* __restrict__ ol)
{
    extern __shared__ char smem[];
    const uint32_t sb = smem_to_u32(smem);
    const int tid = threadIdx.x, wid = tid >> 5, lane = tid & 31;
    const int l0 = blockIdx.x * 128, g = blockIdx.y, b = blockIdx.z;
    const int m_w = (wid & 1) * 64, n_w = (wid >> 1) * 32;
    const uint32_t XH = sb, WH = sb + 66560u;

    for (int t = tid; t < 2080; t += 256) {
        int r = t >> 4, c16 = t & 15;
        int l = l0 - 1 + r;
        uint32_t d = (uint32_t)(r * 256) + (uint32_t)((c16 * 16) ^ ((r & 7) << 4));
        uint4 vh = make_uint4(0u, 0u, 0u, 0u), vl = vh;
        if (l >= 0 && l < LL) {
            long long gidx = ((long long)b * LL + l) * HH + g * 128 + c16 * 8;
            vh = *(const uint4*)(xh + gidx);
            vl = *(const uint4*)(xl + gidx);
        }
        *(uint4*)(smem + d)         = vh;
        *(uint4*)(smem + 33280 + d) = vl;
    }
    // all 3 weight taps: 3 * 2048 16B-chunks
    for (int t = tid; t < 3 * 2048; t += 256) {
        int tap = t >> 11, u = t & 2047;
        int r = u >> 4, c16 = u & 15;
        uint32_t d = (uint32_t)(r * 256) + (uint32_t)((c16 * 16) ^ ((r & 7) << 4));
        long long widx = (long long)(g * 128 + r) * 384 + tap * 128 + c16 * 8;
        *(uint4*)(smem + 66560 + tap * 32768 + d) = *(const uint4*)(wh + widx);
    }
    __syncthreads();

    float acc[4][4][4];
    #pragma unroll
    for (int mt = 0; mt < 4; mt++)
        #pragma unroll
        for (int nt = 0; nt < 4; nt++)
            #pragma unroll
            for (int q = 0; q < 4; q++) acc[mt][nt][q] = 0.f;

    const uint32_t aCol = (uint32_t)((lane >> 4) * 16);
    const uint32_t bCol = (uint32_t)(((lane >> 3) & 1) * 16);

    for (int tap = 0; tap < 3; tap++) {
        #pragma unroll
        for (int ks = 0; ks < 8; ks++) {
            const uint32_t kb = (uint32_t)(ks * 32);
            uint32_t ah[4][4], al[4][4], bh[4][2];
            #pragma unroll
            for (int mt = 0; mt < 4; mt++) {
                int ar = m_w + 16 * mt + (lane & 15) + tap;
                uint32_t ad = XH + (uint32_t)(ar * 256) + ((kb + aCol) ^ (uint32_t)((ar & 7) << 4));
                ldm_x4(ah[mt][0], ah[mt][1], ah[mt][2], ah[mt][3], ad);
                ldm_x4(al[mt][0], al[mt][1], al[mt][2], al[mt][3], ad + 33280u);
            }
            #pragma unroll
            for (int nt = 0; nt < 4; nt++) {
                int br = n_w + 8 * nt + (lane & 7);
                uint32_t bd = WH + (uint32_t)(tap * 32768) + (uint32_t)(br * 256)
                            + ((kb + bCol) ^ (uint32_t)((br & 7) << 4));
                ldm_x2(bh[nt][0], bh[nt][1], bd);
            }
            #pragma unroll
            for (int mt = 0; mt < 4; mt++)
                #pragma unroll
                for (int nt = 0; nt < 4; nt++) {
                    mma16816(acc[mt][nt], ah[mt], bh[nt]);
                    mma16816(acc[mt][nt], al[mt], bh[nt]);
                }
        }
    }

    const int rq = lane >> 2, cq = (lane & 3) * 2;
    #pragma unroll
    for (int mt = 0; mt < 4; mt++) {
        int row0 = l0 + m_w + 16 * mt + rq;
        #pragma unroll
        for (int nt = 0; nt < 4; nt++) {
            int ch = g * 128 + n_w + 8 * nt + cq;
            float b0 = bias[ch], b1 = bias[ch + 1];
            #pragma unroll
            for (int rr = 0; rr < 2; rr++) {
                int row = row0 + rr * 8;
                float x0 = acc[mt][nt][rr * 2 + 0] + b0;
                float x1 = acc[mt][nt][rr * 2 + 1] + b1;
                float y0 = 0.5f * x0 * (1.0f + erff(x0 * 0.70710678118654752f));
                float y1 = 0.5f * x1 * (1.0f + erff(x1 * 0.70710678118654752f));
                __half h0, l0h, h1, l1h;
                split2(y0, h0, l0h); split2(y1, h1, l1h);
                long long idx = ((long long)b * LL + row) * HH + ch;
                *(__half2*)(oh + idx) = __halves2half2(h0, h1);
                *(__half2*)(ol + idx) = __halves2half2(l0h, l1h);
            }
        }
    }
}

// -------------------- fused fp32 -> (hi, lo) splits -------------------------
__global__ void split_fp16_2(const float4* __restrict__ x0, uint2* __restrict__ h0,
                             uint2* __restrict__ l0, const float4* __restrict__ x1,
                             uint2* __restrict__ h1, uint2* __restrict__ l1, int n4)
{
    int i = blockIdx.x * 256 + threadIdx.x;
    const float4* x; uint2 *hp, *lp;
    if (i >= n4) { i -= n4; if (i >= n4) return; x = x1; hp = h1; lp = l1; }
    else { x = x0; hp = h0; lp = l0; }
    float4 v = x[i];
    __half hx, lx, hy, ly, hz, lz, hw, lw;
    split2(v.x, hx, lx); split2(v.y, hy, ly);
    split2(v.z, hz, lz); split2(v.w, hw, lw);
    __half2 a0 = __halves2half2(hx, hy), a1 = __halves2half2(hz, hw);
    __half2 b0 = __halves2half2(lx, ly), b1 = __halves2half2(lz, lw);
    uint2 oh2, ol2;
    oh2.x = *(uint32_t*)&a0; oh2.y = *(uint32_t*)&a1;
    ol2.x = *(uint32_t*)&b0; ol2.y = *(uint32_t*)&b1;
    hp[i] = oh2; lp[i] = ol2;
}

__global__ void split_w4(const float4* __restrict__ wq, const float4* __restrict__ wk,
                         const float4* __restrict__ wv, const float4* __restrict__ wc2,
                         uint2* __restrict__ hi, uint2* __restrict__ lo)
{
    int idx = blockIdx.x * 256 + threadIdx.x;
    int seg = idx >> 18, i = idx & 262143;
    const float4* src = (seg == 0) ? wq : (seg == 1) ? wk : (seg == 2) ? wv : wc2;
    float4 v = src[i];
    __half hx, lx, hy, ly, hz, lz, hw, lw;
    split2(v.x, hx, lx); split2(v.y, hy, ly);
    split2(v.z, hz, lz); split2(v.w, hw, lw);
    __half2 a0 = __halves2half2(hx, hy), a1 = __halves2half2(hz, hw);
    __half2 b0 = __halves2half2(lx, ly), b1 = __halves2half2(lz, lw);
    uint2 oh2, ol2;
    oh2.x = *(uint32_t*)&a0; oh2.y = *(uint32_t*)&a1;
    ol2.x = *(uint32_t*)&b0; ol2.y = *(uint32_t*)&b1;
    hi[idx] = oh2; lo[idx] = ol2;
}

__global__ void wc1_transform(const float* __restrict__ W, __half* __restrict__ wh)
{
    int idx = blockIdx.x * 256 + threadIdx.x;
    if (idx >= HH * 384) return;
    int o = idx / 384, k = idx % 384;
    int tap = k >> 7, ic = k & 127;
    wh[idx] = __float2half_rn(W[(long long)o * 384 + ic * 3 + tap]);
}

__global__ void transpose_vslice(const float* __restrict__ vv, __half* __restrict__ th)
{
    __shared__ float tile[32][33];
    const int t0 = blockIdx.x * 32, h0 = blockIdx.y * 32, b = blockIdx.z;
    const int tx = threadIdx.x, ty = threadIdx.y;
    #pragma unroll
    for (int y = ty; y < 32; y += 8)
        tile[y][tx] = vv[((long long)b * SS + 256 + t0 + y) * HH + h0 + tx];
    __syncthreads();
    #pragma unroll
    for (int y = ty; y < 32; y += 8) {
        long long o = ((long long)b * HH + h0 + y) * MID_N + t0 + tx;
        th[o] = __float2half_rn(tile[tx][y]);
    }
}

__global__ void copy_text(const float4* __restrict__ src,
                          __half* __restrict__ atth, __half* __restrict__ attl)
{
    int idx = blockIdx.x * 256 + threadIdx.x;
    int b = idx >> 18;
    int r = idx & 262143;
    float4 v = src[idx];
    long long he = ((long long)b * 524288 + 262144 + r) * 4;
    __half hx, lx, hy, ly, hz, lz, hw, lw;
    split2(v.x, hx, lx); split2(v.y, hy, ly);
    split2(v.z, hz, lz); split2(v.w, hw, lw);
    *(__half2*)(atth + he)     = __halves2half2(hx, hy);
    *(__half2*)(atth + he + 2) = __halves2half2(hz, hw);
    *(__half2*)(attl + he)     = __halves2half2(lx, ly);
    *(__half2*)(attl + he + 2) = __halves2half2(lz, lw);
}

// -------- v2t attention, tiled: 8 query rows per block ----------------------
#define V2T_SMEM (40 * 1024 * 4)

__global__ __launch_bounds__(256, 1) void v2t_tile(
    const float* __restrict__ qvis, const float* __restrict__ ktext,
    const float* __restrict__ vtext, const float* __restrict__ visf,
    __half* __restrict__ atth, __half* __restrict__ attl)
{
    extern __shared__ float sm[];
    float* ks = sm;
    float* vs = sm + 20 * 1024;
    const int b = blockIdx.y, i0 = blockIdx.x * 8;
    const int tid = threadIdx.x, w = tid >> 5, lane = tid & 31;
    const int w0 = (i0 < 1016) ? i0 : 1016;

    const float* kb = ktext + (long long)b * SS * HH;
    const float* vb = vtext + (long long)b * SS * HH;
    for (int t = tid; t < 20 * 256; t += 256) {
        int slot = t >> 8, c4 = (t & 255) * 4;
        int row = (slot < 5) ? slot : (w0 + slot - 5);
        row = (row < 1023) ? row : 1023;
        *(float4*)(ks + slot * 1024 + c4) = *(const float4*)(kb + (long long)row * HH + c4);
        *(float4*)(vs + slot * 1024 + c4) = *(const float4*)(vb + (long long)row * HH + c4);
    }
    __syncthreads();

    const int i = i0 + w;
    const int s0 = (i < 1016) ? i : 1016;
    const int nk = (i < 5) ? (i + 8) : 13;

    const float* q = qvis + ((long long)b * SS + i) * HH;
    float qr[32];
    #pragma unroll
    for (int c = 0; c < 32; c++) qr[c] = q[c * 32 + lane];

    int sl[13];
    float p[13];
    #pragma unroll
    for (int j = 0; j < 13; j++) {
        int row = (i < 5) ? j : ((j < 5) ? j : (s0 + j - 5));
        sl[j] = (row < 5) ? row : (5 + row - w0);
        float s = 0.f;
        if (j < nk) {
            const float* kr = ks + sl[j] * 1024;
            #pragma unroll
            for (int c = 0; c < 32; c++) s += qr[c] * kr[c * 32 + lane];
        }
        #pragma unroll
        for (int off = 16; off; off >>= 1) s += __shfl_xor_sync(0xffffffffu, s, off);
        p[j] = s;
    }

    float mx = -3.4e38f;
    #pragma unroll
    for (int j = 0; j < 13; j++) if (j < nk) mx = fmaxf(mx, p[j]);
    float sum = 0.f;
    #pragma unroll
    for (int j = 0; j < 13; j++) {
        float e = (j < nk) ? expf(p[j] - mx) : 0.f;
        p[j] = e; sum += e;
    }
    const float inv = 1.f / sum;
    #pragma unroll
    for (int j = 0; j < 13; j++) p[j] *= inv;

    const float* vf = visf + ((long long)b * SS + i) * HH;
    long long ob = ((long long)b * LL + i) * HH;
    #pragma unroll 4
    for (int r = 0; r < 32; r++) {
        int h = r * 32 + lane;
        float a = vf[h];
        #pragma unroll
        for (int j = 0; j < 13; j++) a += p[j] * vs[sl[j] * 1024 + h];
        __half hh, lh;
        split2(a, hh, lh);
        atth[ob + h] = hh;
        attl[ob + h] = lh;
    }
}

// -------------------- t2v rows 0..4 -----------------------------------------
__global__ __launch_bounds__(256) void t2v_full_rows(
    const float* __restrict__ qtext, const float* __restrict__ kvis,
    const float* __restrict__ vvis, const float* __restrict__ txt,
    __half* __restrict__ atth, __half* __restrict__ attl)
{
    const int r = blockIdx.x, b = blockIdx.y;
    const int tid = threadIdx.x, lane = tid & 31, warp = tid >> 5;
    __shared__ float qs[1024];
    __shared__ float sc[1024];
    __shared__ float red[8];

    const float* q = qtext + ((long long)b * SS + r) * HH;
    for (int h = tid; h < 1024; h += 256) qs[h] = q[h];
    __syncthreads();

    const float* kb = kvis + (long long)b * SS * HH;
    for (int t = warp * 128; t < warp * 128 + 128; t++) {
        const float* kp = kb + (long long)t * HH;
        float p = 0.f;
        #pragma unroll
        for (int c = 0; c < 32; c++) p += qs[c * 32 + lane] * kp[c * 32 + lane];
        #pragma unroll
        for (int off = 16; off; off >>= 1) p += __shfl_xor_sync(0xffffffffu, p, off);
        if (lane == 0) sc[t] = p;
    }
    __syncthreads();

    float m = -3.4e38f;
    for (int t = tid; t < 1024; t += 256) m = fmaxf(m, sc[t]);
    #pragma unroll
    for (int off = 16; off; off >>= 1) m = fmaxf(m, __shfl_xor_sync(0xffffffffu, m, off));
    if (lane == 0) red[warp] = m;
    __syncthreads();
    float mx = red[0];
    #pragma unroll
    for (int k = 1; k < 8; k++) mx = fmaxf(mx, red[k]);

    float s = 0.f;
    for (int t = tid; t < 1024; t += 256) { float e = expf(sc[t] - mx); sc[t] = e; s += e; }
    #pragma unroll
    for (int off = 16; off; off >>= 1) s += __shfl_xor_sync(0xffffffffu, s, off);
    __syncthreads();
    if (lane == 0) red[warp] = s;
    __syncthreads();
    float tot = 0.f;
    #pragma unroll
    for (int k = 0; k < 8; k++) tot += red[k];
    const float inv = 1.f / tot;

    const float* vb = vvis + (long long)b * SS * HH;
    const float* tx = txt + ((long long)b * SS + r) * HH;
    long long ob = ((long long)b * LL + 1024 + r) * HH;
    float accv[4] = {0.f, 0.f, 0.f, 0.f};
    for (int t = 0; t < 1024; t++) {
        float pw = sc[t];
        const float* vr = vb + (long long)t * HH + tid;
        accv[0] += pw * vr[0];
        accv[1] += pw * vr[256];
        accv[2] += pw * vr[512];
        accv[3] += pw * vr[768];
    }
    #pragma unroll
    for (int k = 0; k < 4; k++) {
        int h = tid + k * 256;
        float v = tx[h] + accv[k] * inv;
        __half hh, lh;
        split2(v, hh, lh);
        atth[ob + h] = hh;
        attl[ob + h] = lh;
    }
}

// -------------------- softmax over 512-col rows -> probs hi/lo --------------
__global__ __launch_bounds__(256) void softmax512(const float* __restrict__ S,
                                                  __half* __restrict__ ph,
                                                  __half* __restrict__ pl)
{
    const float* row = S + (long long)blockIdx.x * 512;
    const int tid = threadIdx.x, lane = tid & 31, warp = tid >> 5;
    __shared__ float red[8];
    float a = row[tid], b2 = row[tid + 256];
    float m = fmaxf(a, b2);
    #pragma unroll
    for (int off = 16; off; off >>= 1) m = fmaxf(m, __shfl_xor_sync(0xffffffffu, m, off));
    if (lane == 0) red[warp] = m;
    __syncthreads();
    float mx = red[0];
    #pragma unroll
    for (int k = 1; k < 8; k++) mx = fmaxf(mx, red[k]);
    float e0 = expf(a - mx), e1 = expf(b2 - mx);
    float s = e0 + e1;
    #pragma unroll
    for (int off = 16; off; off >>= 1) s += __shfl_xor_sync(0xffffffffu, s, off);
    __syncthreads();
    if (lane == 0) red[warp] = s;
    __syncthreads();
    float tot = 0.f;
    #pragma unroll
    for (int k = 0; k < 8; k++) tot += red[k];
    float inv = 1.f / tot;
    long long base = (long long)blockIdx.x * 512;
    __half h0, l0, h1, l1;
    split2(e0 * inv, h0, l0);
    split2(e1 * inv, h1, l1);
    ph[base + tid] = h0; pl[base + tid] = l0;
    ph[base + tid + 256] = h1; pl[base + tid + 256] = l1;
}

// -------------------- launcher ----------------------------------------------
extern "C" void kernel_launch(void* const* d_in, const int* in_sizes, int n_in,
                              void* d_out, int out_size)
{
    (void)in_sizes; (void)n_in; (void)out_size;
    const float* vis = (const float*)d_in[0];
    const float* txt = (const float*)d_in[1];
    const float* Wq  = (const float*)d_in[2];  const float* bq  = (const float*)d_in[3];
    const float* Wk  = (const float*)d_in[4];  const float* bk  = (const float*)d_in[5];
    const float* Wv  = (const float*)d_in[6];  const float* bv  = (const float*)d_in[7];
    const float* Wc1 = (const float*)d_in[8];  const float* bc1 = (const float*)d_in[9];
    const float* Wc2 = (const float*)d_in[10]; const float* bc2 = (const float*)d_in[11];
    float* out = (float*)d_out;

    float *qt, *kv, *vv, *qv, *kt, *vt, *attb, *scb;
    __half *vish, *visl, *txth, *txtl, *c1h, *c1l, *wh, *wl;
    __half *qth, *qtl, *kvh, *kvl, *atth, *attl, *wc1h;
    __half *sch, *scl, *vvTh;
    cudaGetSymbolAddress((void**)&qt,  g_q_text);
    cudaGetSymbolAddress((void**)&kv,  g_k_vis);
    cudaGetSymbolAddress((void**)&vv,  g_v_vis);
    cudaGetSymbolAddress((void**)&qv,  g_q_vis);
    cudaGetSymbolAddress((void**)&kt,  g_k_text);
    cudaGetSymbolAddress((void**)&vt,  g_v_text);
    cudaGetSymbolAddress((void**)&attb, g_att);
    cudaGetSymbolAddress((void**)&scb, g_scores);
    cudaGetSymbolAddress((void**)&vish, g_vis_hi);
    cudaGetSymbolAddress((void**)&visl, g_vis_lo);
    cudaGetSymbolAddress((void**)&txth, g_txt_hi);
    cudaGetSymbolAddress((void**)&txtl, g_txt_lo);
    cudaGetSymbolAddress((void**)&c1h, g_c1_hi);
    cudaGetSymbolAddress((void**)&c1l, g_c1_lo);
    cudaGetSymbolAddress((void**)&wh,  g_w_hi);
    cudaGetSymbolAddress((void**)&wl,  g_w_lo);
    cudaGetSymbolAddress((void**)&qth, g_qt_hi);
    cudaGetSymbolAddress((void**)&qtl, g_qt_lo);
    cudaGetSymbolAddress((void**)&kvh, g_kv_hi);
    cudaGetSymbolAddress((void**)&kvl, g_kv_lo);
    cudaGetSymbolAddress((void**)&atth, g_att_hi);
    cudaGetSymbolAddress((void**)&attl, g_att_lo);
    cudaGetSymbolAddress((void**)&wc1h, g_wc1r_hi);
    cudaGetSymbolAddress((void**)&sch, g_sc_hi);
    cudaGetSymbolAddress((void**)&scl, g_sc_lo);
    cudaGetSymbolAddress((void**)&vvTh, g_vvT_hi);

    cudaFuncSetAttribute((const void*)&mma_qkv,
                         cudaFuncAttributeMaxDynamicSharedMemorySize, MG_SMEM);
    cudaFuncSetAttribute((const void*)&mma_gemm<false, false, true,  false, true>,
                         cudaFuncAttributeMaxDynamicSharedMemorySize, MG_SMEM);
    cudaFuncSetAttribute((const void*)&mma_gemm<false, true,  true,  true,  false>,
                         cudaFuncAttributeMaxDynamicSharedMemorySize, MG_SMEM);
    cudaFuncSetAttribute((const void*)&mma_gemm<true,  false, false, false, false>,
                         cudaFuncAttributeMaxDynamicSharedMemorySize, MG_SMEM);
    cudaFuncSetAttribute((const void*)&conv1_mma,
                         cudaFuncAttributeMaxDynamicSharedMemorySize, CV_SMEM);
    cudaFuncSetAttribute((const void*)&v2t_tile,
                         cudaFuncAttributeMaxDynamicSharedMemorySize, V2T_SMEM);

    const long long SH = (long long)SS * HH;
    const long long LH = (long long)LL * HH;
    const long long SCs = (long long)MID_M * MID_N;

    // 0) splits + weight transforms
    int n4in = BB * SS * HH / 4;
    split_fp16_2<<<(2 * n4in + 255) / 256, 256>>>(
        (const float4*)vis, (uint2*)vish, (uint2*)visl,
        (const float4*)txt, (uint2*)txth, (uint2*)txtl, n4in);
    split_w4<<<(WW + 255) / 256, 256>>>(
        (const float4*)Wq, (const float4*)Wk, (const float4*)Wv, (const float4*)Wc2,
        (uint2*)wh, (uint2*)wl);
    wc1_transform<<<(HH * 384 + 255) / 256, 256>>>(Wc1, wc1h);

    // 1) fused QKV projections for both inputs in ONE launch
    mma_qkv<<<dim3(24, 64, 2), 256, MG_SMEM>>>(
        txth, txtl, vish, visl, wh, wl, bq, bk, bv,
        qt, kt, vt, qv, kv, vv,
        qth, qtl, kvh, kvl);

    // 2) text residual rows -> att hi/lo (independent of qkv; early)
    copy_text<<<8192, 256>>>((const float4*)txt, atth, attl);

    // 3) v2t sparse attention (tiled)
    v2t_tile<<<dim3(SS / 8, BB), 256, V2T_SMEM>>>(qv, kt, vt, vis, atth, attl);

    // 4) t2v rows 0..4
    t2v_full_rows<<<dim3(5, BB), 256>>>(qt, kv, vv, txt, atth, attl);

    // 4b) transpose V slice (hoisted off the scores->softmax->AV chain)
    transpose_vslice<<<dim3(MID_N / 32, HH / 32, BB), dim3(32, 8)>>>(vv, vvTh);

    // 5) t2v mid scores (3-term)
    mma_gemm<false, false, true, false, true><<<dim3(MID_N / 128, 3, BB), 256, MG_SMEM>>>(
        qth + 341 * HH, qtl + 341 * HH, SH,
        kvh + 256 * HH, kvl + 256 * HH, SH,
        scb, SCs, MID_N, nullptr, nullptr, nullptr, nullptr, 0, 0, MID_M, HH);

    // 6) softmax -> probs hi/lo
    softmax512<<<BB * MID_M, 256>>>(scb, sch, scl);

    // 7) AV (2-term) + text residual -> att rows hi/lo
    mma_gemm<false, true, true, true, false><<<dim3(HH / 128, 3, BB), 256, MG_SMEM>>>(
        sch, scl, SCs,
        vvTh, vvTh, (long long)HH * MID_N,
        attb + (long long)(1024 + 341) * HH, LH, HH,
        nullptr,
        atth + (long long)(1024 + 341) * HH, attl + (long long)(1024 + 341) * HH,
        txt + 341 * HH, SH, HH,
        MID_M, MID_N);

    // 8) conv1 (2-term) + GELU -> c1 hi/lo
    conv1_mma<<<dim3(LL / 128, 8, BB), 256, CV_SMEM>>>(atth, attl, wc1h, bc1, c1h, c1l);

    // 9) conv2 (2-term) -> output
    mma_gemm<true, false, false, false, false><<<dim3(HH / 128, BB * LL / 128, 1), 256, MG_SMEM>>>(
        c1h, c1l, 0, wh + 3 * WW, wh + 3 * WW, 0,
        out, 0, HH, bc2, nullptr, nullptr, nullptr, 0, 0, BB * LL, HH);
}

// round 9
// speedup vs baseline: 3.1612x; 1.0758x over previous
#include <cuda_runtime.h>
#include <cuda_fp16.h>
#include <math.h>
#include <stdint.h>

#define BB 8
#define SS 1024
#define HH 1024
#define LL 2048
#define MID_M 341
#define MID_N 512
#define WW (HH*HH)

// -------------------- scratch (device globals) ------------------------------
__device__ __align__(128) float g_q_text[BB*SS*HH];
__device__ __align__(128) float g_k_vis [BB*SS*HH];
__device__ __align__(128) float g_v_vis [BB*SS*HH];
__device__ __align__(128) float g_q_vis [BB*SS*HH];
__device__ __align__(128) float g_k_text[BB*SS*HH];
__device__ __align__(128) float g_v_text[BB*SS*HH];
__device__ __align__(128) float g_att   [BB*LL*HH];
__device__ __align__(128) float g_scores[BB*MID_M*MID_N];
__device__ __align__(128) __half g_vis_hi[BB*SS*HH];
__device__ __align__(128) __half g_vis_lo[BB*SS*HH];
__device__ __align__(128) __half g_txt_hi[BB*SS*HH];
__device__ __align__(128) __half g_txt_lo[BB*SS*HH];
__device__ __align__(128) __half g_c1_hi [BB*LL*HH];
__device__ __align__(128) __half g_c1_lo [BB*LL*HH];
__device__ __align__(128) __half g_w_hi  [4*WW];      // Wq, Wk, Wv, Wc2
__device__ __align__(128) __half g_w_lo  [4*WW];
__device__ __align__(128) __half g_qt_hi [BB*SS*HH];
__device__ __align__(128) __half g_qt_lo [BB*SS*HH];
__device__ __align__(128) __half g_kv_hi [BB*SS*HH];
__device__ __align__(128) __half g_kv_lo [BB*SS*HH];
__device__ __align__(128) __half g_att_hi[BB*LL*HH];
__device__ __align__(128) __half g_att_lo[BB*LL*HH];
__device__ __align__(128) __half g_wc1r_hi[HH*384];
__device__ __align__(128) __half g_sc_hi [BB*MID_M*MID_N];
__device__ __align__(128) __half g_sc_lo [BB*MID_M*MID_N];
__device__ __align__(128) __half g_vvT_hi[BB*HH*MID_N];

// ===================== low-level helpers ====================================
__device__ __forceinline__ uint32_t smem_to_u32(const void* p) {
    uint32_t a;
    asm("{ .reg .u64 t; cvta.to.shared.u64 t, %1; cvt.u32.u64 %0, t; }" : "=r"(a) : "l"(p));
    return a;
}
__device__ __forceinline__ void cp_async16(uint32_t saddr, const void* gptr) {
    asm volatile("cp.async.cg.shared.global [%0], [%1], 16;" :: "r"(saddr), "l"(gptr));
}
#define CP_COMMIT() asm volatile("cp.async.commit_group;" ::: "memory")
#define CP_WAIT1()  asm volatile("cp.async.wait_group 1;" ::: "memory")
#define CP_WAIT0()  asm volatile("cp.async.wait_group 0;" ::: "memory")

__device__ __forceinline__ void ldm_x4(uint32_t& r0, uint32_t& r1, uint32_t& r2, uint32_t& r3,
                                       uint32_t addr) {
    asm volatile("ldmatrix.sync.aligned.m8n8.x4.shared.b16 {%0,%1,%2,%3}, [%4];"
                 : "=r"(r0), "=r"(r1), "=r"(r2), "=r"(r3) : "r"(addr));
}
__device__ __forceinline__ void ldm_x2(uint32_t& r0, uint32_t& r1, uint32_t addr) {
    asm volatile("ldmatrix.sync.aligned.m8n8.x2.shared.b16 {%0,%1}, [%2];"
                 : "=r"(r0), "=r"(r1) : "r"(addr));
}
__device__ __forceinline__ void mma16816(float* c, const uint32_t* a, const uint32_t* b) {
    asm volatile("mma.sync.aligned.m16n8k16.row.col.f32.f16.f16.f32 "
                 "{%0,%1,%2,%3}, {%4,%5,%6,%7}, {%8,%9}, {%0,%1,%2,%3};"
                 : "+f"(c[0]), "+f"(c[1]), "+f"(c[2]), "+f"(c[3])
                 : "r"(a[0]), "r"(a[1]), "r"(a[2]), "r"(a[3]), "r"(b[0]), "r"(b[1]));
}
__device__ __forceinline__ void split2(float v, __half& h, __half& l) {
    h = __float2half_rn(v);
    l = __float2half_rn(v - __half2float(h));
}

// ============ GEMM geometry: CTA tile 128x64, 128 threads, 2 CTAs/SM ========
// stage = Ahi 16K | Alo 16K | Bhi 8K | Blo 8K = 48KB; 2 stages = 96KB/CTA.
#define STG 49152u
#define MG_SMEM (2 * 49152)

// =================== generic tensor-core GEMM ===============================
// C[M,N] = A[M,K] @ B[N,K]^T (+bias)(+residual). A hi/lo split.
// TERM3: also split B (3 mma terms); else B hi only (2 terms).
template<bool BIAS, bool HALFOUT, bool GUARD, bool RESID, bool TERM3>
__global__ __launch_bounds__(128, 2)
void mma_gemm(const __half* __restrict__ Ahi, const __half* __restrict__ Alo, long long sA,
              const __half* __restrict__ Bhi, const __half* __restrict__ Blo, long long sB,
              float* __restrict__ C, long long sC, int ldc,
              const float* __restrict__ bias,
              __half* __restrict__ Chi, __half* __restrict__ Clo,
              const float* __restrict__ Rm, long long sR, int ldr,
              int M, int K)
{
    extern __shared__ char smem[];
    const uint32_t sbase = smem_to_u32(smem);
    const int tid = threadIdx.x;
    const int wid = tid >> 5, lane = tid & 31;
    const int m0 = blockIdx.y * 128, n0 = blockIdx.x * 64;
    const int m_w = (wid & 1) * 64;
    const int n_w = (wid >> 1) * 32;
    const int z = blockIdx.z;
    Ahi += z * sA; Alo += z * sA;
    Bhi += z * sB; if (TERM3) Blo += z * sB;
    C   += z * sC;
    if (HALFOUT) { Chi += z * sC; Clo += z * sC; }
    if (RESID)   { Rm  += z * sR; }

    const int crow = tid >> 3;     // 0..15
    const int cc16 = tid & 7;
    const int nk = K >> 6;

    auto issue_stage = [&](int kc, int s) {
        const int k0 = kc * 64;
        const uint32_t st = sbase + (uint32_t)s * STG;
        #pragma unroll
        for (int p = 0; p < 8; p++) {
            int row = p * 16 + crow;
            uint32_t soff = (uint32_t)(row * 128) + (uint32_t)((cc16 * 16) ^ ((row & 7) << 4));
            int gm = m0 + row;
            if (GUARD) gm = (gm < M) ? gm : (M - 1);
            long long ga = (long long)gm * K + k0 + cc16 * 8;
            cp_async16(st + soff,         Ahi + ga);
            cp_async16(st + 16384 + soff, Alo + ga);
            if (p < 4) {
                long long gb = (long long)(n0 + row) * K + k0 + cc16 * 8;
                cp_async16(st + 32768 + soff, Bhi + gb);
                if (TERM3) cp_async16(st + 40960 + soff, Blo + gb);
            }
        }
    };

    uint32_t aRow[4], aXor[4];
    #pragma unroll
    for (int mt = 0; mt < 4; mt++) {
        int r = m_w + 16 * mt + (lane & 15);
        aRow[mt] = (uint32_t)(r * 128);
        aXor[mt] = (uint32_t)((r & 7) << 4);
    }
    const uint32_t aCol = (uint32_t)((lane >> 4) * 16);
    uint32_t bRow[4], bXor[4];
    #pragma unroll
    for (int nt = 0; nt < 4; nt++) {
        int r = n_w + 8 * nt + (lane & 7);
        bRow[nt] = (uint32_t)(r * 128);
        bXor[nt] = (uint32_t)((r & 7) << 4);
    }
    const uint32_t bCol = (uint32_t)(((lane >> 3) & 1) * 16);

    float acc[4][4][4];
    #pragma unroll
    for (int mt = 0; mt < 4; mt++)
        #pragma unroll
        for (int nt = 0; nt < 4; nt++)
            #pragma unroll
            for (int q = 0; q < 4; q++) acc[mt][nt][q] = 0.f;

    uint32_t ah[2][4][4], al[2][4][4], bh[2][4][2], bl[2][4][2];

    auto load_frags = [&](int s, int ks, int pb) {
        const uint32_t st = sbase + (uint32_t)s * STG;
        const uint32_t kb = (uint32_t)(ks * 32);
        #pragma unroll
        for (int mt = 0; mt < 4; mt++) {
            uint32_t ad = st + aRow[mt] + ((kb + aCol) ^ aXor[mt]);
            ldm_x4(ah[pb][mt][0], ah[pb][mt][1], ah[pb][mt][2], ah[pb][mt][3], ad);
            ldm_x4(al[pb][mt][0], al[pb][mt][1], al[pb][mt][2], al[pb][mt][3], ad + 16384);
        }
        #pragma unroll
        for (int nt = 0; nt < 4; nt++) {
            uint32_t bd = st + 32768 + bRow[nt] + ((kb + bCol) ^ bXor[nt]);
            ldm_x2(bh[pb][nt][0], bh[pb][nt][1], bd);
            if (TERM3) ldm_x2(bl[pb][nt][0], bl[pb][nt][1], bd + 8192);
        }
    };
    auto do_mma = [&](int pb) {
        #pragma unroll
        for (int mt = 0; mt < 4; mt++)
            #pragma unroll
            for (int nt = 0; nt < 4; nt++) {
                mma16816(acc[mt][nt], ah[pb][mt], bh[pb][nt]);
                if (TERM3) mma16816(acc[mt][nt], ah[pb][mt], bl[pb][nt]);
                mma16816(acc[mt][nt], al[pb][mt], bh[pb][nt]);
            }
    };

    issue_stage(0, 0); CP_COMMIT();
    issue_stage(1, 1); CP_COMMIT();
    for (int kc = 0; kc < nk; kc++) {
        if (kc + 1 < nk) { CP_WAIT1(); } else { CP_WAIT0(); }
        __syncthreads();
        const int s = kc & 1;
        load_frags(s, 0, 0);
        #pragma unroll
        for (int ks = 0; ks < 4; ks++) {
            if (ks < 3) load_frags(s, ks + 1, (ks + 1) & 1);
            do_mma(ks & 1);
        }
        if (kc + 2 < nk) {
            __syncthreads();            // all warps done reading stage s
            issue_stage(kc + 2, s); CP_COMMIT();
        }
    }

    const int rq = lane >> 2, cq = (lane & 3) * 2;
    #pragma unroll
    for (int mt = 0; mt < 4; mt++) {
        int row0 = m0 + m_w + 16 * mt + rq;
        #pragma unroll
        for (int nt = 0; nt < 4; nt++) {
            int col = n0 + n_w + 8 * nt + cq;
            float b0 = 0.f, b1 = 0.f;
            if (BIAS) { b0 = bias[col]; b1 = bias[col + 1]; }
            #pragma unroll
            for (int rr = 0; rr < 2; rr++) {
                int row = row0 + rr * 8;
                if (GUARD && row >= M) continue;
                float x0 = acc[mt][nt][rr * 2 + 0] + b0;
                float x1 = acc[mt][nt][rr * 2 + 1] + b1;
                if (RESID) {
                    const float* Rp = Rm + (long long)row * ldr + col;
                    x0 += Rp[0]; x1 += Rp[1];
                }
                long long idx = (long long)row * ldc + col;
                *(float2*)(C + idx) = make_float2(x0, x1);
                if (HALFOUT) {
                    __half h0, l0h, h1, l1h;
                    split2(x0, h0, l0h); split2(x1, h1, l1h);
                    *(__half2*)(Chi + idx) = __halves2half2(h0, h1);
                    *(__half2*)(Clo + idx) = __halves2half2(l0h, l1h);
                }
            }
        }
    }
}

// ============ fused QKV projection for BOTH inputs ==========================
// grid = (48, 64, 2). tile N=64. seg = bx/16; z=0 text, z=1 vis.
// q_text (z=0, seg=0) skips local m-tiles {1,6,7} (rows unused downstream).
__global__ __launch_bounds__(128, 2)
void mma_qkv(const __half* __restrict__ A0h, const __half* __restrict__ A0l,
             const __half* __restrict__ A1h, const __half* __restrict__ A1l,
             const __half* __restrict__ Bhi, const __half* __restrict__ Blo,
             const float* __restrict__ b0p, const float* __restrict__ b1p,
             const float* __restrict__ b2p,
             float* __restrict__ Cq0, float* __restrict__ Ck0, float* __restrict__ Cv0,
             float* __restrict__ Cq1, float* __restrict__ Ck1, float* __restrict__ Cv1,
             __half* __restrict__ C0hi, __half* __restrict__ C0lo,
             __half* __restrict__ C1hi, __half* __restrict__ C1lo)
{
    extern __shared__ char smem[];
    const uint32_t sbase = smem_to_u32(smem);
    const int tid = threadIdx.x;
    const int wid = tid >> 5, lane = tid & 31;
    const int m0 = blockIdx.y * 128, n0 = blockIdx.x * 64;
    const int m_w = (wid & 1) * 64;
    const int n_w = (wid >> 1) * 32;
    const int z = blockIdx.z;
    const int seg = n0 >> 10;
    const int ncol0 = n0 & 1023;
    const bool t3 = (seg < 2);

    // dead-tile skip: q_text only consumed at rows 0..4 and 341..681
    if (z == 0 && seg == 0) {
        int lt = blockIdx.y & 7;
        if (lt == 1 || lt == 6 || lt == 7) return;
    }

    const __half* Ahi = z ? A1h : A0h;
    const __half* Alo = z ? A1l : A0l;
    float* C = z ? ((seg == 0) ? Cq1 : (seg == 1) ? Ck1 : Cv1)
                 : ((seg == 0) ? Cq0 : (seg == 1) ? Ck0 : Cv0);
    const float* bias = (seg == 0) ? b0p : (seg == 1) ? b1p : b2p;
    const bool doHalf = (seg == (z ? 1 : 0));
    __half* Chi = z ? C1hi : C0hi;
    __half* Clo = z ? C1lo : C0lo;

    const int crow = tid >> 3;
    const int cc16 = tid & 7;

    auto issue_stage = [&](int kc, int s) {
        const int k0 = kc * 64;
        const uint32_t st = sbase + (uint32_t)s * STG;
        #pragma unroll
        for (int p = 0; p < 8; p++) {
            int row = p * 16 + crow;
            uint32_t soff = (uint32_t)(row * 128) + (uint32_t)((cc16 * 16) ^ ((row & 7) << 4));
            long long ga = (long long)(m0 + row) * 1024 + k0 + cc16 * 8;
            cp_async16(st + soff,         Ahi + ga);
            cp_async16(st + 16384 + soff, Alo + ga);
            if (p < 4) {
                long long gb = (long long)(n0 + row) * 1024 + k0 + cc16 * 8;
                cp_async16(st + 32768 + soff, Bhi + gb);
                if (t3) cp_async16(st + 40960 + soff, Blo + gb);
            }
        }
    };

    uint32_t aRow[4], aXor[4];
    #pragma unroll
    for (int mt = 0; mt < 4; mt++) {
        int r = m_w + 16 * mt + (lane & 15);
        aRow[mt] = (uint32_t)(r * 128);
        aXor[mt] = (uint32_t)((r & 7) << 4);
    }
    const uint32_t aCol = (uint32_t)((lane >> 4) * 16);
    uint32_t bRow[4], bXor[4];
    #pragma unroll
    for (int nt = 0; nt < 4; nt++) {
        int r = n_w + 8 * nt + (lane & 7);
        bRow[nt] = (uint32_t)(r * 128);
        bXor[nt] = (uint32_t)((r & 7) << 4);
    }
    const uint32_t bCol = (uint32_t)(((lane >> 3) & 1) * 16);

    float acc[4][4][4];
    #pragma unroll
    for (int mt = 0; mt < 4; mt++)
        #pragma unroll
        for (int nt = 0; nt < 4; nt++)
            #pragma unroll
            for (int q = 0; q < 4; q++) acc[mt][nt][q] = 0.f;

    uint32_t ah[2][4][4], al[2][4][4], bh[2][4][2], bl[2][4][2];

    auto load_frags = [&](int s, int ks, int pb) {
        const uint32_t st = sbase + (uint32_t)s * STG;
        const uint32_t kb = (uint32_t)(ks * 32);
        #pragma unroll
        for (int mt = 0; mt < 4; mt++) {
            uint32_t ad = st + aRow[mt] + ((kb + aCol) ^ aXor[mt]);
            ldm_x4(ah[pb][mt][0], ah[pb][mt][1], ah[pb][mt][2], ah[pb][mt][3], ad);
            ldm_x4(al[pb][mt][0], al[pb][mt][1], al[pb][mt][2], al[pb][mt][3], ad + 16384);
        }
        #pragma unroll
        for (int nt = 0; nt < 4; nt++) {
            uint32_t bd = st + 32768 + bRow[nt] + ((kb + bCol) ^ bXor[nt]);
            ldm_x2(bh[pb][nt][0], bh[pb][nt][1], bd);
            if (t3) ldm_x2(bl[pb][nt][0], bl[pb][nt][1], bd + 8192);
        }
    };
    auto do_mma = [&](int pb) {
        #pragma unroll
        for (int mt = 0; mt < 4; mt++)
            #pragma unroll
            for (int nt = 0; nt < 4; nt++) {
                mma16816(acc[mt][nt], ah[pb][mt], bh[pb][nt]);
                if (t3) mma16816(acc[mt][nt], ah[pb][mt], bl[pb][nt]);
                mma16816(acc[mt][nt], al[pb][mt], bh[pb][nt]);
            }
    };

    issue_stage(0, 0); CP_COMMIT();
    issue_stage(1, 1); CP_COMMIT();
    for (int kc = 0; kc < 16; kc++) {
        if (kc + 1 < 16) { CP_WAIT1(); } else { CP_WAIT0(); }
        __syncthreads();
        const int s = kc & 1;
        load_frags(s, 0, 0);
        #pragma unroll
        for (int ks = 0; ks < 4; ks++) {
            if (ks < 3) load_frags(s, ks + 1, (ks + 1) & 1);
            do_mma(ks & 1);
        }
        if (kc + 2 < 16) {
            __syncthreads();
            issue_stage(kc + 2, s); CP_COMMIT();
        }
    }

    const int rq = lane >> 2, cq = (lane & 3) * 2;
    #pragma unroll
    for (int mt = 0; mt < 4; mt++) {
        int row0 = m0 + m_w + 16 * mt + rq;
        #pragma unroll
        for (int nt = 0; nt < 4; nt++) {
            int col = ncol0 + n_w + 8 * nt + cq;
            float b0 = bias[col], b1 = bias[col + 1];
            #pragma unroll
            for (int rr = 0; rr < 2; rr++) {
                int row = row0 + rr * 8;
                float x0 = acc[mt][nt][rr * 2 + 0] + b0;
                float x1 = acc[mt][nt][rr * 2 + 1] + b1;
                long long idx = (long long)row * 1024 + col;
                *(float2*)(C + idx) = make_float2(x0, x1);
                if (doHalf) {
                    __half h0, l0h, h1, l1h;
                    split2(x0, h0, l0h); split2(x1, h1, l1h);
                    *(__half2*)(Chi + idx) = __halves2half2(h0, h1);
                    *(__half2*)(Clo + idx) = __halves2half2(l0h, l1h);
                }
            }
        }
    }
}

// =================== conv1 (grouped k=3), single-shot smem ==================
#define CV_SMEM (2*33280 + 3*32768)

__global__ __launch_bounds__(256, 1)
void conv1_mma(const __half* __restrict__ xh, const __half* __restrict__ xl,
               const __half* __restrict__ wh,
               const float* __restrict__ bias,
               __half* __restrict__ oh, __half* __restrict__ ol)
{
    extern __shared__ char smem[];
    const uint32_t sb = smem_to_u32(smem);
    const int tid = threadIdx.x, wid = tid >> 5, lane = tid & 31;
    const int l0 = blockIdx.x * 128, g = blockIdx.y, b = blockIdx.z;
    const int m_w = (wid & 1) * 64, n_w = (wid >> 1) * 32;
    const uint32_t XH = sb, WH = sb + 66560u;

    for (int t = tid; t < 2080; t += 256) {
        int r = t >> 4, c16 = t & 15;
        int l = l0 - 1 + r;
        uint32_t d = (uint32_t)(r * 256) + (uint32_t)((c16 * 16) ^ ((r & 7) << 4));
        uint4 vh = make_uint4(0u, 0u, 0u, 0u), vl = vh;
        if (l >= 0 && l < LL) {
            long long gidx = ((long long)b * LL + l) * HH + g * 128 + c16 * 8;
            vh = *(const uint4*)(xh + gidx);
            vl = *(const uint4*)(xl + gidx);
        }
        *(uint4*)(smem + d)         = vh;
        *(uint4*)(smem + 33280 + d) = vl;
    }
    for (int t = tid; t < 3 * 2048; t += 256) {
        int tap = t >> 11, u = t & 2047;
        int r = u >> 4, c16 = u & 15;
        uint32_t d = (uint32_t)(r * 256) + (uint32_t)((c16 * 16) ^ ((r & 7) << 4));
        long long widx = (long long)(g * 128 + r) * 384 + tap * 128 + c16 * 8;
        *(uint4*)(smem + 66560 + tap * 32768 + d) = *(const uint4*)(wh + widx);
    }
    __syncthreads();

    float acc[4][4][4];
    #pragma unroll
    for (int mt = 0; mt < 4; mt++)
        #pragma unroll
        for (int nt = 0; nt < 4; nt++)
            #pragma unroll
            for (int q = 0; q < 4; q++) acc[mt][nt][q] = 0.f;

    const uint32_t aCol = (uint32_t)((lane >> 4) * 16);
    const uint32_t bCol = (uint32_t)(((lane >> 3) & 1) * 16);

    for (int tap = 0; tap < 3; tap++) {
        #pragma unroll
        for (int ks = 0; ks < 8; ks++) {
            const uint32_t kb = (uint32_t)(ks * 32);
            uint32_t ah[4][4], al[4][4], bh[4][2];
            #pragma unroll
            for (int mt = 0; mt < 4; mt++) {
                int ar = m_w + 16 * mt + (lane & 15) + tap;
                uint32_t ad = XH + (uint32_t)(ar * 256) + ((kb + aCol) ^ (uint32_t)((ar & 7) << 4));
                ldm_x4(ah[mt][0], ah[mt][1], ah[mt][2], ah[mt][3], ad);
                ldm_x4(al[mt][0], al[mt][1], al[mt][2], al[mt][3], ad + 33280u);
            }
            #pragma unroll
            for (int nt = 0; nt < 4; nt++) {
                int br = n_w + 8 * nt + (lane & 7);
                uint32_t bd = WH + (uint32_t)(tap * 32768) + (uint32_t)(br * 256)
                            + ((kb + bCol) ^ (uint32_t)((br & 7) << 4));
                ldm_x2(bh[nt][0], bh[nt][1], bd);
            }
            #pragma unroll
            for (int mt = 0; mt < 4; mt++)
                #pragma unroll
                for (int nt = 0; nt < 4; nt++) {
                    mma16816(acc[mt][nt], ah[mt], bh[nt]);
                    mma16816(acc[mt][nt], al[mt], bh[nt]);
                }
        }
    }

    const int rq = lane >> 2, cq = (lane & 3) * 2;
    #pragma unroll
    for (int mt = 0; mt < 4; mt++) {
        int row0 = l0 + m_w + 16 * mt + rq;
        #pragma unroll
        for (int nt = 0; nt < 4; nt++) {
            int ch = g * 128 + n_w + 8 * nt + cq;
            float b0 = bias[ch], b1 = bias[ch + 1];
            #pragma unroll
            for (int rr = 0; rr < 2; rr++) {
                int row = row0 + rr * 8;
                float x0 = acc[mt][nt][rr * 2 + 0] + b0;
                float x1 = acc[mt][nt][rr * 2 + 1] + b1;
                float y0 = 0.5f * x0 * (1.0f + erff(x0 * 0.70710678118654752f));
                float y1 = 0.5f * x1 * (1.0f + erff(x1 * 0.70710678118654752f));
                __half h0, l0h, h1, l1h;
                split2(y0, h0, l0h); split2(y1, h1, l1h);
                long long idx = ((long long)b * LL + row) * HH + ch;
                *(__half2*)(oh + idx) = __halves2half2(h0, h1);
                *(__half2*)(ol + idx) = __halves2half2(l0h, l1h);
            }
        }
    }
}

// ------ fused fp32 -> (hi, lo) splits; txt part also seeds att rows ---------
__global__ void split_fp16_2(const float4* __restrict__ x0, uint2* __restrict__ h0,
                             uint2* __restrict__ l0, const float4* __restrict__ x1,
                             uint2* __restrict__ h1, uint2* __restrict__ l1,
                             uint2* __restrict__ atth4, uint2* __restrict__ attl4, int n4)
{
    int i = blockIdx.x * 256 + threadIdx.x;
    bool isTxt = false;
    const float4* x; uint2 *hp, *lp;
    if (i >= n4) { i -= n4; if (i >= n4) return; x = x1; hp = h1; lp = l1; isTxt = true; }
    else { x = x0; hp = h0; lp = l0; }
    float4 v = x[i];
    __half hx, lx, hy, ly, hz, lz, hw, lw;
    split2(v.x, hx, lx); split2(v.y, hy, ly);
    split2(v.z, hz, lz); split2(v.w, hw, lw);
    __half2 a0 = __halves2half2(hx, hy), a1 = __halves2half2(hz, hw);
    __half2 b0 = __halves2half2(lx, ly), b1 = __halves2half2(lz, lw);
    uint2 oh2, ol2;
    oh2.x = *(uint32_t*)&a0; oh2.y = *(uint32_t*)&a1;
    ol2.x = *(uint32_t*)&b0; ol2.y = *(uint32_t*)&b1;
    hp[i] = oh2; lp[i] = ol2;
    if (isTxt) {
        int b = i >> 18, r = i & 262143;
        long long d4 = (long long)b * 524288 + 262144 + r;
        atth4[d4] = oh2; attl4[d4] = ol2;
    }
}

__global__ void split_w4(const float4* __restrict__ wq, const float4* __restrict__ wk,
                         const float4* __restrict__ wv, const float4* __restrict__ wc2,
                         uint2* __restrict__ hi, uint2* __restrict__ lo)
{
    int idx = blockIdx.x * 256 + threadIdx.x;
    int seg = idx >> 18, i = idx & 262143;
    const float4* src = (seg == 0) ? wq : (seg == 1) ? wk : (seg == 2) ? wv : wc2;
    float4 v = src[i];
    __half hx, lx, hy, ly, hz, lz, hw, lw;
    split2(v.x, hx, lx); split2(v.y, hy, ly);
    split2(v.z, hz, lz); split2(v.w, hw, lw);
    __half2 a0 = __halves2half2(hx, hy), a1 = __halves2half2(hz, hw);
    __half2 b0 = __halves2half2(lx, ly), b1 = __halves2half2(lz, lw);
    uint2 oh2, ol2;
    oh2.x = *(uint32_t*)&a0; oh2.y = *(uint32_t*)&a1;
    ol2.x = *(uint32_t*)&b0; ol2.y = *(uint32_t*)&b1;
    hi[idx] = oh2; lo[idx] = ol2;
}

__global__ void wc1_transform(const float* __restrict__ W, __half* __restrict__ wh)
{
    int idx = blockIdx.x * 256 + threadIdx.x;
    if (idx >= HH * 384) return;
    int o = idx / 384, k = idx % 384;
    int tap = k >> 7, ic = k & 127;
    wh[idx] = __float2half_rn(W[(long long)o * 384 + ic * 3 + tap]);
}

__global__ void transpose_vslice(const float* __restrict__ vv, __half* __restrict__ th)
{
    __shared__ float tile[32][33];
    const int t0 = blockIdx.x * 32, h0 = blockIdx.y * 32, b = blockIdx.z;
    const int tx = threadIdx.x, ty = threadIdx.y;
    #pragma unroll
    for (int y = ty; y < 32; y += 8)
        tile[y][tx] = vv[((long long)b * SS + 256 + t0 + y) * HH + h0 + tx];
    __syncthreads();
    #pragma unroll
    for (int y = ty; y < 32; y += 8) {
        long long o = ((long long)b * HH + h0 + y) * MID_N + t0 + tx;
        th[o] = __float2half_rn(tile[tx][y]);
    }
}

// -------- v2t attention, tiled: 8 query rows per block ----------------------
#define V2T_SMEM (40 * 1024 * 4)

__global__ __launch_bounds__(256, 1) void v2t_tile(
    const float* __restrict__ qvis, const float* __restrict__ ktext,
    const float* __restrict__ vtext, const float* __restrict__ visf,
    __half* __restrict__ atth, __half* __restrict__ attl)
{
    extern __shared__ float sm[];
    float* ks = sm;
    float* vs = sm + 20 * 1024;
    const int b = blockIdx.y, i0 = blockIdx.x * 8;
    const int tid = threadIdx.x, w = tid >> 5, lane = tid & 31;
    const int w0 = (i0 < 1016) ? i0 : 1016;

    const float* kb = ktext + (long long)b * SS * HH;
    const float* vb = vtext + (long long)b * SS * HH;
    for (int t = tid; t < 20 * 256; t += 256) {
        int slot = t >> 8, c4 = (t & 255) * 4;
        int row = (slot < 5) ? slot : (w0 + slot - 5);
        row = (row < 1023) ? row : 1023;
        *(float4*)(ks + slot * 1024 + c4) = *(const float4*)(kb + (long long)row * HH + c4);
        *(float4*)(vs + slot * 1024 + c4) = *(const float4*)(vb + (long long)row * HH + c4);
    }
    __syncthreads();

    const int i = i0 + w;
    const int s0 = (i < 1016) ? i : 1016;
    const int nk = (i < 5) ? (i + 8) : 13;

    const float* q = qvis + ((long long)b * SS + i) * HH;
    float qr[32];
    #pragma unroll
    for (int c = 0; c < 32; c++) qr[c] = q[c * 32 + lane];

    int sl[13];
    float p[13];
    #pragma unroll
    for (int j = 0; j < 13; j++) {
        int row = (i < 5) ? j : ((j < 5) ? j : (s0 + j - 5));
        sl[j] = (row < 5) ? row : (5 + row - w0);
        float s = 0.f;
        if (j < nk) {
            const float* kr = ks + sl[j] * 1024;
            #pragma unroll
            for (int c = 0; c < 32; c++) s += qr[c] * kr[c * 32 + lane];
        }
        #pragma unroll
        for (int off = 16; off; off >>= 1) s += __shfl_xor_sync(0xffffffffu, s, off);
        p[j] = s;
    }

    float mx = -3.4e38f;
    #pragma unroll
    for (int j = 0; j < 13; j++) if (j < nk) mx = fmaxf(mx, p[j]);
    float sum = 0.f;
    #pragma unroll
    for (int j = 0; j < 13; j++) {
        float e = (j < nk) ? expf(p[j] - mx) : 0.f;
        p[j] = e; sum += e;
    }
    const float inv = 1.f / sum;
    #pragma unroll
    for (int j = 0; j < 13; j++) p[j] *= inv;

    const float* vf = visf + ((long long)b * SS + i) * HH;
    long long ob = ((long long)b * LL + i) * HH;
    #pragma unroll 4
    for (int r = 0; r < 32; r++) {
        int h = r * 32 + lane;
        float a = vf[h];
        #pragma unroll
        for (int j = 0; j < 13; j++) a += p[j] * vs[sl[j] * 1024 + h];
        __half hh, lh;
        split2(a, hh, lh);
        atth[ob + h] = hh;
        attl[ob + h] = lh;
    }
}

// -------------------- t2v rows 0..4 -----------------------------------------
__global__ __launch_bounds__(256) void t2v_full_rows(
    const float* __restrict__ qtext, const float* __restrict__ kvis,
    const float* __restrict__ vvis, const float* __restrict__ txt,
    __half* __restrict__ atth, __half* __restrict__ attl)
{
    const int r = blockIdx.x, b = blockIdx.y;
    const int tid = threadIdx.x, lane = tid & 31, warp = tid >> 5;
    __shared__ float qs[1024];
    __shared__ float sc[1024];
    __shared__ float red[8];

    const float* q = qtext + ((long long)b * SS + r) * HH;
    for (int h = tid; h < 1024; h += 256) qs[h] = q[h];
    __syncthreads();

    const float* kb = kvis + (long long)b * SS * HH;
    for (int t = warp * 128; t < warp * 128 + 128; t++) {
        const float* kp = kb + (long long)t * HH;
        float p = 0.f;
        #pragma unroll
        for (int c = 0; c < 32; c++) p += qs[c * 32 + lane] * kp[c * 32 + lane];
        #pragma unroll
        for (int off = 16; off; off >>= 1) p += __shfl_xor_sync(0xffffffffu, p, off);
        if (lane == 0) sc[t] = p;
    }
    __syncthreads();

    float m = -3.4e38f;
    for (int t = tid; t < 1024; t += 256) m = fmaxf(m, sc[t]);
    #pragma unroll
    for (int off = 16; off; off >>= 1) m = fmaxf(m, __shfl_xor_sync(0xffffffffu, m, off));
    if (lane == 0) red[warp] = m;
    __syncthreads();
    float mx = red[0];
    #pragma unroll
    for (int k = 1; k < 8; k++) mx = fmaxf(mx, red[k]);

    float s = 0.f;
    for (int t = tid; t < 1024; t += 256) { float e = expf(sc[t] - mx); sc[t] = e; s += e; }
    #pragma unroll
    for (int off = 16; off; off >>= 1) s += __shfl_xor_sync(0xffffffffu, s, off);
    __syncthreads();
    if (lane == 0) red[warp] = s;
    __syncthreads();
    float tot = 0.f;
    #pragma unroll
    for (int k = 0; k < 8; k++) tot += red[k];
    const float inv = 1.f / tot;

    const float* vb = vvis + (long long)b * SS * HH;
    const float* tx = txt + ((long long)b * SS + r) * HH;
    long long ob = ((long long)b * LL + 1024 + r) * HH;
    float accv[4] = {0.f, 0.f, 0.f, 0.f};
    for (int t = 0; t < 1024; t++) {
        float pw = sc[t];
        const float* vr = vb + (long long)t * HH + tid;
        accv[0] += pw * vr[0];
        accv[1] += pw * vr[256];
        accv[2] += pw * vr[512];
        accv[3] += pw * vr[768];
    }
    #pragma unroll
    for (int k = 0; k < 4; k++) {
        int h = tid + k * 256;
        float v = tx[h] + accv[k] * inv;
        __half hh, lh;
        split2(v, hh, lh);
        atth[ob + h] = hh;
        attl[ob + h] = lh;
    }
}

// -------------------- softmax over 512-col rows -> probs hi/lo --------------
__global__ __launch_bounds__(256) void softmax512(const float* __restrict__ S,
                                                  __half* __restrict__ ph,
                                                  __half* __restrict__ pl)
{
    const float* row = S + (long long)blockIdx.x * 512;
    const int tid = threadIdx.x, lane = tid & 31, warp = tid >> 5;
    __shared__ float red[8];
    float a = row[tid], b2 = row[tid + 256];
    float m = fmaxf(a, b2);
    #pragma unroll
    for (int off = 16; off; off >>= 1) m = fmaxf(m, __shfl_xor_sync(0xffffffffu, m, off));
    if (lane == 0) red[warp] = m;
    __syncthreads();
    float mx = red[0];
    #pragma unroll
    for (int k = 1; k < 8; k++) mx = fmaxf(mx, red[k]);
    float e0 = expf(a - mx), e1 = expf(b2 - mx);
    float s = e0 + e1;
    #pragma unroll
    for (int off = 16; off; off >>= 1) s += __shfl_xor_sync(0xffffffffu, s, off);
    __syncthreads();
    if (lane == 0) red[warp] = s;
    __syncthreads();
    float tot = 0.f;
    #pragma unroll
    for (int k = 0; k < 8; k++) tot += red[k];
    float inv = 1.f / tot;
    long long base = (long long)blockIdx.x * 512;
    __half h0, l0, h1, l1;
    split2(e0 * inv, h0, l0);
    split2(e1 * inv, h1, l1);
    ph[base + tid] = h0; pl[base + tid] = l0;
    ph[base + tid + 256] = h1; pl[base + tid + 256] = l1;
}

// -------------------- launcher ----------------------------------------------
extern "C" void kernel_launch(void* const* d_in, const int* in_sizes, int n_in,
                              void* d_out, int out_size)
{
    (void)in_sizes; (void)n_in; (void)out_size;
    const float* vis = (const float*)d_in[0];
    const float* txt = (const float*)d_in[1];
    const float* Wq  = (const float*)d_in[2];  const float* bq  = (const float*)d_in[3];
    const float* Wk  = (const float*)d_in[4];  const float* bk  = (const float*)d_in[5];
    const float* Wv  = (const float*)d_in[6];  const float* bv  = (const float*)d_in[7];
    const float* Wc1 = (const float*)d_in[8];  const float* bc1 = (const float*)d_in[9];
    const float* Wc2 = (const float*)d_in[10]; const float* bc2 = (const float*)d_in[11];
    float* out = (float*)d_out;

    float *qt, *kv, *vv, *qv, *kt, *vt, *attb, *scb;
    __half *vish, *visl, *txth, *txtl, *c1h, *c1l, *wh, *wl;
    __half *qth, *qtl, *kvh, *kvl, *atth, *attl, *wc1h;
    __half *sch, *scl, *vvTh;
    cudaGetSymbolAddress((void**)&qt,  g_q_text);
    cudaGetSymbolAddress((void**)&kv,  g_k_vis);
    cudaGetSymbolAddress((void**)&vv,  g_v_vis);
    cudaGetSymbolAddress((void**)&qv,  g_q_vis);
    cudaGetSymbolAddress((void**)&kt,  g_k_text);
    cudaGetSymbolAddress((void**)&vt,  g_v_text);
    cudaGetSymbolAddress((void**)&attb, g_att);
    cudaGetSymbolAddress((void**)&scb, g_scores);
    cudaGetSymbolAddress((void**)&vish, g_vis_hi);
    cudaGetSymbolAddress((void**)&visl, g_vis_lo);
    cudaGetSymbolAddress((void**)&txth, g_txt_hi);
    cudaGetSymbolAddress((void**)&txtl, g_txt_lo);
    cudaGetSymbolAddress((void**)&c1h, g_c1_hi);
    cudaGetSymbolAddress((void**)&c1l, g_c1_lo);
    cudaGetSymbolAddress((void**)&wh,  g_w_hi);
    cudaGetSymbolAddress((void**)&wl,  g_w_lo);
    cudaGetSymbolAddress((void**)&qth, g_qt_hi);
    cudaGetSymbolAddress((void**)&qtl, g_qt_lo);
    cudaGetSymbolAddress((void**)&kvh, g_kv_hi);
    cudaGetSymbolAddress((void**)&kvl, g_kv_lo);
    cudaGetSymbolAddress((void**)&atth, g_att_hi);
    cudaGetSymbolAddress((void**)&attl, g_att_lo);
    cudaGetSymbolAddress((void**)&wc1h, g_wc1r_hi);
    cudaGetSymbolAddress((void**)&sch, g_sc_hi);
    cudaGetSymbolAddress((void**)&scl, g_sc_lo);
    cudaGetSymbolAddress((void**)&vvTh, g_vvT_hi);

    cudaFuncSetAttribute((const void*)&mma_qkv,
                         cudaFuncAttributeMaxDynamicSharedMemorySize, MG_SMEM);
    cudaFuncSetAttribute((const void*)&mma_gemm<false, false, true,  false, true>,
                         cudaFuncAttributeMaxDynamicSharedMemorySize, MG_SMEM);
    cudaFuncSetAttribute((const void*)&mma_gemm<false, true,  true,  true,  false>,
                         cudaFuncAttributeMaxDynamicSharedMemorySize, MG_SMEM);
    cudaFuncSetAttribute((const void*)&mma_gemm<true,  false, false, false, false>,
                         cudaFuncAttributeMaxDynamicSharedMemorySize, MG_SMEM);
    cudaFuncSetAttribute((const void*)&conv1_mma,
                         cudaFuncAttributeMaxDynamicSharedMemorySize, CV_SMEM);
    cudaFuncSetAttribute((const void*)&v2t_tile,
                         cudaFuncAttributeMaxDynamicSharedMemorySize, V2T_SMEM);

    const long long SH = (long long)SS * HH;
    const long long LH = (long long)LL * HH;
    const long long SCs = (long long)MID_M * MID_N;

    // 0) splits + weight transforms (txt split also seeds att text rows)
    int n4in = BB * SS * HH / 4;
    split_fp16_2<<<(2 * n4in + 255) / 256, 256>>>(
        (const float4*)vis, (uint2*)vish, (uint2*)visl,
        (const float4*)txt, (uint2*)txth, (uint2*)txtl,
        (uint2*)atth, (uint2*)attl, n4in);
    split_w4<<<(WW + 255) / 256, 256>>>(
        (const float4*)Wq, (const float4*)Wk, (const float4*)Wv, (const float4*)Wc2,
        (uint2*)wh, (uint2*)wl);
    wc1_transform<<<(HH * 384 + 255) / 256, 256>>>(Wc1, wc1h);

    // 1) fused QKV projections for both inputs (128x64 tiles, 2 CTAs/SM)
    mma_qkv<<<dim3(48, 64, 2), 128, MG_SMEM>>>(
        txth, txtl, vish, visl, wh, wl, bq, bk, bv,
        qt, kt, vt, qv, kv, vv,
        qth, qtl, kvh, kvl);

    // 2) v2t sparse attention (tiled)
    v2t_tile<<<dim3(SS / 8, BB), 256, V2T_SMEM>>>(qv, kt, vt, vis, atth, attl);

    // 3) t2v rows 0..4
    t2v_full_rows<<<dim3(5, BB), 256>>>(qt, kv, vv, txt, atth, attl);

    // 3b) transpose V slice (off the critical chain)
    transpose_vslice<<<dim3(MID_N / 32, HH / 32, BB), dim3(32, 8)>>>(vv, vvTh);

    // 4) t2v mid scores (3-term)
    mma_gemm<false, false, true, false, true><<<dim3(MID_N / 64, 3, BB), 128, MG_SMEM>>>(
        qth + 341 * HH, qtl + 341 * HH, SH,
        kvh + 256 * HH, kvl + 256 * HH, SH,
        scb, SCs, MID_N, nullptr, nullptr, nullptr, nullptr, 0, 0, MID_M, HH);

    // 5) softmax -> probs hi/lo
    softmax512<<<BB * MID_M, 256>>>(scb, sch, scl);

    // 6) AV (2-term) + text residual -> att rows hi/lo
    mma_gemm<false, true, true, true, false><<<dim3(HH / 64, 3, BB), 128, MG_SMEM>>>(
        sch, scl, SCs,
        vvTh, vvTh, (long long)HH * MID_N,
        attb + (long long)(1024 + 341) * HH, LH, HH,
        nullptr,
        atth + (long long)(1024 + 341) * HH, attl + (long long)(1024 + 341) * HH,
        txt + 341 * HH, SH, HH,
        MID_M, MID_N);

    // 7) conv1 (2-term) + GELU -> c1 hi/lo
    conv1_mma<<<dim3(LL / 128, 8, BB), 256, CV_SMEM>>>(atth, attl, wc1h, bc1, c1h, c1l);

    // 8) conv2 (2-term) -> output
    mma_gemm<true, false, false, false, false><<<dim3(HH / 64, BB * LL / 128, 1), 128, MG_SMEM>>>(
        c1h, c1l, 0, wh + 3 * WW, wh + 3 * WW, 0,
        out, 0, HH, bc2, nullptr, nullptr, nullptr, 0, 0, BB * LL, HH);
}

// round 10
// speedup vs baseline: 3.4446x; 1.0897x over previous
#include <cuda_runtime.h>
#include <cuda_fp16.h>
#include <math.h>
#include <stdint.h>

#define BB 8
#define SS 1024
#define HH 1024
#define LL 2048
#define MID_M 341
#define MID_N 512
#define WW (HH*HH)

// -------------------- scratch (device globals) ------------------------------
__device__ __align__(128) float g_q_text[BB*SS*HH];
__device__ __align__(128) float g_k_vis [BB*SS*HH];
__device__ __align__(128) float g_v_vis [BB*SS*HH];
__device__ __align__(128) float g_q_vis [BB*SS*HH];
__device__ __align__(128) float g_k_text[BB*SS*HH];
__device__ __align__(128) float g_v_text[BB*SS*HH];
__device__ __align__(128) float g_att   [BB*LL*HH];
__device__ __align__(128) float g_scores[BB*MID_M*MID_N];
__device__ __align__(128) __half g_vis_hi[BB*SS*HH];
__device__ __align__(128) __half g_vis_lo[BB*SS*HH];
__device__ __align__(128) __half g_txt_hi[BB*SS*HH];
__device__ __align__(128) __half g_txt_lo[BB*SS*HH];
__device__ __align__(128) __half g_c1_hi [BB*LL*HH];
__device__ __align__(128) __half g_w_hi  [4*WW];      // Wq, Wk, Wv, Wc2
__device__ __align__(128) __half g_w_lo  [4*WW];
__device__ __align__(128) __half g_qt_hi [BB*SS*HH];
__device__ __align__(128) __half g_qt_lo [BB*SS*HH];
__device__ __align__(128) __half g_kv_hi [BB*SS*HH];
__device__ __align__(128) __half g_kv_lo [BB*SS*HH];
__device__ __align__(128) __half g_att_hi[BB*LL*HH];
__device__ __align__(128) __half g_wc1r_hi[HH*384];
__device__ __align__(128) __half g_sc_hi [BB*MID_M*MID_N];
__device__ __align__(128) __half g_vvT_hi[BB*HH*MID_N];

// ===================== low-level helpers ====================================
__device__ __forceinline__ uint32_t smem_to_u32(const void* p) {
    uint32_t a;
    asm("{ .reg .u64 t; cvta.to.shared.u64 t, %1; cvt.u32.u64 %0, t; }" : "=r"(a) : "l"(p));
    return a;
}
__device__ __forceinline__ void cp_async16(uint32_t saddr, const void* gptr) {
    asm volatile("cp.async.cg.shared.global [%0], [%1], 16;" :: "r"(saddr), "l"(gptr));
}
#define CP_COMMIT() asm volatile("cp.async.commit_group;" ::: "memory")
#define CP_WAIT1()  asm volatile("cp.async.wait_group 1;" ::: "memory")
#define CP_WAIT0()  asm volatile("cp.async.wait_group 0;" ::: "memory")

__device__ __forceinline__ void ldm_x4(uint32_t& r0, uint32_t& r1, uint32_t& r2, uint32_t& r3,
                                       uint32_t addr) {
    asm volatile("ldmatrix.sync.aligned.m8n8.x4.shared.b16 {%0,%1,%2,%3}, [%4];"
                 : "=r"(r0), "=r"(r1), "=r"(r2), "=r"(r3) : "r"(addr));
}
__device__ __forceinline__ void ldm_x2(uint32_t& r0, uint32_t& r1, uint32_t addr) {
    asm volatile("ldmatrix.sync.aligned.m8n8.x2.shared.b16 {%0,%1}, [%2];"
                 : "=r"(r0), "=r"(r1) : "r"(addr));
}
__device__ __forceinline__ void mma16816(float* c, const uint32_t* a, const uint32_t* b) {
    asm volatile("mma.sync.aligned.m16n8k16.row.col.f32.f16.f16.f32 "
                 "{%0,%1,%2,%3}, {%4,%5,%6,%7}, {%8,%9}, {%0,%1,%2,%3};"
                 : "+f"(c[0]), "+f"(c[1]), "+f"(c[2]), "+f"(c[3])
                 : "r"(a[0]), "r"(a[1]), "r"(a[2]), "r"(a[3]), "r"(b[0]), "r"(b[1]));
}
__device__ __forceinline__ void split2(float v, __half& h, __half& l) {
    h = __float2half_rn(v);
    l = __float2half_rn(v - __half2float(h));
}

// ============ GEMM geometry: CTA tile 128x64, 128 threads, 2 CTAs/SM ========
#define STG 49152u
#define MG_SMEM (2 * 49152)

// =================== generic tensor-core GEMM ===============================
// C[M,N] = A[M,K] @ B[N,K]^T (+bias)(+residual).
// TERMS: 3 = Ah*Bh + Ah*Bl + Al*Bh ; 2 = Ah*Bh + Al*Bh ; 1 = Ah*Bh.
// HALFOUT writes fp16 hi only (att path).
template<bool BIAS, bool HALFOUT, bool GUARD, bool RESID, int TERMS>
__global__ __launch_bounds__(128, 2)
void mma_gemm(const __half* __restrict__ Ahi, const __half* __restrict__ Alo, long long sA,
              const __half* __restrict__ Bhi, const __half* __restrict__ Blo, long long sB,
              float* __restrict__ C, long long sC, int ldc,
              const float* __restrict__ bias,
              __half* __restrict__ Chi,
              const float* __restrict__ Rm, long long sR, int ldr,
              int M, int K)
{
    extern __shared__ char smem[];
    const uint32_t sbase = smem_to_u32(smem);
    const int tid = threadIdx.x;
    const int wid = tid >> 5, lane = tid & 31;
    const int m0 = blockIdx.y * 128, n0 = blockIdx.x * 64;
    const int m_w = (wid & 1) * 64;
    const int n_w = (wid >> 1) * 32;
    const int z = blockIdx.z;
    Ahi += z * sA; if (TERMS >= 2) Alo += z * sA;
    Bhi += z * sB; if (TERMS == 3) Blo += z * sB;
    C   += z * sC;
    if (HALFOUT) Chi += z * sC;
    if (RESID)   Rm  += z * sR;

    const int crow = tid >> 3;
    const int cc16 = tid & 7;
    const int nk = K >> 6;

    auto issue_stage = [&](int kc, int s) {
        const int k0 = kc * 64;
        const uint32_t st = sbase + (uint32_t)s * STG;
        #pragma unroll
        for (int p = 0; p < 8; p++) {
            int row = p * 16 + crow;
            uint32_t soff = (uint32_t)(row * 128) + (uint32_t)((cc16 * 16) ^ ((row & 7) << 4));
            int gm = m0 + row;
            if (GUARD) gm = (gm < M) ? gm : (M - 1);
            long long ga = (long long)gm * K + k0 + cc16 * 8;
            cp_async16(st + soff, Ahi + ga);
            if (TERMS >= 2) cp_async16(st + 16384 + soff, Alo + ga);
            if (p < 4) {
                long long gb = (long long)(n0 + row) * K + k0 + cc16 * 8;
                cp_async16(st + 32768 + soff, Bhi + gb);
                if (TERMS == 3) cp_async16(st + 40960 + soff, Blo + gb);
            }
        }
    };

    uint32_t aRow[4], aXor[4];
    #pragma unroll
    for (int mt = 0; mt < 4; mt++) {
        int r = m_w + 16 * mt + (lane & 15);
        aRow[mt] = (uint32_t)(r * 128);
        aXor[mt] = (uint32_t)((r & 7) << 4);
    }
    const uint32_t aCol = (uint32_t)((lane >> 4) * 16);
    uint32_t bRow[4], bXor[4];
    #pragma unroll
    for (int nt = 0; nt < 4; nt++) {
        int r = n_w + 8 * nt + (lane & 7);
        bRow[nt] = (uint32_t)(r * 128);
        bXor[nt] = (uint32_t)((r & 7) << 4);
    }
    const uint32_t bCol = (uint32_t)(((lane >> 3) & 1) * 16);

    float acc[4][4][4];
    #pragma unroll
    for (int mt = 0; mt < 4; mt++)
        #pragma unroll
        for (int nt = 0; nt < 4; nt++)
            #pragma unroll
            for (int q = 0; q < 4; q++) acc[mt][nt][q] = 0.f;

    uint32_t ah[2][4][4], al[2][4][4], bh[2][4][2], bl[2][4][2];

    auto load_frags = [&](int s, int ks, int pb) {
        const uint32_t st = sbase + (uint32_t)s * STG;
        const uint32_t kb = (uint32_t)(ks * 32);
        #pragma unroll
        for (int mt = 0; mt < 4; mt++) {
            uint32_t ad = st + aRow[mt] + ((kb + aCol) ^ aXor[mt]);
            ldm_x4(ah[pb][mt][0], ah[pb][mt][1], ah[pb][mt][2], ah[pb][mt][3], ad);
            if (TERMS >= 2)
                ldm_x4(al[pb][mt][0], al[pb][mt][1], al[pb][mt][2], al[pb][mt][3], ad + 16384);
        }
        #pragma unroll
        for (int nt = 0; nt < 4; nt++) {
            uint32_t bd = st + 32768 + bRow[nt] + ((kb + bCol) ^ bXor[nt]);
            ldm_x2(bh[pb][nt][0], bh[pb][nt][1], bd);
            if (TERMS == 3) ldm_x2(bl[pb][nt][0], bl[pb][nt][1], bd + 8192);
        }
    };
    auto do_mma = [&](int pb) {
        #pragma unroll
        for (int mt = 0; mt < 4; mt++)
            #pragma unroll
            for (int nt = 0; nt < 4; nt++) {
                mma16816(acc[mt][nt], ah[pb][mt], bh[pb][nt]);
                if (TERMS == 3) mma16816(acc[mt][nt], ah[pb][mt], bl[pb][nt]);
                if (TERMS >= 2) mma16816(acc[mt][nt], al[pb][mt], bh[pb][nt]);
            }
    };

    issue_stage(0, 0); CP_COMMIT();
    issue_stage(1, 1); CP_COMMIT();
    for (int kc = 0; kc < nk; kc++) {
        if (kc + 1 < nk) { CP_WAIT1(); } else { CP_WAIT0(); }
        __syncthreads();
        const int s = kc & 1;
        load_frags(s, 0, 0);
        #pragma unroll
        for (int ks = 0; ks < 4; ks++) {
            if (ks < 3) load_frags(s, ks + 1, (ks + 1) & 1);
            do_mma(ks & 1);
        }
        if (kc + 2 < nk) {
            __syncthreads();
            issue_stage(kc + 2, s); CP_COMMIT();
        }
    }

    const int rq = lane >> 2, cq = (lane & 3) * 2;
    #pragma unroll
    for (int mt = 0; mt < 4; mt++) {
        int row0 = m0 + m_w + 16 * mt + rq;
        #pragma unroll
        for (int nt = 0; nt < 4; nt++) {
            int col = n0 + n_w + 8 * nt + cq;
            float b0 = 0.f, b1 = 0.f;
            if (BIAS) { b0 = bias[col]; b1 = bias[col + 1]; }
            #pragma unroll
            for (int rr = 0; rr < 2; rr++) {
                int row = row0 + rr * 8;
                if (GUARD && row >= M) continue;
                float x0 = acc[mt][nt][rr * 2 + 0] + b0;
                float x1 = acc[mt][nt][rr * 2 + 1] + b1;
                if (RESID) {
                    const float* Rp = Rm + (long long)row * ldr + col;
                    x0 += Rp[0]; x1 += Rp[1];
                }
                long long idx = (long long)row * ldc + col;
                *(float2*)(C + idx) = make_float2(x0, x1);
                if (HALFOUT) {
                    *(__half2*)(Chi + idx) =
                        __halves2half2(__float2half_rn(x0), __float2half_rn(x1));
                }
            }
        }
    }
}

// ============ fused QKV projection for BOTH inputs ==========================
// grid = (48, 64, 2). seg = bx/16: q,k 3-term; v 1-term.
// z=0 text (hi/lo out on q_text); z=1 vis (hi/lo out on k_vis).
__global__ __launch_bounds__(128, 2)
void mma_qkv(const __half* __restrict__ A0h, const __half* __restrict__ A0l,
             const __half* __restrict__ A1h, const __half* __restrict__ A1l,
             const __half* __restrict__ Bhi, const __half* __restrict__ Blo,
             const float* __restrict__ b0p, const float* __restrict__ b1p,
             const float* __restrict__ b2p,
             float* __restrict__ Cq0, float* __restrict__ Ck0, float* __restrict__ Cv0,
             float* __restrict__ Cq1, float* __restrict__ Ck1, float* __restrict__ Cv1,
             __half* __restrict__ C0hi, __half* __restrict__ C0lo,
             __half* __restrict__ C1hi, __half* __restrict__ C1lo)
{
    extern __shared__ char smem[];
    const uint32_t sbase = smem_to_u32(smem);
    const int tid = threadIdx.x;
    const int wid = tid >> 5, lane = tid & 31;
    const int m0 = blockIdx.y * 128, n0 = blockIdx.x * 64;
    const int m_w = (wid & 1) * 64;
    const int n_w = (wid >> 1) * 32;
    const int z = blockIdx.z;
    const int seg = n0 >> 10;
    const int ncol0 = n0 & 1023;
    const bool t3 = (seg < 2);      // q,k: 3-term; v: 1-term

    if (z == 0 && seg == 0) {
        int lt = blockIdx.y & 7;
        if (lt == 1 || lt == 6 || lt == 7) return;
    }

    const __half* Ahi = z ? A1h : A0h;
    const __half* Alo = z ? A1l : A0l;
    float* C = z ? ((seg == 0) ? Cq1 : (seg == 1) ? Ck1 : Cv1)
                 : ((seg == 0) ? Cq0 : (seg == 1) ? Ck0 : Cv0);
    const float* bias = (seg == 0) ? b0p : (seg == 1) ? b1p : b2p;
    const bool doHalf = (seg == (z ? 1 : 0));
    __half* Chi = z ? C1hi : C0hi;
    __half* Clo = z ? C1lo : C0lo;

    const int crow = tid >> 3;
    const int cc16 = tid & 7;

    auto issue_stage = [&](int kc, int s) {
        const int k0 = kc * 64;
        const uint32_t st = sbase + (uint32_t)s * STG;
        #pragma unroll
        for (int p = 0; p < 8; p++) {
            int row = p * 16 + crow;
            uint32_t soff = (uint32_t)(row * 128) + (uint32_t)((cc16 * 16) ^ ((row & 7) << 4));
            long long ga = (long long)(m0 + row) * 1024 + k0 + cc16 * 8;
            cp_async16(st + soff, Ahi + ga);
            if (t3) cp_async16(st + 16384 + soff, Alo + ga);
            if (p < 4) {
                long long gb = (long long)(n0 + row) * 1024 + k0 + cc16 * 8;
                cp_async16(st + 32768 + soff, Bhi + gb);
                if (t3) cp_async16(st + 40960 + soff, Blo + gb);
            }
        }
    };

    uint32_t aRow[4], aXor[4];
    #pragma unroll
    for (int mt = 0; mt < 4; mt++) {
        int r = m_w + 16 * mt + (lane & 15);
        aRow[mt] = (uint32_t)(r * 128);
        aXor[mt] = (uint32_t)((r & 7) << 4);
    }
    const uint32_t aCol = (uint32_t)((lane >> 4) * 16);
    uint32_t bRow[4], bXor[4];
    #pragma unroll
    for (int nt = 0; nt < 4; nt++) {
        int r = n_w + 8 * nt + (lane & 7);
        bRow[nt] = (uint32_t)(r * 128);
        bXor[nt] = (uint32_t)((r & 7) << 4);
    }
    const uint32_t bCol = (uint32_t)(((lane >> 3) & 1) * 16);

    float acc[4][4][4];
    #pragma unroll
    for (int mt = 0; mt < 4; mt++)
        #pragma unroll
        for (int nt = 0; nt < 4; nt++)
            #pragma unroll
            for (int q = 0; q < 4; q++) acc[mt][nt][q] = 0.f;

    uint32_t ah[2][4][4], al[2][4][4], bh[2][4][2], bl[2][4][2];

    auto load_frags = [&](int s, int ks, int pb) {
        const uint32_t st = sbase + (uint32_t)s * STG;
        const uint32_t kb = (uint32_t)(ks * 32);
        #pragma unroll
        for (int mt = 0; mt < 4; mt++) {
            uint32_t ad = st + aRow[mt] + ((kb + aCol) ^ aXor[mt]);
            ldm_x4(ah[pb][mt][0], ah[pb][mt][1], ah[pb][mt][2], ah[pb][mt][3], ad);
            if (t3) ldm_x4(al[pb][mt][0], al[pb][mt][1], al[pb][mt][2], al[pb][mt][3], ad + 16384);
        }
        #pragma unroll
        for (int nt = 0; nt < 4; nt++) {
            uint32_t bd = st + 32768 + bRow[nt] + ((kb + bCol) ^ bXor[nt]);
            ldm_x2(bh[pb][nt][0], bh[pb][nt][1], bd);
            if (t3) ldm_x2(bl[pb][nt][0], bl[pb][nt][1], bd + 8192);
        }
    };
    auto do_mma = [&](int pb) {
        #pragma unroll
        for (int mt = 0; mt < 4; mt++)
            #pragma unroll
            for (int nt = 0; nt < 4; nt++) {
                mma16816(acc[mt][nt], ah[pb][mt], bh[pb][nt]);
                if (t3) {
                    mma16816(acc[mt][nt], ah[pb][mt], bl[pb][nt]);
                    mma16816(acc[mt][nt], al[pb][mt], bh[pb][nt]);
                }
            }
    };

    issue_stage(0, 0); CP_COMMIT();
    issue_stage(1, 1); CP_COMMIT();
    for (int kc = 0; kc < 16; kc++) {
        if (kc + 1 < 16) { CP_WAIT1(); } else { CP_WAIT0(); }
        __syncthreads();
        const int s = kc & 1;
        load_frags(s, 0, 0);
        #pragma unroll
        for (int ks = 0; ks < 4; ks++) {
            if (ks < 3) load_frags(s, ks + 1, (ks + 1) & 1);
            do_mma(ks & 1);
        }
        if (kc + 2 < 16) {
            __syncthreads();
            issue_stage(kc + 2, s); CP_COMMIT();
        }
    }

    const int rq = lane >> 2, cq = (lane & 3) * 2;
    #pragma unroll
    for (int mt = 0; mt < 4; mt++) {
        int row0 = m0 + m_w + 16 * mt + rq;
        #pragma unroll
        for (int nt = 0; nt < 4; nt++) {
            int col = ncol0 + n_w + 8 * nt + cq;
            float b0 = bias[col], b1 = bias[col + 1];
            #pragma unroll
            for (int rr = 0; rr < 2; rr++) {
                int row = row0 + rr * 8;
                float x0 = acc[mt][nt][rr * 2 + 0] + b0;
                float x1 = acc[mt][nt][rr * 2 + 1] + b1;
                long long idx = (long long)row * 1024 + col;
                *(float2*)(C + idx) = make_float2(x0, x1);
                if (doHalf) {
                    __half h0, l0h, h1, l1h;
                    split2(x0, h0, l0h); split2(x1, h1, l1h);
                    *(__half2*)(Chi + idx) = __halves2half2(h0, h1);
                    *(__half2*)(Clo + idx) = __halves2half2(l0h, l1h);
                }
            }
        }
    }
}

// ===== conv1 (grouped k=3), 1-term (x hi, w hi), single-shot smem ===========
#define CV_SMEM (33280 + 3*32768)

__global__ __launch_bounds__(256, 1)
void conv1_mma(const __half* __restrict__ xh,
               const __half* __restrict__ wh,
               const float* __restrict__ bias,
               __half* __restrict__ oh)
{
    extern __shared__ char smem[];
    const uint32_t sb = smem_to_u32(smem);
    const int tid = threadIdx.x, wid = tid >> 5, lane = tid & 31;
    const int l0 = blockIdx.x * 128, g = blockIdx.y, b = blockIdx.z;
    const int m_w = (wid & 1) * 64, n_w = (wid >> 1) * 32;
    const uint32_t XH = sb, WH = sb + 33280u;

    for (int t = tid; t < 2080; t += 256) {
        int r = t >> 4, c16 = t & 15;
        int l = l0 - 1 + r;
        uint32_t d = (uint32_t)(r * 256) + (uint32_t)((c16 * 16) ^ ((r & 7) << 4));
        uint4 vh = make_uint4(0u, 0u, 0u, 0u);
        if (l >= 0 && l < LL) {
            long long gidx = ((long long)b * LL + l) * HH + g * 128 + c16 * 8;
            vh = *(const uint4*)(xh + gidx);
        }
        *(uint4*)(smem + d) = vh;
    }
    for (int t = tid; t < 3 * 2048; t += 256) {
        int tap = t >> 11, u = t & 2047;
        int r = u >> 4, c16 = u & 15;
        uint32_t d = (uint32_t)(r * 256) + (uint32_t)((c16 * 16) ^ ((r & 7) << 4));
        long long widx = (long long)(g * 128 + r) * 384 + tap * 128 + c16 * 8;
        *(uint4*)(smem + 33280 + tap * 32768 + d) = *(const uint4*)(wh + widx);
    }
    __syncthreads();

    float acc[4][4][4];
    #pragma unroll
    for (int mt = 0; mt < 4; mt++)
        #pragma unroll
        for (int nt = 0; nt < 4; nt++)
            #pragma unroll
            for (int q = 0; q < 4; q++) acc[mt][nt][q] = 0.f;

    const uint32_t aCol = (uint32_t)((lane >> 4) * 16);
    const uint32_t bCol = (uint32_t)(((lane >> 3) & 1) * 16);

    for (int tap = 0; tap < 3; tap++) {
        #pragma unroll
        for (int ks = 0; ks < 8; ks++) {
            const uint32_t kb = (uint32_t)(ks * 32);
            uint32_t ah[4][4], bh[4][2];
            #pragma unroll
            for (int mt = 0; mt < 4; mt++) {
                int ar = m_w + 16 * mt + (lane & 15) + tap;
                uint32_t ad = XH + (uint32_t)(ar * 256) + ((kb + aCol) ^ (uint32_t)((ar & 7) << 4));
                ldm_x4(ah[mt][0], ah[mt][1], ah[mt][2], ah[mt][3], ad);
            }
            #pragma unroll
            for (int nt = 0; nt < 4; nt++) {
                int br = n_w + 8 * nt + (lane & 7);
                uint32_t bd = WH + (uint32_t)(tap * 32768) + (uint32_t)(br * 256)
                            + ((kb + bCol) ^ (uint32_t)((br & 7) << 4));
                ldm_x2(bh[nt][0], bh[nt][1], bd);
            }
            #pragma unroll
            for (int mt = 0; mt < 4; mt++)
                #pragma unroll
                for (int nt = 0; nt < 4; nt++)
                    mma16816(acc[mt][nt], ah[mt], bh[nt]);
        }
    }

    const int rq = lane >> 2, cq = (lane & 3) * 2;
    #pragma unroll
    for (int mt = 0; mt < 4; mt++) {
        int row0 = l0 + m_w + 16 * mt + rq;
        #pragma unroll
        for (int nt = 0; nt < 4; nt++) {
            int ch = g * 128 + n_w + 8 * nt + cq;
            float b0 = bias[ch], b1 = bias[ch + 1];
            #pragma unroll
            for (int rr = 0; rr < 2; rr++) {
                int row = row0 + rr * 8;
                float x0 = acc[mt][nt][rr * 2 + 0] + b0;
                float x1 = acc[mt][nt][rr * 2 + 1] + b1;
                float y0 = 0.5f * x0 * (1.0f + erff(x0 * 0.70710678118654752f));
                float y1 = 0.5f * x1 * (1.0f + erff(x1 * 0.70710678118654752f));
                long long idx = ((long long)b * LL + row) * HH + ch;
                *(__half2*)(oh + idx) =
                    __halves2half2(__float2half_rn(y0), __float2half_rn(y1));
            }
        }
    }
}

// ------ fused fp32 -> (hi, lo) splits; txt part also seeds att rows (hi) ----
__global__ void split_fp16_2(const float4* __restrict__ x0, uint2* __restrict__ h0,
                             uint2* __restrict__ l0, const float4* __restrict__ x1,
                             uint2* __restrict__ h1, uint2* __restrict__ l1,
                             uint2* __restrict__ atth4, int n4)
{
    int i = blockIdx.x * 256 + threadIdx.x;
    bool isTxt = false;
    const float4* x; uint2 *hp, *lp;
    if (i >= n4) { i -= n4; if (i >= n4) return; x = x1; hp = h1; lp = l1; isTxt = true; }
    else { x = x0; hp = h0; lp = l0; }
    float4 v = x[i];
    __half hx, lx, hy, ly, hz, lz, hw, lw;
    split2(v.x, hx, lx); split2(v.y, hy, ly);
    split2(v.z, hz, lz); split2(v.w, hw, lw);
    __half2 a0 = __halves2half2(hx, hy), a1 = __halves2half2(hz, hw);
    __half2 b0 = __halves2half2(lx, ly), b1 = __halves2half2(lz, lw);
    uint2 oh2, ol2;
    oh2.x = *(uint32_t*)&a0; oh2.y = *(uint32_t*)&a1;
    ol2.x = *(uint32_t*)&b0; ol2.y = *(uint32_t*)&b1;
    hp[i] = oh2; lp[i] = ol2;
    if (isTxt) {
        int b = i >> 18, r = i & 262143;
        atth4[(long long)b * 524288 + 262144 + r] = oh2;
    }
}

__global__ void split_w4(const float4* __restrict__ wq, const float4* __restrict__ wk,
                         const float4* __restrict__ wv, const float4* __restrict__ wc2,
                         uint2* __restrict__ hi, uint2* __restrict__ lo)
{
    int idx = blockIdx.x * 256 + threadIdx.x;
    int seg = idx >> 18, i = idx & 262143;
    const float4* src = (seg == 0) ? wq : (seg == 1) ? wk : (seg == 2) ? wv : wc2;
    float4 v = src[i];
    __half hx, lx, hy, ly, hz, lz, hw, lw;
    split2(v.x, hx, lx); split2(v.y, hy, ly);
    split2(v.z, hz, lz); split2(v.w, hw, lw);
    __half2 a0 = __halves2half2(hx, hy), a1 = __halves2half2(hz, hw);
    __half2 b0 = __halves2half2(lx, ly), b1 = __halves2half2(lz, lw);
    uint2 oh2, ol2;
    oh2.x = *(uint32_t*)&a0; oh2.y = *(uint32_t*)&a1;
    ol2.x = *(uint32_t*)&b0; ol2.y = *(uint32_t*)&b1;
    hi[idx] = oh2; lo[idx] = ol2;
}

__global__ void wc1_transform(const float* __restrict__ W, __half* __restrict__ wh)
{
    int idx = blockIdx.x * 256 + threadIdx.x;
    if (idx >= HH * 384) return;
    int o = idx / 384, k = idx % 384;
    int tap = k >> 7, ic = k & 127;
    wh[idx] = __float2half_rn(W[(long long)o * 384 + ic * 3 + tap]);
}

__global__ void transpose_vslice(const float* __restrict__ vv, __half* __restrict__ th)
{
    __shared__ float tile[32][33];
    const int t0 = blockIdx.x * 32, h0 = blockIdx.y * 32, b = blockIdx.z;
    const int tx = threadIdx.x, ty = threadIdx.y;
    #pragma unroll
    for (int y = ty; y < 32; y += 8)
        tile[y][tx] = vv[((long long)b * SS + 256 + t0 + y) * HH + h0 + tx];
    __syncthreads();
    #pragma unroll
    for (int y = ty; y < 32; y += 8) {
        long long o = ((long long)b * HH + h0 + y) * MID_N + t0 + tx;
        th[o] = __float2half_rn(tile[tx][y]);
    }
}

// -------- v2t attention, tiled: 8 query rows per block ----------------------
#define V2T_SMEM (40 * 1024 * 4)

__global__ __launch_bounds__(256, 1) void v2t_tile(
    const float* __restrict__ qvis, const float* __restrict__ ktext,
    const float* __restrict__ vtext, const float* __restrict__ visf,
    __half* __restrict__ atth)
{
    extern __shared__ float sm[];
    float* ks = sm;
    float* vs = sm + 20 * 1024;
    const int b = blockIdx.y, i0 = blockIdx.x * 8;
    const int tid = threadIdx.x, w = tid >> 5, lane = tid & 31;
    const int w0 = (i0 < 1016) ? i0 : 1016;

    const float* kb = ktext + (long long)b * SS * HH;
    const float* vb = vtext + (long long)b * SS * HH;
    for (int t = tid; t < 20 * 256; t += 256) {
        int slot = t >> 8, c4 = (t & 255) * 4;
        int row = (slot < 5) ? slot : (w0 + slot - 5);
        row = (row < 1023) ? row : 1023;
        *(float4*)(ks + slot * 1024 + c4) = *(const float4*)(kb + (long long)row * HH + c4);
        *(float4*)(vs + slot * 1024 + c4) = *(const float4*)(vb + (long long)row * HH + c4);
    }
    __syncthreads();

    const int i = i0 + w;
    const int s0 = (i < 1016) ? i : 1016;
    const int nk = (i < 5) ? (i + 8) : 13;

    const float* q = qvis + ((long long)b * SS + i) * HH;
    float qr[32];
    #pragma unroll
    for (int c = 0; c < 32; c++) qr[c] = q[c * 32 + lane];

    int sl[13];
    float p[13];
    #pragma unroll
    for (int j = 0; j < 13; j++) {
        int row = (i < 5) ? j : ((j < 5) ? j : (s0 + j - 5));
        sl[j] = (row < 5) ? row : (5 + row - w0);
        float s = 0.f;
        if (j < nk) {
            const float* kr = ks + sl[j] * 1024;
            #pragma unroll
            for (int c = 0; c < 32; c++) s += qr[c] * kr[c * 32 + lane];
        }
        #pragma unroll
        for (int off = 16; off; off >>= 1) s += __shfl_xor_sync(0xffffffffu, s, off);
        p[j] = s;
    }

    float mx = -3.4e38f;
    #pragma unroll
    for (int j = 0; j < 13; j++) if (j < nk) mx = fmaxf(mx, p[j]);
    float sum = 0.f;
    #pragma unroll
    for (int j = 0; j < 13; j++) {
        float e = (j < nk) ? expf(p[j] - mx) : 0.f;
        p[j] = e; sum += e;
    }
    const float inv = 1.f / sum;
    #pragma unroll
    for (int j = 0; j < 13; j++) p[j] *= inv;

    const float* vf = visf + ((long long)b * SS + i) * HH;
    long long ob = ((long long)b * LL + i) * HH;
    #pragma unroll 4
    for (int r = 0; r < 32; r++) {
        int h = r * 32 + lane;
        float a = vf[h];
        #pragma unroll
        for (int j = 0; j < 13; j++) a += p[j] * vs[sl[j] * 1024 + h];
        atth[ob + h] = __float2half_rn(a);
    }
}

// -------------------- t2v rows 0..4 -----------------------------------------
__global__ __launch_bounds__(256) void t2v_full_rows(
    const float* __restrict__ qtext, const float* __restrict__ kvis,
    const float* __restrict__ vvis, const float* __restrict__ txt,
    __half* __restrict__ atth)
{
    const int r = blockIdx.x, b = blockIdx.y;
    const int tid = threadIdx.x, lane = tid & 31, warp = tid >> 5;
    __shared__ float qs[1024];
    __shared__ float sc[1024];
    __shared__ float red[8];

    const float* q = qtext + ((long long)b * SS + r) * HH;
    for (int h = tid; h < 1024; h += 256) qs[h] = q[h];
    __syncthreads();

    const float* kb = kvis + (long long)b * SS * HH;
    for (int t = warp * 128; t < warp * 128 + 128; t++) {
        const float* kp = kb + (long long)t * HH;
        float p = 0.f;
        #pragma unroll
        for (int c = 0; c < 32; c++) p += qs[c * 32 + lane] * kp[c * 32 + lane];
        #pragma unroll
        for (int off = 16; off; off >>= 1) p += __shfl_xor_sync(0xffffffffu, p, off);
        if (lane == 0) sc[t] = p;
    }
    __syncthreads();

    float m = -3.4e38f;
    for (int t = tid; t < 1024; t += 256) m = fmaxf(m, sc[t]);
    #pragma unroll
    for (int off = 16; off; off >>= 1) m = fmaxf(m, __shfl_xor_sync(0xffffffffu, m, off));
    if (lane == 0) red[warp] = m;
    __syncthreads();
    float mx = red[0];
    #pragma unroll
    for (int k = 1; k < 8; k++) mx = fmaxf(mx, red[k]);

    float s = 0.f;
    for (int t = tid; t < 1024; t += 256) { float e = expf(sc[t] - mx); sc[t] = e; s += e; }
    #pragma unroll
    for (int off = 16; off; off >>= 1) s += __shfl_xor_sync(0xffffffffu, s, off);
    __syncthreads();
    if (lane == 0) red[warp] = s;
    __syncthreads();
    float tot = 0.f;
    #pragma unroll
    for (int k = 0; k < 8; k++) tot += red[k];
    const float inv = 1.f / tot;

    const float* vb = vvis + (long long)b * SS * HH;
    const float* tx = txt + ((long long)b * SS + r) * HH;
    long long ob = ((long long)b * LL + 1024 + r) * HH;
    float accv[4] = {0.f, 0.f, 0.f, 0.f};
    for (int t = 0; t < 1024; t++) {
        float pw = sc[t];
        const float* vr = vb + (long long)t * HH + tid;
        accv[0] += pw * vr[0];
        accv[1] += pw * vr[256];
        accv[2] += pw * vr[512];
        accv[3] += pw * vr[768];
    }
    #pragma unroll
    for (int k = 0; k < 4; k++) {
        int h = tid + k * 256;
        float v = tx[h] + accv[k] * inv;
        atth[ob + h] = __float2half_rn(v);
    }
}

// -------------------- softmax over 512-col rows -> probs (fp16 hi) ----------
__global__ __launch_bounds__(256) void softmax512(const float* __restrict__ S,
                                                  __half* __restrict__ ph)
{
    const float* row = S + (long long)blockIdx.x * 512;
    const int tid = threadIdx.x, lane = tid & 31, warp = tid >> 5;
    __shared__ float red[8];
    float a = row[tid], b2 = row[tid + 256];
    float m = fmaxf(a, b2);
    #pragma unroll
    for (int off = 16; off; off >>= 1) m = fmaxf(m, __shfl_xor_sync(0xffffffffu, m, off));
    if (lane == 0) red[warp] = m;
    __syncthreads();
    float mx = red[0];
    #pragma unroll
    for (int k = 1; k < 8; k++) mx = fmaxf(mx, red[k]);
    float e0 = expf(a - mx), e1 = expf(b2 - mx);
    float s = e0 + e1;
    #pragma unroll
    for (int off = 16; off; off >>= 1) s += __shfl_xor_sync(0xffffffffu, s, off);
    __syncthreads();
    if (lane == 0) red[warp] = s;
    __syncthreads();
    float tot = 0.f;
    #pragma unroll
    for (int k = 0; k < 8; k++) tot += red[k];
    float inv = 1.f / tot;
    long long base = (long long)blockIdx.x * 512;
    ph[base + tid]       = __float2half_rn(e0 * inv);
    ph[base + tid + 256] = __float2half_rn(e1 * inv);
}

// -------------------- launcher ----------------------------------------------
extern "C" void kernel_launch(void* const* d_in, const int* in_sizes, int n_in,
                              void* d_out, int out_size)
{
    (void)in_sizes; (void)n_in; (void)out_size;
    const float* vis = (const float*)d_in[0];
    const float* txt = (const float*)d_in[1];
    const float* Wq  = (const float*)d_in[2];  const float* bq  = (const float*)d_in[3];
    const float* Wk  = (const float*)d_in[4];  const float* bk  = (const float*)d_in[5];
    const float* Wv  = (const float*)d_in[6];  const float* bv  = (const float*)d_in[7];
    const float* Wc1 = (const float*)d_in[8];  const float* bc1 = (const float*)d_in[9];
    const float* Wc2 = (const float*)d_in[10]; const float* bc2 = (const float*)d_in[11];
    float* out = (float*)d_out;

    float *qt, *kv, *vv, *qv, *kt, *vt, *attb, *scb;
    __half *vish, *visl, *txth, *txtl, *c1h, *wh, *wl;
    __half *qth, *qtl, *kvh, *kvl, *atth, *wc1h, *sch, *vvTh;
    cudaGetSymbolAddress((void**)&qt,  g_q_text);
    cudaGetSymbolAddress((void**)&kv,  g_k_vis);
    cudaGetSymbolAddress((void**)&vv,  g_v_vis);
    cudaGetSymbolAddress((void**)&qv,  g_q_vis);
    cudaGetSymbolAddress((void**)&kt,  g_k_text);
    cudaGetSymbolAddress((void**)&vt,  g_v_text);
    cudaGetSymbolAddress((void**)&attb, g_att);
    cudaGetSymbolAddress((void**)&scb, g_scores);
    cudaGetSymbolAddress((void**)&vish, g_vis_hi);
    cudaGetSymbolAddress((void**)&visl, g_vis_lo);
    cudaGetSymbolAddress((void**)&txth, g_txt_hi);
    cudaGetSymbolAddress((void**)&txtl, g_txt_lo);
    cudaGetSymbolAddress((void**)&c1h, g_c1_hi);
    cudaGetSymbolAddress((void**)&wh,  g_w_hi);
    cudaGetSymbolAddress((void**)&wl,  g_w_lo);
    cudaGetSymbolAddress((void**)&qth, g_qt_hi);
    cudaGetSymbolAddress((void**)&qtl, g_qt_lo);
    cudaGetSymbolAddress((void**)&kvh, g_kv_hi);
    cudaGetSymbolAddress((void**)&kvl, g_kv_lo);
    cudaGetSymbolAddress((void**)&atth, g_att_hi);
    cudaGetSymbolAddress((void**)&wc1h, g_wc1r_hi);
    cudaGetSymbolAddress((void**)&sch, g_sc_hi);
    cudaGetSymbolAddress((void**)&vvTh, g_vvT_hi);

    cudaFuncSetAttribute((const void*)&mma_qkv,
                         cudaFuncAttributeMaxDynamicSharedMemorySize, MG_SMEM);
    cudaFuncSetAttribute((const void*)&mma_gemm<false, false, true,  false, 3>,
                         cudaFuncAttributeMaxDynamicSharedMemorySize, MG_SMEM);
    cudaFuncSetAttribute((const void*)&mma_gemm<false, true,  true,  true,  1>,
                         cudaFuncAttributeMaxDynamicSharedMemorySize, MG_SMEM);
    cudaFuncSetAttribute((const void*)&mma_gemm<true,  false, false, false, 1>,
                         cudaFuncAttributeMaxDynamicSharedMemorySize, MG_SMEM);
    cudaFuncSetAttribute((const void*)&conv1_mma,
                         cudaFuncAttributeMaxDynamicSharedMemorySize, CV_SMEM);
    cudaFuncSetAttribute((const void*)&v2t_tile,
                         cudaFuncAttributeMaxDynamicSharedMemorySize, V2T_SMEM);

    const long long SH = (long long)SS * HH;
    const long long LH = (long long)LL * HH;
    const long long SCs = (long long)MID_M * MID_N;

    // 0) splits + weight transforms (txt split also seeds att text rows, hi)
    int n4in = BB * SS * HH / 4;
    split_fp16_2<<<(2 * n4in + 255) / 256, 256>>>(
        (const float4*)vis, (uint2*)vish, (uint2*)visl,
        (const float4*)txt, (uint2*)txth, (uint2*)txtl,
        (uint2*)atth, n4in);
    split_w4<<<(WW + 255) / 256, 256>>>(
        (const float4*)Wq, (const float4*)Wk, (const float4*)Wv, (const float4*)Wc2,
        (uint2*)wh, (uint2*)wl);
    wc1_transform<<<(HH * 384 + 255) / 256, 256>>>(Wc1, wc1h);

    // 1) fused QKV projections (q,k 3-term; v 1-term)
    mma_qkv<<<dim3(48, 64, 2), 128, MG_SMEM>>>(
        txth, txtl, vish, visl, wh, wl, bq, bk, bv,
        qt, kt, vt, qv, kv, vv,
        qth, qtl, kvh, kvl);

    // 2) v2t sparse attention (tiled)
    v2t_tile<<<dim3(SS / 8, BB), 256, V2T_SMEM>>>(qv, kt, vt, vis, atth);

    // 3) t2v rows 0..4
    t2v_full_rows<<<dim3(5, BB), 256>>>(qt, kv, vv, txt, atth);

    // 3b) transpose V slice (off the critical chain)
    transpose_vslice<<<dim3(MID_N / 32, HH / 32, BB), dim3(32, 8)>>>(vv, vvTh);

    // 4) t2v mid scores (3-term)
    mma_gemm<false, false, true, false, 3><<<dim3(MID_N / 64, 3, BB), 128, MG_SMEM>>>(
        qth + 341 * HH, qtl + 341 * HH, SH,
        kvh + 256 * HH, kvl + 256 * HH, SH,
        scb, SCs, MID_N, nullptr, nullptr, nullptr, 0, 0, MID_M, HH);

    // 5) softmax -> probs fp16
    softmax512<<<BB * MID_M, 256>>>(scb, sch);

    // 6) AV (1-term) + text residual -> att rows (fp16 hi out)
    mma_gemm<false, true, true, true, 1><<<dim3(HH / 64, 3, BB), 128, MG_SMEM>>>(
        sch, sch, SCs,
        vvTh, vvTh, (long long)HH * MID_N,
        attb + (long long)(1024 + 341) * HH, LH, HH,
        nullptr,
        atth + (long long)(1024 + 341) * HH,
        txt + 341 * HH, SH, HH,
        MID_M, MID_N);

    // 7) conv1 (1-term) + GELU -> c1 fp16
    conv1_mma<<<dim3(LL / 128, 8, BB), 256, CV_SMEM>>>(atth, wc1h, bc1, c1h);

    // 8) conv2 (1-term) -> output
    mma_gemm<true, false, false, false, 1><<<dim3(HH / 64, BB * LL / 128, 1), 128, MG_SMEM>>>(
        c1h, c1h, 0, wh + 3 * WW, wh + 3 * WW, 0,
        out, 0, HH, bc2, nullptr, nullptr, 0, 0, BB * LL, HH);
}